// round 1
// baseline (speedup 1.0000x reference)
#include <cuda_runtime.h>
#include <cstdint>

// Problem constants
#define DIMN    4096
#define S_LEN   2048
#define BATCH   2
#define HQ      32
#define HKV     8
#define NREP    4
#define HD      128
#define MROWS   (BATCH * S_LEN)   // 4096 total rows
#define KVDIM   (HKV * HD)        // 1024

// ---------------------------------------------------------------------------
// Scratch (no cudaMalloc allowed -> __device__ globals)
// ---------------------------------------------------------------------------
__device__ float g_q[(size_t)MROWS * DIMN];     // [m][h*128+d]
__device__ float g_k[(size_t)MROWS * KVDIM];    // [m][kh*128+d]
__device__ float g_v[(size_t)MROWS * KVDIM];
__device__ float g_attn[(size_t)MROWS * DIMN];  // attention output, [m][h*128+d]

// ---------------------------------------------------------------------------
// FP32 SGEMM: C[M,N] = A[M,K] @ B[K,N], all row-major, dims multiples of 128/8
// ---------------------------------------------------------------------------
constexpr int BM = 128, BN = 128, BK = 8, TM = 8, TN = 8;

__global__ __launch_bounds__(256) void sgemm_kernel(
    int M, int N, int K,
    const float* __restrict__ A, const float* __restrict__ B, float* __restrict__ C)
{
    __shared__ float As[BK * BM];  // transposed: As[k][m]
    __shared__ float Bs[BK * BN];

    const int tid  = threadIdx.x;
    const int cRow = blockIdx.y, cCol = blockIdx.x;
    const int threadCol = tid % (BN / TN);   // 0..15
    const int threadRow = tid / (BN / TN);   // 0..15

    const float* Ab = A + (size_t)cRow * BM * K;
    const float* Bb = B + cCol * BN;
    float*       Cb = C + (size_t)cRow * BM * N + cCol * BN;

    const int innerRowA = tid / 2;            // 0..127
    const int innerColA = (tid % 2) * 4;      // 0 or 4
    const int innerRowB = tid / 32;           // 0..7
    const int innerColB = (tid % 32) * 4;     // 0..124

    float res[TM * TN] = {0.f};
    float regM[TM], regN[TN];

    for (int bk = 0; bk < K; bk += BK) {
        float4 ta = *(const float4*)(Ab + (size_t)innerRowA * K + bk + innerColA);
        As[(innerColA + 0) * BM + innerRowA] = ta.x;
        As[(innerColA + 1) * BM + innerRowA] = ta.y;
        As[(innerColA + 2) * BM + innerRowA] = ta.z;
        As[(innerColA + 3) * BM + innerRowA] = ta.w;
        *(float4*)(Bs + innerRowB * BN + innerColB) =
            *(const float4*)(Bb + (size_t)(bk + innerRowB) * N + innerColB);
        __syncthreads();

        #pragma unroll
        for (int k = 0; k < BK; k++) {
            #pragma unroll
            for (int i = 0; i < TM; i++) regM[i] = As[k * BM + threadRow * TM + i];
            #pragma unroll
            for (int j = 0; j < TN; j++) regN[j] = Bs[k * BN + threadCol * TN + j];
            #pragma unroll
            for (int i = 0; i < TM; i++)
                #pragma unroll
                for (int j = 0; j < TN; j++)
                    res[i * TN + j] += regM[i] * regN[j];
        }
        __syncthreads();
    }

    #pragma unroll
    for (int i = 0; i < TM; i++) {
        #pragma unroll
        for (int j = 0; j < TN; j += 4) {
            float4 v = make_float4(res[i * TN + j], res[i * TN + j + 1],
                                   res[i * TN + j + 2], res[i * TN + j + 3]);
            *(float4*)(Cb + (size_t)(threadRow * TM + i) * N + threadCol * TN + j) = v;
        }
    }
}

// ---------------------------------------------------------------------------
// Flash-attention style causal GQA attention, fp32.
// Grid: (S/64, HQ, B). Block: 256 threads.
// ---------------------------------------------------------------------------
constexpr int AB_M = 64, AB_N = 64;
constexpr int QPAD = 132;   // row stride (floats) for Q/K/V smem tiles (16B-aligned)
constexpr int PPAD = 65;    // row stride for P tile
constexpr int SMEM_FLOATS = 3 * AB_M * QPAD + AB_M * PPAD + 3 * AB_M;
constexpr int SMEM_BYTES  = SMEM_FLOATS * 4;  // 118784

__global__ __launch_bounds__(256) void attn_kernel(
    const float* __restrict__ Qg, const float* __restrict__ Kg,
    const float* __restrict__ Vg, float* __restrict__ Og)
{
    extern __shared__ float smem[];
    float* sQ   = smem;                       // [64][132]
    float* sK   = sQ + AB_M * QPAD;           // [64][132]
    float* sV   = sK + AB_M * QPAD;           // [64][132]
    float* sP   = sV + AB_M * QPAD;           // [64][65]
    float* rowM = sP + AB_M * PPAD;           // [64]
    float* rowL = rowM + AB_M;                // [64]
    float* rowA = rowL + AB_M;                // [64]

    const int tid = threadIdx.x;
    const int b   = blockIdx.z;
    const int h   = blockIdx.y;
    const int q0  = blockIdx.x * AB_M;
    const int kvh = h / NREP;

    const float SCALE = 0.08838834764831845f;  // 1/sqrt(128)

    const float* Qbase = Qg + ((size_t)(b * S_LEN + q0)) * DIMN + h * HD;
    const float* Kh    = Kg + ((size_t)(b * S_LEN)) * KVDIM + kvh * HD;
    const float* Vh    = Vg + ((size_t)(b * S_LEN)) * KVDIM + kvh * HD;

    // Load Q tile (64 rows x 128 cols)
    for (int idx = tid; idx < AB_M * 32; idx += 256) {
        int r = idx >> 5, c4 = (idx & 31) * 4;
        float4 t = *(const float4*)(Qbase + (size_t)r * DIMN + c4);
        *(float4*)&sQ[r * QPAD + c4] = t;
    }
    if (tid < AB_M) { rowM[tid] = -1e30f; rowL[tid] = 0.f; }

    // Per-thread output accumulator: row m = tid>>2, d = 16*g + 4*dpart + e
    const int m     = tid >> 2;
    const int dpart = tid & 3;
    float o[32];
    #pragma unroll
    for (int i = 0; i < 32; i++) o[i] = 0.f;

    // Phase-A mapping (GEMM-style 4x4 micro-tile)
    const int tm = tid >> 4;   // 0..15 -> rows tm*4 .. tm*4+3
    const int tn = tid & 15;   // cols tn + 16*c, c=0..3

    const int n_tiles = blockIdx.x + 1;  // causal: only tiles with kt0 <= q0

    for (int t = 0; t < n_tiles; t++) {
        const int kt0 = t * AB_N;
        __syncthreads();  // previous phase B done before overwriting K/V

        // Load K/V tiles (64 rows x 128 cols, global row stride 1024)
        for (int idx = tid; idx < AB_M * 32; idx += 256) {
            int r = idx >> 5, c4 = (idx & 31) * 4;
            float4 tk = *(const float4*)(Kh + (size_t)(kt0 + r) * KVDIM + c4);
            *(float4*)&sK[r * QPAD + c4] = tk;
            float4 tv = *(const float4*)(Vh + (size_t)(kt0 + r) * KVDIM + c4);
            *(float4*)&sV[r * QPAD + c4] = tv;
        }
        __syncthreads();

        // ---- Phase A: S = Q @ K^T (4x4 per thread), scaled + causal mask ----
        float acc[4][4];
        #pragma unroll
        for (int r = 0; r < 4; r++)
            #pragma unroll
            for (int c = 0; c < 4; c++) acc[r][c] = 0.f;

        #pragma unroll 4
        for (int kk4 = 0; kk4 < 32; kk4++) {
            float4 a[4], bb[4];
            #pragma unroll
            for (int r = 0; r < 4; r++)
                a[r] = *(const float4*)&sQ[(tm * 4 + r) * QPAD + kk4 * 4];
            #pragma unroll
            for (int c = 0; c < 4; c++)
                bb[c] = *(const float4*)&sK[(tn + 16 * c) * QPAD + kk4 * 4];
            #pragma unroll
            for (int r = 0; r < 4; r++)
                #pragma unroll
                for (int c = 0; c < 4; c++) {
                    acc[r][c] += a[r].x * bb[c].x;
                    acc[r][c] += a[r].y * bb[c].y;
                    acc[r][c] += a[r].z * bb[c].z;
                    acc[r][c] += a[r].w * bb[c].w;
                }
        }
        #pragma unroll
        for (int r = 0; r < 4; r++) {
            int mg = q0 + tm * 4 + r;
            #pragma unroll
            for (int c = 0; c < 4; c++) {
                int ng = kt0 + tn + 16 * c;
                sP[(tm * 4 + r) * PPAD + tn + 16 * c] =
                    (ng <= mg) ? acc[r][c] * SCALE : -1e30f;
            }
        }
        __syncthreads();

        // ---- Softmax row update (one thread per row) ----
        if (tid < AB_M) {
            const int row = tid;
            float mold = rowM[row];
            float mnew = mold;
            #pragma unroll 8
            for (int n = 0; n < AB_N; n++) mnew = fmaxf(mnew, sP[row * PPAD + n]);
            float alpha = __expf(mold - mnew);
            float lsum = 0.f;
            #pragma unroll 8
            for (int n = 0; n < AB_N; n++) {
                float p = __expf(sP[row * PPAD + n] - mnew);
                sP[row * PPAD + n] = p;
                lsum += p;
            }
            rowL[row] = rowL[row] * alpha + lsum;
            rowM[row] = mnew;
            rowA[row] = alpha;
        }
        __syncthreads();

        // ---- Phase B: O = alpha*O + P @ V ----
        float alpha = rowA[m];
        #pragma unroll
        for (int i = 0; i < 32; i++) o[i] *= alpha;

        #pragma unroll 4
        for (int n = 0; n < AB_N; n++) {
            float pv = sP[m * PPAD + n];
            const float4* vrow = (const float4*)&sV[n * QPAD];
            #pragma unroll
            for (int g = 0; g < 8; g++) {
                float4 vv = vrow[dpart + 4 * g];
                o[g * 4 + 0] += pv * vv.x;
                o[g * 4 + 1] += pv * vv.y;
                o[g * 4 + 2] += pv * vv.z;
                o[g * 4 + 3] += pv * vv.w;
            }
        }
    }

    // ---- Epilogue: normalize and store ----
    float inv = 1.0f / rowL[m];
    float* orow = Og + ((size_t)(b * S_LEN + q0 + m)) * DIMN + h * HD;
    #pragma unroll
    for (int g = 0; g < 8; g++) {
        float4 v = make_float4(o[g * 4 + 0] * inv, o[g * 4 + 1] * inv,
                               o[g * 4 + 2] * inv, o[g * 4 + 3] * inv);
        *(float4*)&orow[16 * g + 4 * dpart] = v;
    }
}

// ---------------------------------------------------------------------------
// Launch
// ---------------------------------------------------------------------------
extern "C" void kernel_launch(void* const* d_in, const int* in_sizes, int n_in,
                              void* d_out, int out_size)
{
    const float* x  = (const float*)d_in[0];
    const float* wq = (const float*)d_in[1];
    const float* wk = (const float*)d_in[2];
    const float* wv = (const float*)d_in[3];
    const float* wo = (const float*)d_in[4];
    float* out = (float*)d_out;

    float *qp, *kp, *vp, *ap;
    cudaGetSymbolAddress((void**)&qp, g_q);
    cudaGetSymbolAddress((void**)&kp, g_k);
    cudaGetSymbolAddress((void**)&vp, g_v);
    cudaGetSymbolAddress((void**)&ap, g_attn);

    cudaFuncSetAttribute(attn_kernel, cudaFuncAttributeMaxDynamicSharedMemorySize,
                         SMEM_BYTES);

    dim3 gBig(DIMN / BN, MROWS / BM);    // 32 x 32
    dim3 gKV(KVDIM / BN, MROWS / BM);    // 8 x 32

    sgemm_kernel<<<gBig, 256>>>(MROWS, DIMN, DIMN, x, wq, qp);
    sgemm_kernel<<<gKV, 256>>>(MROWS, KVDIM, DIMN, x, wk, kp);
    sgemm_kernel<<<gKV, 256>>>(MROWS, KVDIM, DIMN, x, wv, vp);

    attn_kernel<<<dim3(S_LEN / AB_M, HQ, BATCH), 256, SMEM_BYTES>>>(qp, kp, vp, ap);

    sgemm_kernel<<<gBig, 256>>>(MROWS, DIMN, DIMN, ap, wo, out);
}

// round 3
// speedup vs baseline: 1.8787x; 1.8787x over previous
#include <cuda_runtime.h>
#include <cuda_bf16.h>
#include <cstdint>

// Problem constants
#define DIMN    4096
#define S_LEN   2048
#define BATCH   2
#define HQ      32
#define HKV     8
#define NREP    4
#define HD      128
#define MROWS   (BATCH * S_LEN)   // 4096
#define KVDIM   (HKV * HD)        // 1024

// ---------------------------------------------------------------------------
// Scratch (__device__ globals; no cudaMalloc allowed)
// ---------------------------------------------------------------------------
__device__ float g_q[(size_t)MROWS * DIMN];
__device__ float g_k[(size_t)MROWS * KVDIM];
__device__ float g_v[(size_t)MROWS * KVDIM];
__device__ float g_attn[(size_t)MROWS * DIMN];

__device__ __nv_bfloat16 g_xh[(size_t)MROWS * DIMN];
__device__ __nv_bfloat16 g_xl[(size_t)MROWS * DIMN];
__device__ __nv_bfloat16 g_ah[(size_t)MROWS * DIMN];
__device__ __nv_bfloat16 g_al[(size_t)MROWS * DIMN];
__device__ __nv_bfloat16 g_wqT_h[(size_t)DIMN * DIMN];
__device__ __nv_bfloat16 g_wqT_l[(size_t)DIMN * DIMN];
__device__ __nv_bfloat16 g_woT_h[(size_t)DIMN * DIMN];
__device__ __nv_bfloat16 g_woT_l[(size_t)DIMN * DIMN];
__device__ __nv_bfloat16 g_wkT_h[(size_t)KVDIM * DIMN];
__device__ __nv_bfloat16 g_wkT_l[(size_t)KVDIM * DIMN];
__device__ __nv_bfloat16 g_wvT_h[(size_t)KVDIM * DIMN];
__device__ __nv_bfloat16 g_wvT_l[(size_t)KVDIM * DIMN];

// ---------------------------------------------------------------------------
// PTX helpers
// ---------------------------------------------------------------------------
__device__ __forceinline__ uint32_t smem_u32(const void* p) {
    return (uint32_t)__cvta_generic_to_shared(p);
}
__device__ __forceinline__ void ldsm4(uint32_t* r, uint32_t addr) {
    asm volatile("ldmatrix.sync.aligned.m8n8.x4.shared.b16 {%0,%1,%2,%3}, [%4];"
                 : "=r"(r[0]), "=r"(r[1]), "=r"(r[2]), "=r"(r[3]) : "r"(addr));
}
__device__ __forceinline__ void mma_bf16(float* d, const uint32_t* a,
                                         const uint32_t b0, const uint32_t b1) {
    asm volatile(
        "mma.sync.aligned.m16n8k16.row.col.f32.bf16.bf16.f32 "
        "{%0,%1,%2,%3}, {%4,%5,%6,%7}, {%8,%9}, {%0,%1,%2,%3};"
        : "+f"(d[0]), "+f"(d[1]), "+f"(d[2]), "+f"(d[3])
        : "r"(a[0]), "r"(a[1]), "r"(a[2]), "r"(a[3]), "r"(b0), "r"(b1));
}

// ---------------------------------------------------------------------------
// Split-bf16 tensor-core GEMM: C[M,N] = (Ah+Al)[M,K] @ (Bh+Bl)[N,K]^T
// 128x128 CTA tile, 8 warps of 64x32, K-chunk 32, 3-stage cp.async pipeline.
// Smem rows padded to 40 bf16 (80B) -> conflict-free ldmatrix.
// ---------------------------------------------------------------------------
constexpr int CK    = 32;                    // K-chunk
constexpr int PADW  = 40;                    // smem row stride in bf16
constexpr int PLANE = 128 * PADW * 2;        // 10240 B per plane
constexpr int STAGE = 4 * PLANE;             // Ah, Al, Bh, Bl
constexpr int GNS   = 3;
constexpr int GEMM_SMEM = GNS * STAGE;       // 122880 B

__device__ __forceinline__ void prefetch_chunk(
    const __nv_bfloat16* Ah, const __nv_bfloat16* Al,
    const __nv_bfloat16* Bh, const __nv_bfloat16* Bl,
    int K, int mtile, int ntile, int k0, uint32_t tbase, int tid)
{
    #pragma unroll
    for (int u = tid; u < 2048; u += 256) {
        int plane = u >> 9;          // 0:Ah 1:Al 2:Bh 3:Bl
        int r = (u >> 2) & 127;
        int seg = u & 3;             // 8-bf16 (16B) segment
        const __nv_bfloat16* src;
        if (plane == 0)      src = Ah + (size_t)(mtile + r) * K + k0 + seg * 8;
        else if (plane == 1) src = Al + (size_t)(mtile + r) * K + k0 + seg * 8;
        else if (plane == 2) src = Bh + (size_t)(ntile + r) * K + k0 + seg * 8;
        else                 src = Bl + (size_t)(ntile + r) * K + k0 + seg * 8;
        uint32_t dst = tbase + plane * PLANE + r * (PADW * 2) + seg * 16;
        asm volatile("cp.async.cg.shared.global [%0], [%1], 16;"
                     :: "r"(dst), "l"(src) : "memory");
    }
}

__global__ __launch_bounds__(256, 1) void gemm_bf16_split(
    int M, int N, int K,
    const __nv_bfloat16* __restrict__ Ah, const __nv_bfloat16* __restrict__ Al,
    const __nv_bfloat16* __restrict__ Bh, const __nv_bfloat16* __restrict__ Bl,
    float* __restrict__ C)
{
    extern __shared__ char smem[];
    const uint32_t sbase = smem_u32(smem);

    const int tid = threadIdx.x;
    const int wid = tid >> 5, lane = tid & 31;
    const int wm = wid >> 2;        // 0..1 -> rows wm*64
    const int wn = wid & 3;         // 0..3 -> cols wn*32
    const int mtile = blockIdx.y * 128;
    const int ntile = blockIdx.x * 128;
    const int nch = K / CK;

    float acc[4][4][4];
    #pragma unroll
    for (int mi = 0; mi < 4; mi++)
        #pragma unroll
        for (int ni = 0; ni < 4; ni++)
            #pragma unroll
            for (int e = 0; e < 4; e++) acc[mi][ni][e] = 0.f;

    // ldmatrix lane address components (within a tile, bytes)
    // A (16x16): row = (lane%8) + ((lane/8)%2)*8, colbyte = (lane/16)*16
    const int a_row_in16 = (lane & 7) + ((lane >> 3) & 1) * 8;
    const int a_colb     = (lane >> 4) * 16;
    // B (n16 x k16): n = (lane%8) + (lane>=16 ? 8 : 0), colbyte = ((lane>>3)&1)*16
    const int b_row_in16 = (lane & 7) + ((lane >> 4) & 1) * 8;
    const int b_colb     = ((lane >> 3) & 1) * 16;

    // Prologue
    for (int i = 0; i < GNS; i++) {
        prefetch_chunk(Ah, Al, Bh, Bl, K, mtile, ntile, i * CK,
                       sbase + i * STAGE, tid);
        asm volatile("cp.async.commit_group;" ::: "memory");
    }

    for (int i = 0; i < nch; i++) {
        const int s = i % GNS;
        const uint32_t tb = sbase + s * STAGE;
        asm volatile("cp.async.wait_group %0;" :: "n"(GNS - 1) : "memory");
        __syncthreads();

        const uint32_t aH = tb;
        const uint32_t aL = tb + PLANE;
        const uint32_t bH = tb + 2 * PLANE;
        const uint32_t bL = tb + 3 * PLANE;

        #pragma unroll
        for (int ks = 0; ks < 2; ks++) {
            const int kb = ks * 32;  // byte offset within row (16 bf16)
            uint32_t fAh[4][4], fAl[4][4], fBh[2][4], fBl[2][4];
            #pragma unroll
            for (int mi = 0; mi < 4; mi++) {
                int row = wm * 64 + mi * 16 + a_row_in16;
                uint32_t addr = row * (PADW * 2) + a_colb + kb;
                ldsm4(fAh[mi], aH + addr);
                ldsm4(fAl[mi], aL + addr);
            }
            #pragma unroll
            for (int ng = 0; ng < 2; ng++) {
                int row = wn * 32 + ng * 16 + b_row_in16;
                uint32_t addr = row * (PADW * 2) + b_colb + kb;
                ldsm4(fBh[ng], bH + addr);
                ldsm4(fBl[ng], bL + addr);
            }
            #pragma unroll
            for (int mi = 0; mi < 4; mi++) {
                #pragma unroll
                for (int ni = 0; ni < 4; ni++) {
                    const int ng = ni >> 1, hf = (ni & 1) * 2;
                    mma_bf16(acc[mi][ni], fAh[mi], fBh[ng][hf], fBh[ng][hf + 1]);
                    mma_bf16(acc[mi][ni], fAh[mi], fBl[ng][hf], fBl[ng][hf + 1]);
                    mma_bf16(acc[mi][ni], fAl[mi], fBh[ng][hf], fBh[ng][hf + 1]);
                }
            }
        }
        __syncthreads();

        if (i + GNS < nch)
            prefetch_chunk(Ah, Al, Bh, Bl, K, mtile, ntile, (i + GNS) * CK,
                           sbase + s * STAGE, tid);
        asm volatile("cp.async.commit_group;" ::: "memory");
    }

    // Epilogue: direct stores (fragment layout)
    const int r0b = mtile + wm * 64 + (lane >> 2);
    const int c0b = ntile + wn * 32 + (lane & 3) * 2;
    #pragma unroll
    for (int mi = 0; mi < 4; mi++) {
        #pragma unroll
        for (int ni = 0; ni < 4; ni++) {
            float* p0 = C + (size_t)(r0b + mi * 16) * N + c0b + ni * 8;
            float* p1 = C + (size_t)(r0b + mi * 16 + 8) * N + c0b + ni * 8;
            *(float2*)p0 = make_float2(acc[mi][ni][0], acc[mi][ni][1]);
            *(float2*)p1 = make_float2(acc[mi][ni][2], acc[mi][ni][3]);
        }
    }
}

// ---------------------------------------------------------------------------
// Conversion kernels: fp32 -> bf16 hi/lo planes
// ---------------------------------------------------------------------------
__global__ void conv_hilo(const float* __restrict__ in,
                          __nv_bfloat16* __restrict__ hi,
                          __nv_bfloat16* __restrict__ lo, int n4)
{
    int i = blockIdx.x * blockDim.x + threadIdx.x;
    if (i >= n4) return;
    float4 v = ((const float4*)in)[i];
    __nv_bfloat16 h0 = __float2bfloat16(v.x), h1 = __float2bfloat16(v.y);
    __nv_bfloat16 h2 = __float2bfloat16(v.z), h3 = __float2bfloat16(v.w);
    __nv_bfloat16 l0 = __float2bfloat16(v.x - __bfloat162float(h0));
    __nv_bfloat16 l1 = __float2bfloat16(v.y - __bfloat162float(h1));
    __nv_bfloat16 l2 = __float2bfloat16(v.z - __bfloat162float(h2));
    __nv_bfloat16 l3 = __float2bfloat16(v.w - __bfloat162float(h3));
    ((__nv_bfloat162*)hi)[2 * i]     = __nv_bfloat162(h0, h1);
    ((__nv_bfloat162*)hi)[2 * i + 1] = __nv_bfloat162(h2, h3);
    ((__nv_bfloat162*)lo)[2 * i]     = __nv_bfloat162(l0, l1);
    ((__nv_bfloat162*)lo)[2 * i + 1] = __nv_bfloat162(l2, l3);
}

// W[K,N] fp32 -> WT[N,K] bf16 hi/lo (tiled transpose)
__global__ void convT_hilo(const float* __restrict__ W,
                           __nv_bfloat16* __restrict__ Th,
                           __nv_bfloat16* __restrict__ Tl, int K, int N)
{
    __shared__ float t[32][33];
    int n0 = blockIdx.x * 32, k0 = blockIdx.y * 32;
    int tx = threadIdx.x, ty0 = threadIdx.y;  // 32 x 8
    #pragma unroll
    for (int j = 0; j < 4; j++) {
        int ty = ty0 + 8 * j;
        t[ty][tx] = W[(size_t)(k0 + ty) * N + n0 + tx];
    }
    __syncthreads();
    #pragma unroll
    for (int j = 0; j < 4; j++) {
        int ty = ty0 + 8 * j;
        float v = t[tx][ty];
        __nv_bfloat16 h = __float2bfloat16(v);
        __nv_bfloat16 l = __float2bfloat16(v - __bfloat162float(h));
        Th[(size_t)(n0 + ty) * K + k0 + tx] = h;
        Tl[(size_t)(n0 + ty) * K + k0 + tx] = l;
    }
}

// ---------------------------------------------------------------------------
// Flash-attention style causal GQA attention, fp32
// ---------------------------------------------------------------------------
constexpr int AB_M = 64, AB_N = 64;
constexpr int QPAD = 132;
constexpr int PPAD = 65;
constexpr int SMEM_FLOATS = 3 * AB_M * QPAD + AB_M * PPAD + 3 * AB_M;
constexpr int ATTN_SMEM = SMEM_FLOATS * 4;

__global__ __launch_bounds__(256) void attn_kernel(
    const float* __restrict__ Qg, const float* __restrict__ Kg,
    const float* __restrict__ Vg, float* __restrict__ Og)
{
    extern __shared__ float smemf[];
    float* sQ   = smemf;
    float* sK   = sQ + AB_M * QPAD;
    float* sV   = sK + AB_M * QPAD;
    float* sP   = sV + AB_M * QPAD;
    float* rowM = sP + AB_M * PPAD;
    float* rowL = rowM + AB_M;
    float* rowA = rowL + AB_M;

    const int tid = threadIdx.x;
    const int b   = blockIdx.z;
    const int h   = blockIdx.y;
    const int q0  = blockIdx.x * AB_M;
    const int kvh = h / NREP;
    const float SCALE = 0.08838834764831845f;

    const float* Qbase = Qg + ((size_t)(b * S_LEN + q0)) * DIMN + h * HD;
    const float* Kh    = Kg + ((size_t)(b * S_LEN)) * KVDIM + kvh * HD;
    const float* Vh    = Vg + ((size_t)(b * S_LEN)) * KVDIM + kvh * HD;

    for (int idx = tid; idx < AB_M * 32; idx += 256) {
        int r = idx >> 5, c4 = (idx & 31) * 4;
        *(float4*)&sQ[r * QPAD + c4] = *(const float4*)(Qbase + (size_t)r * DIMN + c4);
    }
    if (tid < AB_M) { rowM[tid] = -1e30f; rowL[tid] = 0.f; }

    const int m = tid >> 2, dpart = tid & 3;
    float o[32];
    #pragma unroll
    for (int i = 0; i < 32; i++) o[i] = 0.f;

    const int tm = tid >> 4, tn = tid & 15;
    const int n_tiles = blockIdx.x + 1;

    for (int t = 0; t < n_tiles; t++) {
        const int kt0 = t * AB_N;
        __syncthreads();
        for (int idx = tid; idx < AB_M * 32; idx += 256) {
            int r = idx >> 5, c4 = (idx & 31) * 4;
            *(float4*)&sK[r * QPAD + c4] = *(const float4*)(Kh + (size_t)(kt0 + r) * KVDIM + c4);
            *(float4*)&sV[r * QPAD + c4] = *(const float4*)(Vh + (size_t)(kt0 + r) * KVDIM + c4);
        }
        __syncthreads();

        float accq[4][4];
        #pragma unroll
        for (int r = 0; r < 4; r++)
            #pragma unroll
            for (int c = 0; c < 4; c++) accq[r][c] = 0.f;

        #pragma unroll 4
        for (int kk4 = 0; kk4 < 32; kk4++) {
            float4 a[4], bb[4];
            #pragma unroll
            for (int r = 0; r < 4; r++)
                a[r] = *(const float4*)&sQ[(tm * 4 + r) * QPAD + kk4 * 4];
            #pragma unroll
            for (int c = 0; c < 4; c++)
                bb[c] = *(const float4*)&sK[(tn + 16 * c) * QPAD + kk4 * 4];
            #pragma unroll
            for (int r = 0; r < 4; r++)
                #pragma unroll
                for (int c = 0; c < 4; c++) {
                    accq[r][c] += a[r].x * bb[c].x;
                    accq[r][c] += a[r].y * bb[c].y;
                    accq[r][c] += a[r].z * bb[c].z;
                    accq[r][c] += a[r].w * bb[c].w;
                }
        }
        #pragma unroll
        for (int r = 0; r < 4; r++) {
            int mg = q0 + tm * 4 + r;
            #pragma unroll
            for (int c = 0; c < 4; c++) {
                int ng = kt0 + tn + 16 * c;
                sP[(tm * 4 + r) * PPAD + tn + 16 * c] =
                    (ng <= mg) ? accq[r][c] * SCALE : -1e30f;
            }
        }
        __syncthreads();

        if (tid < AB_M) {
            const int row = tid;
            float mold = rowM[row], mnew = mold;
            #pragma unroll 8
            for (int n = 0; n < AB_N; n++) mnew = fmaxf(mnew, sP[row * PPAD + n]);
            float alpha = __expf(mold - mnew);
            float lsum = 0.f;
            #pragma unroll 8
            for (int n = 0; n < AB_N; n++) {
                float p = __expf(sP[row * PPAD + n] - mnew);
                sP[row * PPAD + n] = p;
                lsum += p;
            }
            rowL[row] = rowL[row] * alpha + lsum;
            rowM[row] = mnew;
            rowA[row] = alpha;
        }
        __syncthreads();

        float alpha = rowA[m];
        #pragma unroll
        for (int i = 0; i < 32; i++) o[i] *= alpha;

        #pragma unroll 4
        for (int n = 0; n < AB_N; n++) {
            float pv = sP[m * PPAD + n];
            const float4* vrow = (const float4*)&sV[n * QPAD];
            #pragma unroll
            for (int g = 0; g < 8; g++) {
                float4 vv = vrow[dpart + 4 * g];
                o[g * 4 + 0] += pv * vv.x;
                o[g * 4 + 1] += pv * vv.y;
                o[g * 4 + 2] += pv * vv.z;
                o[g * 4 + 3] += pv * vv.w;
            }
        }
    }

    float inv = 1.0f / rowL[m];
    float* orow = Og + ((size_t)(b * S_LEN + q0 + m)) * DIMN + h * HD;
    #pragma unroll
    for (int g = 0; g < 8; g++) {
        float4 v = make_float4(o[g * 4 + 0] * inv, o[g * 4 + 1] * inv,
                               o[g * 4 + 2] * inv, o[g * 4 + 3] * inv);
        *(float4*)&orow[16 * g + 4 * dpart] = v;
    }
}

// ---------------------------------------------------------------------------
// Launch
// ---------------------------------------------------------------------------
extern "C" void kernel_launch(void* const* d_in, const int* in_sizes, int n_in,
                              void* d_out, int out_size)
{
    const float* x  = (const float*)d_in[0];
    const float* wq = (const float*)d_in[1];
    const float* wk = (const float*)d_in[2];
    const float* wv = (const float*)d_in[3];
    const float* wo = (const float*)d_in[4];
    float* out = (float*)d_out;

    float *qp, *kp, *vp, *ap;
    cudaGetSymbolAddress((void**)&qp, g_q);
    cudaGetSymbolAddress((void**)&kp, g_k);
    cudaGetSymbolAddress((void**)&vp, g_v);
    cudaGetSymbolAddress((void**)&ap, g_attn);

    __nv_bfloat16 *xh, *xl, *ah, *al, *wqh, *wql, *wkh, *wkl, *wvh, *wvl, *woh, *wol;
    cudaGetSymbolAddress((void**)&xh, g_xh);   cudaGetSymbolAddress((void**)&xl, g_xl);
    cudaGetSymbolAddress((void**)&ah, g_ah);   cudaGetSymbolAddress((void**)&al, g_al);
    cudaGetSymbolAddress((void**)&wqh, g_wqT_h); cudaGetSymbolAddress((void**)&wql, g_wqT_l);
    cudaGetSymbolAddress((void**)&wkh, g_wkT_h); cudaGetSymbolAddress((void**)&wkl, g_wkT_l);
    cudaGetSymbolAddress((void**)&wvh, g_wvT_h); cudaGetSymbolAddress((void**)&wvl, g_wvT_l);
    cudaGetSymbolAddress((void**)&woh, g_woT_h); cudaGetSymbolAddress((void**)&wol, g_woT_l);

    cudaFuncSetAttribute(gemm_bf16_split,
                         cudaFuncAttributeMaxDynamicSharedMemorySize, GEMM_SMEM);
    cudaFuncSetAttribute(attn_kernel,
                         cudaFuncAttributeMaxDynamicSharedMemorySize, ATTN_SMEM);

    // 1) Conversions
    int n4x = MROWS * DIMN / 4;
    conv_hilo<<<(n4x + 255) / 256, 256>>>(x, xh, xl, n4x);
    convT_hilo<<<dim3(DIMN / 32, DIMN / 32), dim3(32, 8)>>>(wq, wqh, wql, DIMN, DIMN);
    convT_hilo<<<dim3(KVDIM / 32, DIMN / 32), dim3(32, 8)>>>(wk, wkh, wkl, DIMN, KVDIM);
    convT_hilo<<<dim3(KVDIM / 32, DIMN / 32), dim3(32, 8)>>>(wv, wvh, wvl, DIMN, KVDIM);
    convT_hilo<<<dim3(DIMN / 32, DIMN / 32), dim3(32, 8)>>>(wo, woh, wol, DIMN, DIMN);

    // 2) Projections (tensor cores via mma.sync)
    gemm_bf16_split<<<dim3(DIMN / 128, MROWS / 128), 256, GEMM_SMEM>>>(
        MROWS, DIMN, DIMN, xh, xl, wqh, wql, qp);
    gemm_bf16_split<<<dim3(KVDIM / 128, MROWS / 128), 256, GEMM_SMEM>>>(
        MROWS, KVDIM, DIMN, xh, xl, wkh, wkl, kp);
    gemm_bf16_split<<<dim3(KVDIM / 128, MROWS / 128), 256, GEMM_SMEM>>>(
        MROWS, KVDIM, DIMN, xh, xl, wvh, wvl, vp);

    // 3) Attention
    attn_kernel<<<dim3(S_LEN / AB_M, HQ, BATCH), 256, ATTN_SMEM>>>(qp, kp, vp, ap);

    // 4) Output projection
    conv_hilo<<<(n4x + 255) / 256, 256>>>(ap, ah, al, n4x);
    gemm_bf16_split<<<dim3(DIMN / 128, MROWS / 128), 256, GEMM_SMEM>>>(
        MROWS, DIMN, DIMN, ah, al, woh, wol, out);
}

// round 4
// speedup vs baseline: 3.2327x; 1.7208x over previous
#include <cuda_runtime.h>
#include <cuda_bf16.h>
#include <cstdint>

// Problem constants
#define DIMN    4096
#define S_LEN   2048
#define BATCH   2
#define HQ      32
#define HKV     8
#define NREP    4
#define HD      128
#define MROWS   (BATCH * S_LEN)   // 4096
#define KVDIM   (HKV * HD)        // 1024

// ---------------------------------------------------------------------------
// Scratch (__device__ globals)
// ---------------------------------------------------------------------------
__device__ __nv_bfloat16 g_xh[(size_t)MROWS * DIMN];
__device__ __nv_bfloat16 g_xl[(size_t)MROWS * DIMN];
__device__ __nv_bfloat16 g_qh[(size_t)MROWS * DIMN];
__device__ __nv_bfloat16 g_ql[(size_t)MROWS * DIMN];
__device__ __nv_bfloat16 g_kh[(size_t)MROWS * KVDIM];
__device__ __nv_bfloat16 g_kl[(size_t)MROWS * KVDIM];
__device__ __nv_bfloat16 g_vh[(size_t)MROWS * KVDIM];
__device__ __nv_bfloat16 g_vl[(size_t)MROWS * KVDIM];
__device__ __nv_bfloat16 g_ah[(size_t)MROWS * DIMN];
__device__ __nv_bfloat16 g_al[(size_t)MROWS * DIMN];
__device__ __nv_bfloat16 g_wqT_h[(size_t)DIMN * DIMN];
__device__ __nv_bfloat16 g_wqT_l[(size_t)DIMN * DIMN];
__device__ __nv_bfloat16 g_woT_h[(size_t)DIMN * DIMN];
__device__ __nv_bfloat16 g_woT_l[(size_t)DIMN * DIMN];
__device__ __nv_bfloat16 g_wkT_h[(size_t)KVDIM * DIMN];
__device__ __nv_bfloat16 g_wkT_l[(size_t)KVDIM * DIMN];
__device__ __nv_bfloat16 g_wvT_h[(size_t)KVDIM * DIMN];
__device__ __nv_bfloat16 g_wvT_l[(size_t)KVDIM * DIMN];

// ---------------------------------------------------------------------------
// PTX helpers
// ---------------------------------------------------------------------------
__device__ __forceinline__ uint32_t smem_u32(const void* p) {
    return (uint32_t)__cvta_generic_to_shared(p);
}
__device__ __forceinline__ void ldsm4(uint32_t* r, uint32_t addr) {
    asm volatile("ldmatrix.sync.aligned.m8n8.x4.shared.b16 {%0,%1,%2,%3}, [%4];"
                 : "=r"(r[0]), "=r"(r[1]), "=r"(r[2]), "=r"(r[3]) : "r"(addr));
}
__device__ __forceinline__ void ldsm4t(uint32_t* r, uint32_t addr) {
    asm volatile("ldmatrix.sync.aligned.m8n8.x4.trans.shared.b16 {%0,%1,%2,%3}, [%4];"
                 : "=r"(r[0]), "=r"(r[1]), "=r"(r[2]), "=r"(r[3]) : "r"(addr));
}
__device__ __forceinline__ void mma_bf16(float* d, const uint32_t* a,
                                         const uint32_t b0, const uint32_t b1) {
    asm volatile(
        "mma.sync.aligned.m16n8k16.row.col.f32.bf16.bf16.f32 "
        "{%0,%1,%2,%3}, {%4,%5,%6,%7}, {%8,%9}, {%0,%1,%2,%3};"
        : "+f"(d[0]), "+f"(d[1]), "+f"(d[2]), "+f"(d[3])
        : "r"(a[0]), "r"(a[1]), "r"(a[2]), "r"(a[3]), "r"(b0), "r"(b1));
}
__device__ __forceinline__ uint32_t pack_bf2(float a, float b) {
    __nv_bfloat162 t = __float22bfloat162_rn(make_float2(a, b));
    return *(uint32_t*)&t;
}

// ---------------------------------------------------------------------------
// Split-bf16 tensor-core GEMM: C = (Ah+Al)[M,K] @ (Bh+Bl)[N,K]^T
// OUTBF=0: fp32 C. OUTBF=1: bf16 hi/lo planes Ch, Cl.
// ---------------------------------------------------------------------------
constexpr int CK    = 32;
constexpr int PADW  = 40;
constexpr int PLANE = 128 * PADW * 2;
constexpr int STAGE = 4 * PLANE;
constexpr int GNS   = 3;
constexpr int GEMM_SMEM = GNS * STAGE;

__device__ __forceinline__ void prefetch_chunk(
    const __nv_bfloat16* Ah, const __nv_bfloat16* Al,
    const __nv_bfloat16* Bh, const __nv_bfloat16* Bl,
    int K, int mtile, int ntile, int k0, uint32_t tbase, int tid)
{
    #pragma unroll
    for (int u = tid; u < 2048; u += 256) {
        int plane = u >> 9;
        int r = (u >> 2) & 127;
        int seg = u & 3;
        const __nv_bfloat16* src;
        if (plane == 0)      src = Ah + (size_t)(mtile + r) * K + k0 + seg * 8;
        else if (plane == 1) src = Al + (size_t)(mtile + r) * K + k0 + seg * 8;
        else if (plane == 2) src = Bh + (size_t)(ntile + r) * K + k0 + seg * 8;
        else                 src = Bl + (size_t)(ntile + r) * K + k0 + seg * 8;
        uint32_t dst = tbase + plane * PLANE + r * (PADW * 2) + seg * 16;
        asm volatile("cp.async.cg.shared.global [%0], [%1], 16;"
                     :: "r"(dst), "l"(src) : "memory");
    }
}

template <int OUTBF>
__global__ __launch_bounds__(256, 1) void gemm_bf16_split(
    int M, int N, int K,
    const __nv_bfloat16* __restrict__ Ah, const __nv_bfloat16* __restrict__ Al,
    const __nv_bfloat16* __restrict__ Bh, const __nv_bfloat16* __restrict__ Bl,
    float* __restrict__ C,
    __nv_bfloat16* __restrict__ Ch, __nv_bfloat16* __restrict__ Cl)
{
    extern __shared__ char smem[];
    const uint32_t sbase = smem_u32(smem);

    const int tid = threadIdx.x;
    const int wid = tid >> 5, lane = tid & 31;
    const int wm = wid >> 2;
    const int wn = wid & 3;
    const int mtile = blockIdx.y * 128;
    const int ntile = blockIdx.x * 128;
    const int nch = K / CK;

    float acc[4][4][4];
    #pragma unroll
    for (int mi = 0; mi < 4; mi++)
        #pragma unroll
        for (int ni = 0; ni < 4; ni++)
            #pragma unroll
            for (int e = 0; e < 4; e++) acc[mi][ni][e] = 0.f;

    const int a_row_in16 = (lane & 7) + ((lane >> 3) & 1) * 8;
    const int a_colb     = (lane >> 4) * 16;
    const int b_row_in16 = (lane & 7) + ((lane >> 4) & 1) * 8;
    const int b_colb     = ((lane >> 3) & 1) * 16;

    for (int i = 0; i < GNS; i++) {
        prefetch_chunk(Ah, Al, Bh, Bl, K, mtile, ntile, i * CK,
                       sbase + i * STAGE, tid);
        asm volatile("cp.async.commit_group;" ::: "memory");
    }

    for (int i = 0; i < nch; i++) {
        const int s = i % GNS;
        const uint32_t tb = sbase + s * STAGE;
        asm volatile("cp.async.wait_group %0;" :: "n"(GNS - 1) : "memory");
        __syncthreads();

        const uint32_t aH = tb;
        const uint32_t aL = tb + PLANE;
        const uint32_t bH = tb + 2 * PLANE;
        const uint32_t bL = tb + 3 * PLANE;

        #pragma unroll
        for (int ks = 0; ks < 2; ks++) {
            const int kb = ks * 32;
            uint32_t fAh[4][4], fAl[4][4], fBh[2][4], fBl[2][4];
            #pragma unroll
            for (int mi = 0; mi < 4; mi++) {
                int row = wm * 64 + mi * 16 + a_row_in16;
                uint32_t addr = row * (PADW * 2) + a_colb + kb;
                ldsm4(fAh[mi], aH + addr);
                ldsm4(fAl[mi], aL + addr);
            }
            #pragma unroll
            for (int ng = 0; ng < 2; ng++) {
                int row = wn * 32 + ng * 16 + b_row_in16;
                uint32_t addr = row * (PADW * 2) + b_colb + kb;
                ldsm4(fBh[ng], bH + addr);
                ldsm4(fBl[ng], bL + addr);
            }
            #pragma unroll
            for (int mi = 0; mi < 4; mi++) {
                #pragma unroll
                for (int ni = 0; ni < 4; ni++) {
                    const int ng = ni >> 1, hf = (ni & 1) * 2;
                    mma_bf16(acc[mi][ni], fAh[mi], fBh[ng][hf], fBh[ng][hf + 1]);
                    mma_bf16(acc[mi][ni], fAh[mi], fBl[ng][hf], fBl[ng][hf + 1]);
                    mma_bf16(acc[mi][ni], fAl[mi], fBh[ng][hf], fBh[ng][hf + 1]);
                }
            }
        }
        __syncthreads();

        if (i + GNS < nch)
            prefetch_chunk(Ah, Al, Bh, Bl, K, mtile, ntile, (i + GNS) * CK,
                           sbase + s * STAGE, tid);
        asm volatile("cp.async.commit_group;" ::: "memory");
    }

    const int r0b = mtile + wm * 64 + (lane >> 2);
    const int c0b = ntile + wn * 32 + (lane & 3) * 2;
    #pragma unroll
    for (int mi = 0; mi < 4; mi++) {
        #pragma unroll
        for (int ni = 0; ni < 4; ni++) {
            size_t o0 = (size_t)(r0b + mi * 16) * N + c0b + ni * 8;
            size_t o1 = (size_t)(r0b + mi * 16 + 8) * N + c0b + ni * 8;
            if (OUTBF == 0) {
                *(float2*)(C + o0) = make_float2(acc[mi][ni][0], acc[mi][ni][1]);
                *(float2*)(C + o1) = make_float2(acc[mi][ni][2], acc[mi][ni][3]);
            } else {
                float v0 = acc[mi][ni][0], v1 = acc[mi][ni][1];
                float v2 = acc[mi][ni][2], v3 = acc[mi][ni][3];
                uint32_t h0 = pack_bf2(v0, v1), h1 = pack_bf2(v2, v3);
                float r0x = v0 - __bfloat162float(__float2bfloat16(v0));
                float r0y = v1 - __bfloat162float(__float2bfloat16(v1));
                float r1x = v2 - __bfloat162float(__float2bfloat16(v2));
                float r1y = v3 - __bfloat162float(__float2bfloat16(v3));
                *(uint32_t*)(Ch + o0) = h0;
                *(uint32_t*)(Ch + o1) = h1;
                *(uint32_t*)(Cl + o0) = pack_bf2(r0x, r0y);
                *(uint32_t*)(Cl + o1) = pack_bf2(r1x, r1y);
            }
        }
    }
}

// ---------------------------------------------------------------------------
// Conversions (x and weights only)
// ---------------------------------------------------------------------------
__global__ void conv_hilo(const float* __restrict__ in,
                          __nv_bfloat16* __restrict__ hi,
                          __nv_bfloat16* __restrict__ lo, int n4)
{
    int i = blockIdx.x * blockDim.x + threadIdx.x;
    if (i >= n4) return;
    float4 v = ((const float4*)in)[i];
    __nv_bfloat16 h0 = __float2bfloat16(v.x), h1 = __float2bfloat16(v.y);
    __nv_bfloat16 h2 = __float2bfloat16(v.z), h3 = __float2bfloat16(v.w);
    __nv_bfloat16 l0 = __float2bfloat16(v.x - __bfloat162float(h0));
    __nv_bfloat16 l1 = __float2bfloat16(v.y - __bfloat162float(h1));
    __nv_bfloat16 l2 = __float2bfloat16(v.z - __bfloat162float(h2));
    __nv_bfloat16 l3 = __float2bfloat16(v.w - __bfloat162float(h3));
    ((__nv_bfloat162*)hi)[2 * i]     = __nv_bfloat162(h0, h1);
    ((__nv_bfloat162*)hi)[2 * i + 1] = __nv_bfloat162(h2, h3);
    ((__nv_bfloat162*)lo)[2 * i]     = __nv_bfloat162(l0, l1);
    ((__nv_bfloat162*)lo)[2 * i + 1] = __nv_bfloat162(l2, l3);
}

__global__ void convT_hilo(const float* __restrict__ W,
                           __nv_bfloat16* __restrict__ Th,
                           __nv_bfloat16* __restrict__ Tl, int K, int N)
{
    __shared__ float t[32][33];
    int n0 = blockIdx.x * 32, k0 = blockIdx.y * 32;
    int tx = threadIdx.x, ty0 = threadIdx.y;
    #pragma unroll
    for (int j = 0; j < 4; j++) {
        int ty = ty0 + 8 * j;
        t[ty][tx] = W[(size_t)(k0 + ty) * N + n0 + tx];
    }
    __syncthreads();
    #pragma unroll
    for (int j = 0; j < 4; j++) {
        int ty = ty0 + 8 * j;
        float v = t[tx][ty];
        __nv_bfloat16 h = __float2bfloat16(v);
        __nv_bfloat16 l = __float2bfloat16(v - __bfloat162float(h));
        Th[(size_t)(n0 + ty) * K + k0 + tx] = h;
        Tl[(size_t)(n0 + ty) * K + k0 + tx] = l;
    }
}

// ---------------------------------------------------------------------------
// Tensor-core flash attention (split bf16), causal GQA.
// CTA: 64 q rows, 4 warps (16 rows each). K tiles of 64. D=128.
// ---------------------------------------------------------------------------
constexpr int FB_STRIDE_B = 272;             // bytes per smem row (136 bf16)
constexpr int FPLANE = 64 * FB_STRIDE_B;     // 17408
constexpr int FATTN_SMEM = 6 * FPLANE;       // 104448

__global__ __launch_bounds__(128) void fattn_kernel(
    const __nv_bfloat16* __restrict__ Qh_g, const __nv_bfloat16* __restrict__ Ql_g,
    const __nv_bfloat16* __restrict__ Kh_g, const __nv_bfloat16* __restrict__ Kl_g,
    const __nv_bfloat16* __restrict__ Vh_g, const __nv_bfloat16* __restrict__ Vl_g,
    __nv_bfloat16* __restrict__ Oh_g, __nv_bfloat16* __restrict__ Ol_g)
{
    extern __shared__ char smem[];
    const uint32_t sb = smem_u32(smem);
    const uint32_t sQh = sb,             sQl = sb + FPLANE;
    const uint32_t sKh = sb + 2*FPLANE,  sKl = sb + 3*FPLANE;
    const uint32_t sVh = sb + 4*FPLANE,  sVl = sb + 5*FPLANE;

    const int tid = threadIdx.x, wid = tid >> 5, lane = tid & 31;
    const int bx = blockIdx.x, h = blockIdx.y, b = blockIdx.z;
    const int q0 = bx * 64;
    const int kvh = h >> 2;   // h / NREP

    const __nv_bfloat16* qh = Qh_g + ((size_t)(b * S_LEN + q0)) * DIMN + h * HD;
    const __nv_bfloat16* ql = Ql_g + ((size_t)(b * S_LEN + q0)) * DIMN + h * HD;
    const __nv_bfloat16* kh = Kh_g + ((size_t)(b * S_LEN)) * KVDIM + kvh * HD;
    const __nv_bfloat16* kl = Kl_g + ((size_t)(b * S_LEN)) * KVDIM + kvh * HD;
    const __nv_bfloat16* vh = Vh_g + ((size_t)(b * S_LEN)) * KVDIM + kvh * HD;
    const __nv_bfloat16* vl = Vl_g + ((size_t)(b * S_LEN)) * KVDIM + kvh * HD;

    // Load Q tiles (hi/lo): 64 rows x 16 segs x 2 planes
    #pragma unroll
    for (int u = tid; u < 2048; u += 128) {
        int plane = u >> 10, r = (u >> 4) & 63, seg = u & 15;
        const __nv_bfloat16* src = (plane ? ql : qh) + (size_t)r * DIMN + seg * 8;
        uint32_t dst = (plane ? sQl : sQh) + r * FB_STRIDE_B + seg * 16;
        asm volatile("cp.async.cg.shared.global [%0], [%1], 16;"
                     :: "r"(dst), "l"(src) : "memory");
    }
    asm volatile("cp.async.commit_group;" ::: "memory");

    float accO[16][4];
    #pragma unroll
    for (int t = 0; t < 16; t++)
        #pragma unroll
        for (int e = 0; e < 4; e++) accO[t][e] = 0.f;
    float m0 = -1e30f, m1 = -1e30f, l0 = 0.f, l1 = 0.f;

    const int a_r  = (lane & 7) + ((lane >> 3) & 1) * 8;
    const int a_cb = (lane >> 4) * 16;
    const int b_r  = (lane & 7) + ((lane >> 4) & 1) * 8;
    const int b_cb = ((lane >> 3) & 1) * 16;

    const float SL = 0.08838834764831845f * 1.4426950408889634f;  // scale*log2e

    for (int t = 0; t <= bx; t++) {
        const int kt0 = t * 64;
        __syncthreads();
        // Load K/V (hi/lo): 4 planes x 64 rows x 16 segs
        #pragma unroll
        for (int u = tid; u < 4096; u += 128) {
            int plane = u >> 10, r = (u >> 4) & 63, seg = u & 15;
            const __nv_bfloat16* src;
            uint32_t dplane;
            if (plane == 0)      { src = kh; dplane = sKh; }
            else if (plane == 1) { src = kl; dplane = sKl; }
            else if (plane == 2) { src = vh; dplane = sVh; }
            else                 { src = vl; dplane = sVl; }
            src += (size_t)(kt0 + r) * KVDIM + seg * 8;
            uint32_t dst = dplane + r * FB_STRIDE_B + seg * 16;
            asm volatile("cp.async.cg.shared.global [%0], [%1], 16;"
                         :: "r"(dst), "l"(src) : "memory");
        }
        asm volatile("cp.async.commit_group;" ::: "memory");
        asm volatile("cp.async.wait_group 0;" ::: "memory");
        __syncthreads();

        // ---- S = Q @ K^T (3-term split) ----
        float accS[8][4];
        #pragma unroll
        for (int ni = 0; ni < 8; ni++)
            #pragma unroll
            for (int e = 0; e < 4; e++) accS[ni][e] = 0.f;

        #pragma unroll
        for (int kk = 0; kk < 8; kk++) {
            uint32_t fQh[4], fQl[4];
            uint32_t aaddr = (wid * 16 + a_r) * FB_STRIDE_B + kk * 32 + a_cb;
            ldsm4(fQh, sQh + aaddr);
            ldsm4(fQl, sQl + aaddr);
            #pragma unroll
            for (int ng = 0; ng < 4; ng++) {
                uint32_t baddr = (ng * 16 + b_r) * FB_STRIDE_B + kk * 32 + b_cb;
                uint32_t fKh[4], fKl[4];
                ldsm4(fKh, sKh + baddr);
                ldsm4(fKl, sKl + baddr);
                #pragma unroll
                for (int hf2 = 0; hf2 < 2; hf2++) {
                    const int ni = ng * 2 + hf2;
                    mma_bf16(accS[ni], fQh, fKh[hf2 * 2], fKh[hf2 * 2 + 1]);
                    mma_bf16(accS[ni], fQh, fKl[hf2 * 2], fKl[hf2 * 2 + 1]);
                    mma_bf16(accS[ni], fQl, fKh[hf2 * 2], fKh[hf2 * 2 + 1]);
                }
            }
        }

        // scale into log2 domain
        #pragma unroll
        for (int ni = 0; ni < 8; ni++)
            #pragma unroll
            for (int e = 0; e < 4; e++) accS[ni][e] *= SL;

        // causal mask (diagonal tile only): local col > wid*16 + local row
        if (t == bx) {
            const int r0 = wid * 16 + (lane >> 2);
            #pragma unroll
            for (int ni = 0; ni < 8; ni++) {
                int c = ni * 8 + (lane & 3) * 2;
                if (c > r0)     accS[ni][0] = -1e30f;
                if (c + 1 > r0) accS[ni][1] = -1e30f;
                if (c > r0 + 8)     accS[ni][2] = -1e30f;
                if (c + 1 > r0 + 8) accS[ni][3] = -1e30f;
            }
        }

        // row maxes
        float mx0 = -1e30f, mx1 = -1e30f;
        #pragma unroll
        for (int ni = 0; ni < 8; ni++) {
            mx0 = fmaxf(mx0, fmaxf(accS[ni][0], accS[ni][1]));
            mx1 = fmaxf(mx1, fmaxf(accS[ni][2], accS[ni][3]));
        }
        mx0 = fmaxf(mx0, __shfl_xor_sync(0xffffffffu, mx0, 1));
        mx0 = fmaxf(mx0, __shfl_xor_sync(0xffffffffu, mx0, 2));
        mx1 = fmaxf(mx1, __shfl_xor_sync(0xffffffffu, mx1, 1));
        mx1 = fmaxf(mx1, __shfl_xor_sync(0xffffffffu, mx1, 2));

        const float mn0 = fmaxf(m0, mx0), mn1 = fmaxf(m1, mx1);
        const float al0 = exp2f(m0 - mn0), al1 = exp2f(m1 - mn1);
        m0 = mn0; m1 = mn1;

        // exp + hi/lo P fragments
        uint32_t phA[8], phB[8], plA[8], plB[8];
        float s0 = 0.f, s1 = 0.f;
        #pragma unroll
        for (int ni = 0; ni < 8; ni++) {
            float p0 = exp2f(accS[ni][0] - mn0);
            float p1 = exp2f(accS[ni][1] - mn0);
            float p2 = exp2f(accS[ni][2] - mn1);
            float p3 = exp2f(accS[ni][3] - mn1);
            s0 += p0 + p1; s1 += p2 + p3;
            phA[ni] = pack_bf2(p0, p1);
            phB[ni] = pack_bf2(p2, p3);
            float q0f = p0 - __bfloat162float(__float2bfloat16(p0));
            float q1f = p1 - __bfloat162float(__float2bfloat16(p1));
            float q2f = p2 - __bfloat162float(__float2bfloat16(p2));
            float q3f = p3 - __bfloat162float(__float2bfloat16(p3));
            plA[ni] = pack_bf2(q0f, q1f);
            plB[ni] = pack_bf2(q2f, q3f);
        }
        s0 += __shfl_xor_sync(0xffffffffu, s0, 1);
        s0 += __shfl_xor_sync(0xffffffffu, s0, 2);
        s1 += __shfl_xor_sync(0xffffffffu, s1, 1);
        s1 += __shfl_xor_sync(0xffffffffu, s1, 2);
        l0 = l0 * al0 + s0;
        l1 = l1 * al1 + s1;

        // rescale O
        #pragma unroll
        for (int ti = 0; ti < 16; ti++) {
            accO[ti][0] *= al0; accO[ti][1] *= al0;
            accO[ti][2] *= al1; accO[ti][3] *= al1;
        }

        // ---- O += P @ V (3-term split) ----
        #pragma unroll
        for (int j = 0; j < 4; j++) {
            uint32_t aPh[4] = { phA[2*j], phB[2*j], phA[2*j+1], phB[2*j+1] };
            uint32_t aPl[4] = { plA[2*j], plB[2*j], plA[2*j+1], plB[2*j+1] };
            #pragma unroll
            for (int dg = 0; dg < 8; dg++) {
                uint32_t vaddr = (j * 16 + (lane & 15)) * FB_STRIDE_B
                               + dg * 32 + (lane >> 4) * 16;
                uint32_t fVh[4], fVl[4];
                ldsm4t(fVh, sVh + vaddr);
                ldsm4t(fVl, sVl + vaddr);
                const int t0i = dg * 2, t1i = dg * 2 + 1;
                mma_bf16(accO[t0i], aPh, fVh[0], fVh[1]);
                mma_bf16(accO[t0i], aPh, fVl[0], fVl[1]);
                mma_bf16(accO[t0i], aPl, fVh[0], fVh[1]);
                mma_bf16(accO[t1i], aPh, fVh[2], fVh[3]);
                mma_bf16(accO[t1i], aPh, fVl[2], fVl[3]);
                mma_bf16(accO[t1i], aPl, fVh[2], fVh[3]);
            }
        }
    }

    // Epilogue: normalize, split hi/lo, store
    const float inv0 = 1.0f / l0, inv1 = 1.0f / l1;
    const size_t row0 = (size_t)(b * S_LEN + q0 + wid * 16 + (lane >> 2));
    const size_t row1 = row0 + 8;
    __nv_bfloat16* oh0 = Oh_g + row0 * DIMN + h * HD;
    __nv_bfloat16* oh1 = Oh_g + row1 * DIMN + h * HD;
    __nv_bfloat16* ol0 = Ol_g + row0 * DIMN + h * HD;
    __nv_bfloat16* ol1 = Ol_g + row1 * DIMN + h * HD;
    #pragma unroll
    for (int ti = 0; ti < 16; ti++) {
        int c = ti * 8 + (lane & 3) * 2;
        float v0 = accO[ti][0] * inv0, v1 = accO[ti][1] * inv0;
        float v2 = accO[ti][2] * inv1, v3 = accO[ti][3] * inv1;
        *(uint32_t*)(oh0 + c) = pack_bf2(v0, v1);
        *(uint32_t*)(oh1 + c) = pack_bf2(v2, v3);
        float r0x = v0 - __bfloat162float(__float2bfloat16(v0));
        float r0y = v1 - __bfloat162float(__float2bfloat16(v1));
        float r1x = v2 - __bfloat162float(__float2bfloat16(v2));
        float r1y = v3 - __bfloat162float(__float2bfloat16(v3));
        *(uint32_t*)(ol0 + c) = pack_bf2(r0x, r0y);
        *(uint32_t*)(ol1 + c) = pack_bf2(r1x, r1y);
    }
}

// ---------------------------------------------------------------------------
// Launch
// ---------------------------------------------------------------------------
extern "C" void kernel_launch(void* const* d_in, const int* in_sizes, int n_in,
                              void* d_out, int out_size)
{
    const float* x  = (const float*)d_in[0];
    const float* wq = (const float*)d_in[1];
    const float* wk = (const float*)d_in[2];
    const float* wv = (const float*)d_in[3];
    const float* wo = (const float*)d_in[4];
    float* out = (float*)d_out;

    __nv_bfloat16 *xh, *xl, *qh, *ql, *kh, *kl, *vh, *vl, *ah, *al;
    __nv_bfloat16 *wqh, *wql, *wkh, *wkl, *wvh, *wvl, *woh, *wol;
    cudaGetSymbolAddress((void**)&xh, g_xh);   cudaGetSymbolAddress((void**)&xl, g_xl);
    cudaGetSymbolAddress((void**)&qh, g_qh);   cudaGetSymbolAddress((void**)&ql, g_ql);
    cudaGetSymbolAddress((void**)&kh, g_kh);   cudaGetSymbolAddress((void**)&kl, g_kl);
    cudaGetSymbolAddress((void**)&vh, g_vh);   cudaGetSymbolAddress((void**)&vl, g_vl);
    cudaGetSymbolAddress((void**)&ah, g_ah);   cudaGetSymbolAddress((void**)&al, g_al);
    cudaGetSymbolAddress((void**)&wqh, g_wqT_h); cudaGetSymbolAddress((void**)&wql, g_wqT_l);
    cudaGetSymbolAddress((void**)&wkh, g_wkT_h); cudaGetSymbolAddress((void**)&wkl, g_wkT_l);
    cudaGetSymbolAddress((void**)&wvh, g_wvT_h); cudaGetSymbolAddress((void**)&wvl, g_wvT_l);
    cudaGetSymbolAddress((void**)&woh, g_woT_h); cudaGetSymbolAddress((void**)&wol, g_woT_l);

    cudaFuncSetAttribute(gemm_bf16_split<0>,
                         cudaFuncAttributeMaxDynamicSharedMemorySize, GEMM_SMEM);
    cudaFuncSetAttribute(gemm_bf16_split<1>,
                         cudaFuncAttributeMaxDynamicSharedMemorySize, GEMM_SMEM);
    cudaFuncSetAttribute(fattn_kernel,
                         cudaFuncAttributeMaxDynamicSharedMemorySize, FATTN_SMEM);

    // 1) Conversions (x + weights)
    int n4x = MROWS * DIMN / 4;
    conv_hilo<<<(n4x + 255) / 256, 256>>>(x, xh, xl, n4x);
    convT_hilo<<<dim3(DIMN / 32, DIMN / 32), dim3(32, 8)>>>(wq, wqh, wql, DIMN, DIMN);
    convT_hilo<<<dim3(KVDIM / 32, DIMN / 32), dim3(32, 8)>>>(wk, wkh, wkl, DIMN, KVDIM);
    convT_hilo<<<dim3(KVDIM / 32, DIMN / 32), dim3(32, 8)>>>(wv, wvh, wvl, DIMN, KVDIM);
    convT_hilo<<<dim3(DIMN / 32, DIMN / 32), dim3(32, 8)>>>(wo, woh, wol, DIMN, DIMN);

    // 2) Projections -> bf16 hi/lo planes
    gemm_bf16_split<1><<<dim3(DIMN / 128, MROWS / 128), 256, GEMM_SMEM>>>(
        MROWS, DIMN, DIMN, xh, xl, wqh, wql, nullptr, qh, ql);
    gemm_bf16_split<1><<<dim3(KVDIM / 128, MROWS / 128), 256, GEMM_SMEM>>>(
        MROWS, KVDIM, DIMN, xh, xl, wkh, wkl, nullptr, kh, kl);
    gemm_bf16_split<1><<<dim3(KVDIM / 128, MROWS / 128), 256, GEMM_SMEM>>>(
        MROWS, KVDIM, DIMN, xh, xl, wvh, wvl, nullptr, vh, vl);

    // 3) Tensor-core flash attention -> bf16 hi/lo planes
    fattn_kernel<<<dim3(S_LEN / 64, HQ, BATCH), 128, FATTN_SMEM>>>(
        qh, ql, kh, kl, vh, vl, ah, al);

    // 4) Output projection -> fp32 out
    gemm_bf16_split<0><<<dim3(DIMN / 128, MROWS / 128), 256, GEMM_SMEM>>>(
        MROWS, DIMN, DIMN, ah, al, woh, wol, out, nullptr, nullptr);
}

// round 5
// speedup vs baseline: 3.4563x; 1.0692x over previous
#include <cuda_runtime.h>
#include <cuda_bf16.h>
#include <cstdint>

// Problem constants
#define DIMN    4096
#define S_LEN   2048
#define BATCH   2
#define HQ      32
#define HKV     8
#define NREP    4
#define HD      128
#define MROWS   (BATCH * S_LEN)   // 4096
#define KVDIM   (HKV * HD)        // 1024

// ---------------------------------------------------------------------------
// Scratch (__device__ globals)
// ---------------------------------------------------------------------------
__device__ __nv_bfloat16 g_xh[(size_t)MROWS * DIMN];
__device__ __nv_bfloat16 g_xl[(size_t)MROWS * DIMN];
__device__ __nv_bfloat16 g_qh[(size_t)MROWS * DIMN];
__device__ __nv_bfloat16 g_ql[(size_t)MROWS * DIMN];
__device__ __nv_bfloat16 g_kh[(size_t)MROWS * KVDIM];
__device__ __nv_bfloat16 g_kl[(size_t)MROWS * KVDIM];
__device__ __nv_bfloat16 g_vh[(size_t)MROWS * KVDIM];
__device__ __nv_bfloat16 g_vl[(size_t)MROWS * KVDIM];
__device__ __nv_bfloat16 g_ah[(size_t)MROWS * DIMN];
__device__ __nv_bfloat16 g_al[(size_t)MROWS * DIMN];
__device__ __nv_bfloat16 g_wqT_h[(size_t)DIMN * DIMN];
__device__ __nv_bfloat16 g_wqT_l[(size_t)DIMN * DIMN];
__device__ __nv_bfloat16 g_woT_h[(size_t)DIMN * DIMN];
__device__ __nv_bfloat16 g_woT_l[(size_t)DIMN * DIMN];
__device__ __nv_bfloat16 g_wkT_h[(size_t)KVDIM * DIMN];
__device__ __nv_bfloat16 g_wkT_l[(size_t)KVDIM * DIMN];
__device__ __nv_bfloat16 g_wvT_h[(size_t)KVDIM * DIMN];
__device__ __nv_bfloat16 g_wvT_l[(size_t)KVDIM * DIMN];

// ---------------------------------------------------------------------------
// PTX helpers
// ---------------------------------------------------------------------------
__device__ __forceinline__ uint32_t smem_u32(const void* p) {
    return (uint32_t)__cvta_generic_to_shared(p);
}
__device__ __forceinline__ void ldsm4(uint32_t* r, uint32_t addr) {
    asm volatile("ldmatrix.sync.aligned.m8n8.x4.shared.b16 {%0,%1,%2,%3}, [%4];"
                 : "=r"(r[0]), "=r"(r[1]), "=r"(r[2]), "=r"(r[3]) : "r"(addr));
}
__device__ __forceinline__ void ldsm4t(uint32_t* r, uint32_t addr) {
    asm volatile("ldmatrix.sync.aligned.m8n8.x4.trans.shared.b16 {%0,%1,%2,%3}, [%4];"
                 : "=r"(r[0]), "=r"(r[1]), "=r"(r[2]), "=r"(r[3]) : "r"(addr));
}
__device__ __forceinline__ void mma_bf16(float* d, const uint32_t* a,
                                         const uint32_t b0, const uint32_t b1) {
    asm volatile(
        "mma.sync.aligned.m16n8k16.row.col.f32.bf16.bf16.f32 "
        "{%0,%1,%2,%3}, {%4,%5,%6,%7}, {%8,%9}, {%0,%1,%2,%3};"
        : "+f"(d[0]), "+f"(d[1]), "+f"(d[2]), "+f"(d[3])
        : "r"(a[0]), "r"(a[1]), "r"(a[2]), "r"(a[3]), "r"(b0), "r"(b1));
}
__device__ __forceinline__ uint32_t pack_bf2(float a, float b) {
    __nv_bfloat162 t = __float22bfloat162_rn(make_float2(a, b));
    return *(uint32_t*)&t;
}

// ---------------------------------------------------------------------------
// Split-bf16 tensor-core GEMM: C = (Ah+Al)[M,K] @ (Bh+Bl)[N,K]^T
// 2-stage pipeline, 2 CTAs/SM.
// ---------------------------------------------------------------------------
constexpr int CK    = 32;
constexpr int PADW  = 40;
constexpr int PLANE = 128 * PADW * 2;
constexpr int STAGE = 4 * PLANE;
constexpr int GNS   = 2;
constexpr int GEMM_SMEM = GNS * STAGE;     // 81920

__device__ __forceinline__ void prefetch_chunk(
    const __nv_bfloat16* Ah, const __nv_bfloat16* Al,
    const __nv_bfloat16* Bh, const __nv_bfloat16* Bl,
    int K, int mtile, int ntile, int k0, uint32_t tbase, int tid)
{
    #pragma unroll
    for (int u = tid; u < 2048; u += 256) {
        int plane = u >> 9;
        int r = (u >> 2) & 127;
        int seg = u & 3;
        const __nv_bfloat16* src;
        if (plane == 0)      src = Ah + (size_t)(mtile + r) * K + k0 + seg * 8;
        else if (plane == 1) src = Al + (size_t)(mtile + r) * K + k0 + seg * 8;
        else if (plane == 2) src = Bh + (size_t)(ntile + r) * K + k0 + seg * 8;
        else                 src = Bl + (size_t)(ntile + r) * K + k0 + seg * 8;
        uint32_t dst = tbase + plane * PLANE + r * (PADW * 2) + seg * 16;
        asm volatile("cp.async.cg.shared.global [%0], [%1], 16;"
                     :: "r"(dst), "l"(src) : "memory");
    }
}

template <int OUTBF>
__global__ __launch_bounds__(256, 2) void gemm_bf16_split(
    int M, int N, int K,
    const __nv_bfloat16* __restrict__ Ah, const __nv_bfloat16* __restrict__ Al,
    const __nv_bfloat16* __restrict__ Bh, const __nv_bfloat16* __restrict__ Bl,
    float* __restrict__ C,
    __nv_bfloat16* __restrict__ Ch, __nv_bfloat16* __restrict__ Cl)
{
    extern __shared__ char smem[];
    const uint32_t sbase = smem_u32(smem);

    const int tid = threadIdx.x;
    const int wid = tid >> 5, lane = tid & 31;
    const int wm = wid >> 2;
    const int wn = wid & 3;
    const int mtile = blockIdx.y * 128;
    const int ntile = blockIdx.x * 128;
    const int nch = K / CK;

    float acc[4][4][4];
    #pragma unroll
    for (int mi = 0; mi < 4; mi++)
        #pragma unroll
        for (int ni = 0; ni < 4; ni++)
            #pragma unroll
            for (int e = 0; e < 4; e++) acc[mi][ni][e] = 0.f;

    const int a_row_in16 = (lane & 7) + ((lane >> 3) & 1) * 8;
    const int a_colb     = (lane >> 4) * 16;
    const int b_row_in16 = (lane & 7) + ((lane >> 4) & 1) * 8;
    const int b_colb     = ((lane >> 3) & 1) * 16;

    for (int i = 0; i < GNS; i++) {
        prefetch_chunk(Ah, Al, Bh, Bl, K, mtile, ntile, i * CK,
                       sbase + i * STAGE, tid);
        asm volatile("cp.async.commit_group;" ::: "memory");
    }

    for (int i = 0; i < nch; i++) {
        const int s = i % GNS;
        const uint32_t tb = sbase + s * STAGE;
        asm volatile("cp.async.wait_group %0;" :: "n"(GNS - 1) : "memory");
        __syncthreads();

        const uint32_t aH = tb;
        const uint32_t aL = tb + PLANE;
        const uint32_t bH = tb + 2 * PLANE;
        const uint32_t bL = tb + 3 * PLANE;

        #pragma unroll
        for (int ks = 0; ks < 2; ks++) {
            const int kb = ks * 32;
            uint32_t fAh[4][4], fAl[4][4], fBh[2][4], fBl[2][4];
            #pragma unroll
            for (int mi = 0; mi < 4; mi++) {
                int row = wm * 64 + mi * 16 + a_row_in16;
                uint32_t addr = row * (PADW * 2) + a_colb + kb;
                ldsm4(fAh[mi], aH + addr);
                ldsm4(fAl[mi], aL + addr);
            }
            #pragma unroll
            for (int ng = 0; ng < 2; ng++) {
                int row = wn * 32 + ng * 16 + b_row_in16;
                uint32_t addr = row * (PADW * 2) + b_colb + kb;
                ldsm4(fBh[ng], bH + addr);
                ldsm4(fBl[ng], bL + addr);
            }
            #pragma unroll
            for (int mi = 0; mi < 4; mi++) {
                #pragma unroll
                for (int ni = 0; ni < 4; ni++) {
                    const int ng = ni >> 1, hf = (ni & 1) * 2;
                    mma_bf16(acc[mi][ni], fAh[mi], fBh[ng][hf], fBh[ng][hf + 1]);
                    mma_bf16(acc[mi][ni], fAh[mi], fBl[ng][hf], fBl[ng][hf + 1]);
                    mma_bf16(acc[mi][ni], fAl[mi], fBh[ng][hf], fBh[ng][hf + 1]);
                }
            }
        }
        __syncthreads();

        if (i + GNS < nch)
            prefetch_chunk(Ah, Al, Bh, Bl, K, mtile, ntile, (i + GNS) * CK,
                           sbase + s * STAGE, tid);
        asm volatile("cp.async.commit_group;" ::: "memory");
    }

    const int r0b = mtile + wm * 64 + (lane >> 2);
    const int c0b = ntile + wn * 32 + (lane & 3) * 2;
    #pragma unroll
    for (int mi = 0; mi < 4; mi++) {
        #pragma unroll
        for (int ni = 0; ni < 4; ni++) {
            size_t o0 = (size_t)(r0b + mi * 16) * N + c0b + ni * 8;
            size_t o1 = (size_t)(r0b + mi * 16 + 8) * N + c0b + ni * 8;
            if (OUTBF == 0) {
                *(float2*)(C + o0) = make_float2(acc[mi][ni][0], acc[mi][ni][1]);
                *(float2*)(C + o1) = make_float2(acc[mi][ni][2], acc[mi][ni][3]);
            } else {
                float v0 = acc[mi][ni][0], v1 = acc[mi][ni][1];
                float v2 = acc[mi][ni][2], v3 = acc[mi][ni][3];
                uint32_t h0 = pack_bf2(v0, v1), h1 = pack_bf2(v2, v3);
                float r0x = v0 - __bfloat162float(__float2bfloat16(v0));
                float r0y = v1 - __bfloat162float(__float2bfloat16(v1));
                float r1x = v2 - __bfloat162float(__float2bfloat16(v2));
                float r1y = v3 - __bfloat162float(__float2bfloat16(v3));
                *(uint32_t*)(Ch + o0) = h0;
                *(uint32_t*)(Ch + o1) = h1;
                *(uint32_t*)(Cl + o0) = pack_bf2(r0x, r0y);
                *(uint32_t*)(Cl + o1) = pack_bf2(r1x, r1y);
            }
        }
    }
}

// ---------------------------------------------------------------------------
// Conversions (x and weights only)
// ---------------------------------------------------------------------------
__global__ void conv_hilo(const float* __restrict__ in,
                          __nv_bfloat16* __restrict__ hi,
                          __nv_bfloat16* __restrict__ lo, int n4)
{
    int i = blockIdx.x * blockDim.x + threadIdx.x;
    if (i >= n4) return;
    float4 v = ((const float4*)in)[i];
    __nv_bfloat16 h0 = __float2bfloat16(v.x), h1 = __float2bfloat16(v.y);
    __nv_bfloat16 h2 = __float2bfloat16(v.z), h3 = __float2bfloat16(v.w);
    __nv_bfloat16 l0 = __float2bfloat16(v.x - __bfloat162float(h0));
    __nv_bfloat16 l1 = __float2bfloat16(v.y - __bfloat162float(h1));
    __nv_bfloat16 l2 = __float2bfloat16(v.z - __bfloat162float(h2));
    __nv_bfloat16 l3 = __float2bfloat16(v.w - __bfloat162float(h3));
    ((__nv_bfloat162*)hi)[2 * i]     = __nv_bfloat162(h0, h1);
    ((__nv_bfloat162*)hi)[2 * i + 1] = __nv_bfloat162(h2, h3);
    ((__nv_bfloat162*)lo)[2 * i]     = __nv_bfloat162(l0, l1);
    ((__nv_bfloat162*)lo)[2 * i + 1] = __nv_bfloat162(l2, l3);
}

__global__ void convT_hilo(const float* __restrict__ W,
                           __nv_bfloat16* __restrict__ Th,
                           __nv_bfloat16* __restrict__ Tl, int K, int N)
{
    __shared__ float t[32][33];
    int n0 = blockIdx.x * 32, k0 = blockIdx.y * 32;
    int tx = threadIdx.x, ty0 = threadIdx.y;
    #pragma unroll
    for (int j = 0; j < 4; j++) {
        int ty = ty0 + 8 * j;
        t[ty][tx] = W[(size_t)(k0 + ty) * N + n0 + tx];
    }
    __syncthreads();
    #pragma unroll
    for (int j = 0; j < 4; j++) {
        int ty = ty0 + 8 * j;
        float v = t[tx][ty];
        __nv_bfloat16 h = __float2bfloat16(v);
        __nv_bfloat16 l = __float2bfloat16(v - __bfloat162float(h));
        Th[(size_t)(n0 + ty) * K + k0 + tx] = h;
        Tl[(size_t)(n0 + ty) * K + k0 + tx] = l;
    }
}

// ---------------------------------------------------------------------------
// Tensor-core flash attention (split bf16), causal GQA.
// CTA: 64 q rows, 4 warps. K tiles of 64. Double-buffered K/V.
// smem: 2 Q planes + 2 stages x 4 K/V planes = 10 planes.
// ---------------------------------------------------------------------------
constexpr int FB_STRIDE_B = 272;
constexpr int FPLANE = 64 * FB_STRIDE_B;       // 17408
constexpr int FATTN_SMEM = 10 * FPLANE;        // 174080

__global__ __launch_bounds__(128) void fattn_kernel(
    const __nv_bfloat16* __restrict__ Qh_g, const __nv_bfloat16* __restrict__ Ql_g,
    const __nv_bfloat16* __restrict__ Kh_g, const __nv_bfloat16* __restrict__ Kl_g,
    const __nv_bfloat16* __restrict__ Vh_g, const __nv_bfloat16* __restrict__ Vl_g,
    __nv_bfloat16* __restrict__ Oh_g, __nv_bfloat16* __restrict__ Ol_g)
{
    extern __shared__ char smem[];
    const uint32_t sb = smem_u32(smem);
    const uint32_t sQh = sb, sQl = sb + FPLANE;
    // stage s (s=0,1): K/V planes at sb + (2 + 4*s)*FPLANE

    const int tid = threadIdx.x, wid = tid >> 5, lane = tid & 31;
    const int bx = blockIdx.x, h = blockIdx.y, b = blockIdx.z;
    const int q0 = bx * 64;
    const int kvh = h >> 2;

    const __nv_bfloat16* qh = Qh_g + ((size_t)(b * S_LEN + q0)) * DIMN + h * HD;
    const __nv_bfloat16* ql = Ql_g + ((size_t)(b * S_LEN + q0)) * DIMN + h * HD;
    const __nv_bfloat16* kh = Kh_g + ((size_t)(b * S_LEN)) * KVDIM + kvh * HD;
    const __nv_bfloat16* kl = Kl_g + ((size_t)(b * S_LEN)) * KVDIM + kvh * HD;
    const __nv_bfloat16* vh = Vh_g + ((size_t)(b * S_LEN)) * KVDIM + kvh * HD;
    const __nv_bfloat16* vl = Vl_g + ((size_t)(b * S_LEN)) * KVDIM + kvh * HD;

    // KV tile loader into stage s
    auto load_kv = [&](int kt0, int s) {
        const uint32_t base = sb + (2 + 4 * s) * FPLANE;
        #pragma unroll
        for (int u = tid; u < 4096; u += 128) {
            int plane = u >> 10, r = (u >> 4) & 63, seg = u & 15;
            const __nv_bfloat16* src;
            if (plane == 0)      src = kh;
            else if (plane == 1) src = kl;
            else if (plane == 2) src = vh;
            else                 src = vl;
            src += (size_t)(kt0 + r) * KVDIM + seg * 8;
            uint32_t dst = base + plane * FPLANE + r * FB_STRIDE_B + seg * 16;
            asm volatile("cp.async.cg.shared.global [%0], [%1], 16;"
                         :: "r"(dst), "l"(src) : "memory");
        }
    };

    // Prologue: Q + KV(0) in group 0
    #pragma unroll
    for (int u = tid; u < 2048; u += 128) {
        int plane = u >> 10, r = (u >> 4) & 63, seg = u & 15;
        const __nv_bfloat16* src = (plane ? ql : qh) + (size_t)r * DIMN + seg * 8;
        uint32_t dst = (plane ? sQl : sQh) + r * FB_STRIDE_B + seg * 16;
        asm volatile("cp.async.cg.shared.global [%0], [%1], 16;"
                     :: "r"(dst), "l"(src) : "memory");
    }
    load_kv(0, 0);
    asm volatile("cp.async.commit_group;" ::: "memory");

    float accO[16][4];
    #pragma unroll
    for (int t = 0; t < 16; t++)
        #pragma unroll
        for (int e = 0; e < 4; e++) accO[t][e] = 0.f;
    float m0 = -1e30f, m1 = -1e30f, l0 = 0.f, l1 = 0.f;

    const int a_r  = (lane & 7) + ((lane >> 3) & 1) * 8;
    const int a_cb = (lane >> 4) * 16;
    const int b_r  = (lane & 7) + ((lane >> 4) & 1) * 8;
    const int b_cb = ((lane >> 3) & 1) * 16;

    const float SL = 0.08838834764831845f * 1.4426950408889634f;

    for (int t = 0; t <= bx; t++) {
        const int cur = t & 1;
        if (t < bx) {
            load_kv((t + 1) * 64, cur ^ 1);
            asm volatile("cp.async.commit_group;" ::: "memory");
            asm volatile("cp.async.wait_group 1;" ::: "memory");
        } else {
            asm volatile("cp.async.wait_group 0;" ::: "memory");
        }
        __syncthreads();

        const uint32_t kvb = sb + (2 + 4 * cur) * FPLANE;
        const uint32_t sKh = kvb, sKl = kvb + FPLANE;
        const uint32_t sVh = kvb + 2 * FPLANE, sVl = kvb + 3 * FPLANE;

        // ---- S = Q @ K^T (3-term split) ----
        float accS[8][4];
        #pragma unroll
        for (int ni = 0; ni < 8; ni++)
            #pragma unroll
            for (int e = 0; e < 4; e++) accS[ni][e] = 0.f;

        #pragma unroll
        for (int kk = 0; kk < 8; kk++) {
            uint32_t fQh[4], fQl[4];
            uint32_t aaddr = (wid * 16 + a_r) * FB_STRIDE_B + kk * 32 + a_cb;
            ldsm4(fQh, sQh + aaddr);
            ldsm4(fQl, sQl + aaddr);
            #pragma unroll
            for (int ng = 0; ng < 4; ng++) {
                uint32_t baddr = (ng * 16 + b_r) * FB_STRIDE_B + kk * 32 + b_cb;
                uint32_t fKh[4], fKl[4];
                ldsm4(fKh, sKh + baddr);
                ldsm4(fKl, sKl + baddr);
                #pragma unroll
                for (int hf2 = 0; hf2 < 2; hf2++) {
                    const int ni = ng * 2 + hf2;
                    mma_bf16(accS[ni], fQh, fKh[hf2 * 2], fKh[hf2 * 2 + 1]);
                    mma_bf16(accS[ni], fQh, fKl[hf2 * 2], fKl[hf2 * 2 + 1]);
                    mma_bf16(accS[ni], fQl, fKh[hf2 * 2], fKh[hf2 * 2 + 1]);
                }
            }
        }

        #pragma unroll
        for (int ni = 0; ni < 8; ni++)
            #pragma unroll
            for (int e = 0; e < 4; e++) accS[ni][e] *= SL;

        if (t == bx) {
            const int r0 = wid * 16 + (lane >> 2);
            #pragma unroll
            for (int ni = 0; ni < 8; ni++) {
                int c = ni * 8 + (lane & 3) * 2;
                if (c > r0)     accS[ni][0] = -1e30f;
                if (c + 1 > r0) accS[ni][1] = -1e30f;
                if (c > r0 + 8)     accS[ni][2] = -1e30f;
                if (c + 1 > r0 + 8) accS[ni][3] = -1e30f;
            }
        }

        float mx0 = -1e30f, mx1 = -1e30f;
        #pragma unroll
        for (int ni = 0; ni < 8; ni++) {
            mx0 = fmaxf(mx0, fmaxf(accS[ni][0], accS[ni][1]));
            mx1 = fmaxf(mx1, fmaxf(accS[ni][2], accS[ni][3]));
        }
        mx0 = fmaxf(mx0, __shfl_xor_sync(0xffffffffu, mx0, 1));
        mx0 = fmaxf(mx0, __shfl_xor_sync(0xffffffffu, mx0, 2));
        mx1 = fmaxf(mx1, __shfl_xor_sync(0xffffffffu, mx1, 1));
        mx1 = fmaxf(mx1, __shfl_xor_sync(0xffffffffu, mx1, 2));

        const float mn0 = fmaxf(m0, mx0), mn1 = fmaxf(m1, mx1);
        const float al0 = exp2f(m0 - mn0), al1 = exp2f(m1 - mn1);
        m0 = mn0; m1 = mn1;

        uint32_t phA[8], phB[8], plA[8], plB[8];
        float s0 = 0.f, s1 = 0.f;
        #pragma unroll
        for (int ni = 0; ni < 8; ni++) {
            float p0 = exp2f(accS[ni][0] - mn0);
            float p1 = exp2f(accS[ni][1] - mn0);
            float p2 = exp2f(accS[ni][2] - mn1);
            float p3 = exp2f(accS[ni][3] - mn1);
            s0 += p0 + p1; s1 += p2 + p3;
            phA[ni] = pack_bf2(p0, p1);
            phB[ni] = pack_bf2(p2, p3);
            float q0f = p0 - __bfloat162float(__float2bfloat16(p0));
            float q1f = p1 - __bfloat162float(__float2bfloat16(p1));
            float q2f = p2 - __bfloat162float(__float2bfloat16(p2));
            float q3f = p3 - __bfloat162float(__float2bfloat16(p3));
            plA[ni] = pack_bf2(q0f, q1f);
            plB[ni] = pack_bf2(q2f, q3f);
        }
        s0 += __shfl_xor_sync(0xffffffffu, s0, 1);
        s0 += __shfl_xor_sync(0xffffffffu, s0, 2);
        s1 += __shfl_xor_sync(0xffffffffu, s1, 1);
        s1 += __shfl_xor_sync(0xffffffffu, s1, 2);
        l0 = l0 * al0 + s0;
        l1 = l1 * al1 + s1;

        #pragma unroll
        for (int ti = 0; ti < 16; ti++) {
            accO[ti][0] *= al0; accO[ti][1] *= al0;
            accO[ti][2] *= al1; accO[ti][3] *= al1;
        }

        // ---- O += P @ V (3-term split) ----
        #pragma unroll
        for (int j = 0; j < 4; j++) {
            uint32_t aPh[4] = { phA[2*j], phB[2*j], phA[2*j+1], phB[2*j+1] };
            uint32_t aPl[4] = { plA[2*j], plB[2*j], plA[2*j+1], plB[2*j+1] };
            #pragma unroll
            for (int dg = 0; dg < 8; dg++) {
                uint32_t vaddr = (j * 16 + (lane & 15)) * FB_STRIDE_B
                               + dg * 32 + (lane >> 4) * 16;
                uint32_t fVh[4], fVl[4];
                ldsm4t(fVh, sVh + vaddr);
                ldsm4t(fVl, sVl + vaddr);
                const int t0i = dg * 2, t1i = dg * 2 + 1;
                mma_bf16(accO[t0i], aPh, fVh[0], fVh[1]);
                mma_bf16(accO[t0i], aPh, fVl[0], fVl[1]);
                mma_bf16(accO[t0i], aPl, fVh[0], fVh[1]);
                mma_bf16(accO[t1i], aPh, fVh[2], fVh[3]);
                mma_bf16(accO[t1i], aPh, fVl[2], fVl[3]);
                mma_bf16(accO[t1i], aPl, fVh[2], fVh[3]);
            }
        }
        __syncthreads();  // compute done before next iter overwrites this stage
    }

    const float inv0 = 1.0f / l0, inv1 = 1.0f / l1;
    const size_t row0 = (size_t)(b * S_LEN + q0 + wid * 16 + (lane >> 2));
    const size_t row1 = row0 + 8;
    __nv_bfloat16* oh0 = Oh_g + row0 * DIMN + h * HD;
    __nv_bfloat16* oh1 = Oh_g + row1 * DIMN + h * HD;
    __nv_bfloat16* ol0 = Ol_g + row0 * DIMN + h * HD;
    __nv_bfloat16* ol1 = Ol_g + row1 * DIMN + h * HD;
    #pragma unroll
    for (int ti = 0; ti < 16; ti++) {
        int c = ti * 8 + (lane & 3) * 2;
        float v0 = accO[ti][0] * inv0, v1 = accO[ti][1] * inv0;
        float v2 = accO[ti][2] * inv1, v3 = accO[ti][3] * inv1;
        *(uint32_t*)(oh0 + c) = pack_bf2(v0, v1);
        *(uint32_t*)(oh1 + c) = pack_bf2(v2, v3);
        float r0x = v0 - __bfloat162float(__float2bfloat16(v0));
        float r0y = v1 - __bfloat162float(__float2bfloat16(v1));
        float r1x = v2 - __bfloat162float(__float2bfloat16(v2));
        float r1y = v3 - __bfloat162float(__float2bfloat16(v3));
        *(uint32_t*)(ol0 + c) = pack_bf2(r0x, r0y);
        *(uint32_t*)(ol1 + c) = pack_bf2(r1x, r1y);
    }
}

// ---------------------------------------------------------------------------
// Launch
// ---------------------------------------------------------------------------
extern "C" void kernel_launch(void* const* d_in, const int* in_sizes, int n_in,
                              void* d_out, int out_size)
{
    const float* x  = (const float*)d_in[0];
    const float* wq = (const float*)d_in[1];
    const float* wk = (const float*)d_in[2];
    const float* wv = (const float*)d_in[3];
    const float* wo = (const float*)d_in[4];
    float* out = (float*)d_out;

    __nv_bfloat16 *xh, *xl, *qh, *ql, *kh, *kl, *vh, *vl, *ah, *al;
    __nv_bfloat16 *wqh, *wql, *wkh, *wkl, *wvh, *wvl, *woh, *wol;
    cudaGetSymbolAddress((void**)&xh, g_xh);   cudaGetSymbolAddress((void**)&xl, g_xl);
    cudaGetSymbolAddress((void**)&qh, g_qh);   cudaGetSymbolAddress((void**)&ql, g_ql);
    cudaGetSymbolAddress((void**)&kh, g_kh);   cudaGetSymbolAddress((void**)&kl, g_kl);
    cudaGetSymbolAddress((void**)&vh, g_vh);   cudaGetSymbolAddress((void**)&vl, g_vl);
    cudaGetSymbolAddress((void**)&ah, g_ah);   cudaGetSymbolAddress((void**)&al, g_al);
    cudaGetSymbolAddress((void**)&wqh, g_wqT_h); cudaGetSymbolAddress((void**)&wql, g_wqT_l);
    cudaGetSymbolAddress((void**)&wkh, g_wkT_h); cudaGetSymbolAddress((void**)&wkl, g_wkT_l);
    cudaGetSymbolAddress((void**)&wvh, g_wvT_h); cudaGetSymbolAddress((void**)&wvl, g_wvT_l);
    cudaGetSymbolAddress((void**)&woh, g_woT_h); cudaGetSymbolAddress((void**)&wol, g_woT_l);

    cudaFuncSetAttribute(gemm_bf16_split<0>,
                         cudaFuncAttributeMaxDynamicSharedMemorySize, GEMM_SMEM);
    cudaFuncSetAttribute(gemm_bf16_split<1>,
                         cudaFuncAttributeMaxDynamicSharedMemorySize, GEMM_SMEM);
    cudaFuncSetAttribute(fattn_kernel,
                         cudaFuncAttributeMaxDynamicSharedMemorySize, FATTN_SMEM);

    int n4x = MROWS * DIMN / 4;
    conv_hilo<<<(n4x + 255) / 256, 256>>>(x, xh, xl, n4x);
    convT_hilo<<<dim3(DIMN / 32, DIMN / 32), dim3(32, 8)>>>(wq, wqh, wql, DIMN, DIMN);
    convT_hilo<<<dim3(KVDIM / 32, DIMN / 32), dim3(32, 8)>>>(wk, wkh, wkl, DIMN, KVDIM);
    convT_hilo<<<dim3(KVDIM / 32, DIMN / 32), dim3(32, 8)>>>(wv, wvh, wvl, DIMN, KVDIM);
    convT_hilo<<<dim3(DIMN / 32, DIMN / 32), dim3(32, 8)>>>(wo, woh, wol, DIMN, DIMN);

    gemm_bf16_split<1><<<dim3(DIMN / 128, MROWS / 128), 256, GEMM_SMEM>>>(
        MROWS, DIMN, DIMN, xh, xl, wqh, wql, nullptr, qh, ql);
    gemm_bf16_split<1><<<dim3(KVDIM / 128, MROWS / 128), 256, GEMM_SMEM>>>(
        MROWS, KVDIM, DIMN, xh, xl, wkh, wkl, nullptr, kh, kl);
    gemm_bf16_split<1><<<dim3(KVDIM / 128, MROWS / 128), 256, GEMM_SMEM>>>(
        MROWS, KVDIM, DIMN, xh, xl, wvh, wvl, nullptr, vh, vl);

    fattn_kernel<<<dim3(S_LEN / 64, HQ, BATCH), 128, FATTN_SMEM>>>(
        qh, ql, kh, kl, vh, vl, ah, al);

    gemm_bf16_split<0><<<dim3(DIMN / 128, MROWS / 128), 256, GEMM_SMEM>>>(
        MROWS, DIMN, DIMN, ah, al, woh, wol, out, nullptr, nullptr);
}

// round 6
// speedup vs baseline: 3.4983x; 1.0122x over previous
#include <cuda_runtime.h>
#include <cuda_bf16.h>
#include <cstdint>

// Problem constants
#define DIMN    4096
#define S_LEN   2048
#define BATCH   2
#define HQ      32
#define HKV     8
#define NREP    4
#define HD      128
#define MROWS   (BATCH * S_LEN)   // 4096
#define KVDIM   (HKV * HD)        // 1024

// ---------------------------------------------------------------------------
// Scratch (__device__ globals)
// ---------------------------------------------------------------------------
__device__ __nv_bfloat16 g_xh[(size_t)MROWS * DIMN];
__device__ __nv_bfloat16 g_xl[(size_t)MROWS * DIMN];
__device__ __nv_bfloat16 g_qh[(size_t)MROWS * DIMN];
__device__ __nv_bfloat16 g_ql[(size_t)MROWS * DIMN];
__device__ __nv_bfloat16 g_kh[(size_t)MROWS * KVDIM];
__device__ __nv_bfloat16 g_kl[(size_t)MROWS * KVDIM];
__device__ __nv_bfloat16 g_vh[(size_t)MROWS * KVDIM];
__device__ __nv_bfloat16 g_vl[(size_t)MROWS * KVDIM];
__device__ __nv_bfloat16 g_ah[(size_t)MROWS * DIMN];
__device__ __nv_bfloat16 g_al[(size_t)MROWS * DIMN];
__device__ __nv_bfloat16 g_wqT_h[(size_t)DIMN * DIMN];
__device__ __nv_bfloat16 g_wqT_l[(size_t)DIMN * DIMN];
__device__ __nv_bfloat16 g_woT_h[(size_t)DIMN * DIMN];
__device__ __nv_bfloat16 g_woT_l[(size_t)DIMN * DIMN];
__device__ __nv_bfloat16 g_wkT_h[(size_t)KVDIM * DIMN];
__device__ __nv_bfloat16 g_wkT_l[(size_t)KVDIM * DIMN];
__device__ __nv_bfloat16 g_wvT_h[(size_t)KVDIM * DIMN];
__device__ __nv_bfloat16 g_wvT_l[(size_t)KVDIM * DIMN];

// ---------------------------------------------------------------------------
// PTX helpers
// ---------------------------------------------------------------------------
__device__ __forceinline__ uint32_t smem_u32(const void* p) {
    return (uint32_t)__cvta_generic_to_shared(p);
}
__device__ __forceinline__ void ldsm4(uint32_t* r, uint32_t addr) {
    asm volatile("ldmatrix.sync.aligned.m8n8.x4.shared.b16 {%0,%1,%2,%3}, [%4];"
                 : "=r"(r[0]), "=r"(r[1]), "=r"(r[2]), "=r"(r[3]) : "r"(addr));
}
__device__ __forceinline__ void ldsm4t(uint32_t* r, uint32_t addr) {
    asm volatile("ldmatrix.sync.aligned.m8n8.x4.trans.shared.b16 {%0,%1,%2,%3}, [%4];"
                 : "=r"(r[0]), "=r"(r[1]), "=r"(r[2]), "=r"(r[3]) : "r"(addr));
}
__device__ __forceinline__ void mma_bf16(float* d, const uint32_t* a,
                                         const uint32_t b0, const uint32_t b1) {
    asm volatile(
        "mma.sync.aligned.m16n8k16.row.col.f32.bf16.bf16.f32 "
        "{%0,%1,%2,%3}, {%4,%5,%6,%7}, {%8,%9}, {%0,%1,%2,%3};"
        : "+f"(d[0]), "+f"(d[1]), "+f"(d[2]), "+f"(d[3])
        : "r"(a[0]), "r"(a[1]), "r"(a[2]), "r"(a[3]), "r"(b0), "r"(b1));
}
__device__ __forceinline__ uint32_t pack_bf2(float a, float b) {
    __nv_bfloat162 t = __float22bfloat162_rn(make_float2(a, b));
    return *(uint32_t*)&t;
}

// ---------------------------------------------------------------------------
// Split-bf16 tensor-core GEMM: C = (Ah+Al)[M,K] @ (Bh+Bl)[N,K]^T
// 2-stage pipeline, 2 CTAs/SM. Two-pass A loading to cap register pressure.
// ---------------------------------------------------------------------------
constexpr int CK    = 32;
constexpr int PADW  = 40;
constexpr int PLANE = 128 * PADW * 2;
constexpr int STAGE = 4 * PLANE;
constexpr int GNS   = 2;
constexpr int GEMM_SMEM = GNS * STAGE;     // 81920

__device__ __forceinline__ void prefetch_chunk(
    const __nv_bfloat16* Ah, const __nv_bfloat16* Al,
    const __nv_bfloat16* Bh, const __nv_bfloat16* Bl,
    int K, int mtile, int ntile, int k0, uint32_t tbase, int tid)
{
    #pragma unroll
    for (int u = tid; u < 2048; u += 256) {
        int plane = u >> 9;
        int r = (u >> 2) & 127;
        int seg = u & 3;
        const __nv_bfloat16* src;
        if (plane == 0)      src = Ah + (size_t)(mtile + r) * K + k0 + seg * 8;
        else if (plane == 1) src = Al + (size_t)(mtile + r) * K + k0 + seg * 8;
        else if (plane == 2) src = Bh + (size_t)(ntile + r) * K + k0 + seg * 8;
        else                 src = Bl + (size_t)(ntile + r) * K + k0 + seg * 8;
        uint32_t dst = tbase + plane * PLANE + r * (PADW * 2) + seg * 16;
        asm volatile("cp.async.cg.shared.global [%0], [%1], 16;"
                     :: "r"(dst), "l"(src) : "memory");
    }
}

template <int OUTBF>
__global__ __launch_bounds__(256, 2) void gemm_bf16_split(
    int M, int N, int K,
    const __nv_bfloat16* __restrict__ Ah, const __nv_bfloat16* __restrict__ Al,
    const __nv_bfloat16* __restrict__ Bh, const __nv_bfloat16* __restrict__ Bl,
    float* __restrict__ C,
    __nv_bfloat16* __restrict__ Ch, __nv_bfloat16* __restrict__ Cl)
{
    extern __shared__ char smem[];
    const uint32_t sbase = smem_u32(smem);

    const int tid = threadIdx.x;
    const int wid = tid >> 5, lane = tid & 31;
    const int wm = wid >> 2;
    const int wn = wid & 3;
    const int mtile = blockIdx.y * 128;
    const int ntile = blockIdx.x * 128;
    const int nch = K / CK;

    float acc[4][4][4];
    #pragma unroll
    for (int mi = 0; mi < 4; mi++)
        #pragma unroll
        for (int ni = 0; ni < 4; ni++)
            #pragma unroll
            for (int e = 0; e < 4; e++) acc[mi][ni][e] = 0.f;

    const int a_row_in16 = (lane & 7) + ((lane >> 3) & 1) * 8;
    const int a_colb     = (lane >> 4) * 16;
    const int b_row_in16 = (lane & 7) + ((lane >> 4) & 1) * 8;
    const int b_colb     = ((lane >> 3) & 1) * 16;

    for (int i = 0; i < GNS; i++) {
        prefetch_chunk(Ah, Al, Bh, Bl, K, mtile, ntile, i * CK,
                       sbase + i * STAGE, tid);
        asm volatile("cp.async.commit_group;" ::: "memory");
    }

    for (int i = 0; i < nch; i++) {
        const int s = i % GNS;
        const uint32_t tb = sbase + s * STAGE;
        asm volatile("cp.async.wait_group %0;" :: "n"(GNS - 1) : "memory");
        __syncthreads();

        const uint32_t aH = tb;
        const uint32_t aL = tb + PLANE;
        const uint32_t bH = tb + 2 * PLANE;
        const uint32_t bL = tb + 3 * PLANE;

        #pragma unroll
        for (int ks = 0; ks < 2; ks++) {
            const int kb = ks * 32;
            uint32_t fBh[2][4], fBl[2][4];
            #pragma unroll
            for (int ng = 0; ng < 2; ng++) {
                int row = wn * 32 + ng * 16 + b_row_in16;
                uint32_t addr = row * (PADW * 2) + b_colb + kb;
                ldsm4(fBh[ng], bH + addr);
                ldsm4(fBl[ng], bL + addr);
            }
            uint32_t fA[4][4];
            // Pass 1: A-high against B-high and B-low
            #pragma unroll
            for (int mi = 0; mi < 4; mi++) {
                int row = wm * 64 + mi * 16 + a_row_in16;
                ldsm4(fA[mi], aH + row * (PADW * 2) + a_colb + kb);
            }
            #pragma unroll
            for (int mi = 0; mi < 4; mi++)
                #pragma unroll
                for (int ni = 0; ni < 4; ni++) {
                    const int ng = ni >> 1, hf = (ni & 1) * 2;
                    mma_bf16(acc[mi][ni], fA[mi], fBh[ng][hf], fBh[ng][hf + 1]);
                    mma_bf16(acc[mi][ni], fA[mi], fBl[ng][hf], fBl[ng][hf + 1]);
                }
            // Pass 2: A-low against B-high (reuse fA registers)
            #pragma unroll
            for (int mi = 0; mi < 4; mi++) {
                int row = wm * 64 + mi * 16 + a_row_in16;
                ldsm4(fA[mi], aL + row * (PADW * 2) + a_colb + kb);
            }
            #pragma unroll
            for (int mi = 0; mi < 4; mi++)
                #pragma unroll
                for (int ni = 0; ni < 4; ni++) {
                    const int ng = ni >> 1, hf = (ni & 1) * 2;
                    mma_bf16(acc[mi][ni], fA[mi], fBh[ng][hf], fBh[ng][hf + 1]);
                }
        }
        __syncthreads();

        if (i + GNS < nch)
            prefetch_chunk(Ah, Al, Bh, Bl, K, mtile, ntile, (i + GNS) * CK,
                           sbase + s * STAGE, tid);
        asm volatile("cp.async.commit_group;" ::: "memory");
    }

    const int r0b = mtile + wm * 64 + (lane >> 2);
    const int c0b = ntile + wn * 32 + (lane & 3) * 2;
    #pragma unroll
    for (int mi = 0; mi < 4; mi++) {
        #pragma unroll
        for (int ni = 0; ni < 4; ni++) {
            size_t o0 = (size_t)(r0b + mi * 16) * N + c0b + ni * 8;
            size_t o1 = (size_t)(r0b + mi * 16 + 8) * N + c0b + ni * 8;
            if (OUTBF == 0) {
                *(float2*)(C + o0) = make_float2(acc[mi][ni][0], acc[mi][ni][1]);
                *(float2*)(C + o1) = make_float2(acc[mi][ni][2], acc[mi][ni][3]);
            } else {
                float v0 = acc[mi][ni][0], v1 = acc[mi][ni][1];
                float v2 = acc[mi][ni][2], v3 = acc[mi][ni][3];
                uint32_t h0 = pack_bf2(v0, v1), h1 = pack_bf2(v2, v3);
                float r0x = v0 - __bfloat162float(__float2bfloat16(v0));
                float r0y = v1 - __bfloat162float(__float2bfloat16(v1));
                float r1x = v2 - __bfloat162float(__float2bfloat16(v2));
                float r1y = v3 - __bfloat162float(__float2bfloat16(v3));
                *(uint32_t*)(Ch + o0) = h0;
                *(uint32_t*)(Ch + o1) = h1;
                *(uint32_t*)(Cl + o0) = pack_bf2(r0x, r0y);
                *(uint32_t*)(Cl + o1) = pack_bf2(r1x, r1y);
            }
        }
    }
}

// ---------------------------------------------------------------------------
// Conversions
// ---------------------------------------------------------------------------
__global__ void conv_hilo(const float* __restrict__ in,
                          __nv_bfloat16* __restrict__ hi,
                          __nv_bfloat16* __restrict__ lo, int n4)
{
    int i = blockIdx.x * blockDim.x + threadIdx.x;
    if (i >= n4) return;
    float4 v = ((const float4*)in)[i];
    __nv_bfloat16 h0 = __float2bfloat16(v.x), h1 = __float2bfloat16(v.y);
    __nv_bfloat16 h2 = __float2bfloat16(v.z), h3 = __float2bfloat16(v.w);
    __nv_bfloat16 l0 = __float2bfloat16(v.x - __bfloat162float(h0));
    __nv_bfloat16 l1 = __float2bfloat16(v.y - __bfloat162float(h1));
    __nv_bfloat16 l2 = __float2bfloat16(v.z - __bfloat162float(h2));
    __nv_bfloat16 l3 = __float2bfloat16(v.w - __bfloat162float(h3));
    ((__nv_bfloat162*)hi)[2 * i]     = __nv_bfloat162(h0, h1);
    ((__nv_bfloat162*)hi)[2 * i + 1] = __nv_bfloat162(h2, h3);
    ((__nv_bfloat162*)lo)[2 * i]     = __nv_bfloat162(l0, l1);
    ((__nv_bfloat162*)lo)[2 * i + 1] = __nv_bfloat162(l2, l3);
}

__global__ void convT_hilo(const float* __restrict__ W,
                           __nv_bfloat16* __restrict__ Th,
                           __nv_bfloat16* __restrict__ Tl, int K, int N)
{
    __shared__ float t[32][33];
    int n0 = blockIdx.x * 32, k0 = blockIdx.y * 32;
    int tx = threadIdx.x, ty0 = threadIdx.y;
    #pragma unroll
    for (int j = 0; j < 4; j++) {
        int ty = ty0 + 8 * j;
        t[ty][tx] = W[(size_t)(k0 + ty) * N + n0 + tx];
    }
    __syncthreads();
    #pragma unroll
    for (int j = 0; j < 4; j++) {
        int ty = ty0 + 8 * j;
        float v = t[tx][ty];
        __nv_bfloat16 h = __float2bfloat16(v);
        __nv_bfloat16 l = __float2bfloat16(v - __bfloat162float(h));
        Th[(size_t)(n0 + ty) * K + k0 + tx] = h;
        Tl[(size_t)(n0 + ty) * K + k0 + tx] = l;
    }
}

// ---------------------------------------------------------------------------
// Tensor-core flash attention (split bf16), causal GQA.
// CTA: 128 q rows, 8 warps (16 rows each). K tiles of 64, double-buffered.
// smem: 2 Q planes (128 rows) + 2 stages x 4 K/V planes (64 rows).
// ---------------------------------------------------------------------------
constexpr int FB_STRIDE_B = 272;
constexpr int FPLANE  = 64 * FB_STRIDE_B;      // 17408 (KV planes)
constexpr int QPLANE  = 128 * FB_STRIDE_B;     // 34816
constexpr int FATTN_SMEM = 2 * QPLANE + 8 * FPLANE;  // 208896

__global__ __launch_bounds__(256) void fattn_kernel(
    const __nv_bfloat16* __restrict__ Qh_g, const __nv_bfloat16* __restrict__ Ql_g,
    const __nv_bfloat16* __restrict__ Kh_g, const __nv_bfloat16* __restrict__ Kl_g,
    const __nv_bfloat16* __restrict__ Vh_g, const __nv_bfloat16* __restrict__ Vl_g,
    __nv_bfloat16* __restrict__ Oh_g, __nv_bfloat16* __restrict__ Ol_g)
{
    extern __shared__ char smem[];
    const uint32_t sb = smem_u32(smem);
    const uint32_t sQh = sb, sQl = sb + QPLANE;
    const uint32_t kvstart = sb + 2 * QPLANE;

    const int tid = threadIdx.x, wid = tid >> 5, lane = tid & 31;
    const int bx = blockIdx.x, h = blockIdx.y, b = blockIdx.z;
    const int q0 = bx * 128;
    const int kvh = h >> 2;

    const __nv_bfloat16* qh = Qh_g + ((size_t)(b * S_LEN + q0)) * DIMN + h * HD;
    const __nv_bfloat16* ql = Ql_g + ((size_t)(b * S_LEN + q0)) * DIMN + h * HD;
    const __nv_bfloat16* kh = Kh_g + ((size_t)(b * S_LEN)) * KVDIM + kvh * HD;
    const __nv_bfloat16* kl = Kl_g + ((size_t)(b * S_LEN)) * KVDIM + kvh * HD;
    const __nv_bfloat16* vh = Vh_g + ((size_t)(b * S_LEN)) * KVDIM + kvh * HD;
    const __nv_bfloat16* vl = Vl_g + ((size_t)(b * S_LEN)) * KVDIM + kvh * HD;

    auto load_kv = [&](int kt0, int s) {
        const uint32_t base = kvstart + 4 * s * FPLANE;
        #pragma unroll
        for (int u = tid; u < 4096; u += 256) {
            int plane = u >> 10, r = (u >> 4) & 63, seg = u & 15;
            const __nv_bfloat16* src;
            if (plane == 0)      src = kh;
            else if (plane == 1) src = kl;
            else if (plane == 2) src = vh;
            else                 src = vl;
            src += (size_t)(kt0 + r) * KVDIM + seg * 8;
            uint32_t dst = base + plane * FPLANE + r * FB_STRIDE_B + seg * 16;
            asm volatile("cp.async.cg.shared.global [%0], [%1], 16;"
                         :: "r"(dst), "l"(src) : "memory");
        }
    };

    // Prologue: Q (2 planes x 128 rows) + KV(0)
    #pragma unroll
    for (int u = tid; u < 4096; u += 256) {
        int plane = u >> 11, r = (u >> 4) & 127, seg = u & 15;
        const __nv_bfloat16* src = (plane ? ql : qh) + (size_t)r * DIMN + seg * 8;
        uint32_t dst = (plane ? sQl : sQh) + r * FB_STRIDE_B + seg * 16;
        asm volatile("cp.async.cg.shared.global [%0], [%1], 16;"
                     :: "r"(dst), "l"(src) : "memory");
    }
    load_kv(0, 0);
    asm volatile("cp.async.commit_group;" ::: "memory");

    float accO[16][4];
    #pragma unroll
    for (int t = 0; t < 16; t++)
        #pragma unroll
        for (int e = 0; e < 4; e++) accO[t][e] = 0.f;
    float m0 = -1e30f, m1 = -1e30f, l0 = 0.f, l1 = 0.f;

    const int a_r  = (lane & 7) + ((lane >> 3) & 1) * 8;
    const int a_cb = (lane >> 4) * 16;
    const int b_r  = (lane & 7) + ((lane >> 4) & 1) * 8;
    const int b_cb = ((lane >> 3) & 1) * 16;

    const float SL = 0.08838834764831845f * 1.4426950408889634f;

    const int n_tiles = 2 * bx + 2;
    for (int t = 0; t < n_tiles; t++) {
        const int kt0 = t * 64;
        const int cur = t & 1;
        if (t < n_tiles - 1) {
            load_kv((t + 1) * 64, cur ^ 1);
            asm volatile("cp.async.commit_group;" ::: "memory");
            asm volatile("cp.async.wait_group 1;" ::: "memory");
        } else {
            asm volatile("cp.async.wait_group 0;" ::: "memory");
        }
        __syncthreads();

        // Warps 0-3 (rows q0..q0+63) are fully masked for the last tile.
        const bool active = !(t == n_tiles - 1 && wid < 4);

        if (active) {
            const uint32_t kvb = kvstart + 4 * cur * FPLANE;
            const uint32_t sKh = kvb, sKl = kvb + FPLANE;
            const uint32_t sVh = kvb + 2 * FPLANE, sVl = kvb + 3 * FPLANE;

            float accS[8][4];
            #pragma unroll
            for (int ni = 0; ni < 8; ni++)
                #pragma unroll
                for (int e = 0; e < 4; e++) accS[ni][e] = 0.f;

            #pragma unroll
            for (int kk = 0; kk < 8; kk++) {
                uint32_t fQh[4], fQl[4];
                uint32_t aaddr = (wid * 16 + a_r) * FB_STRIDE_B + kk * 32 + a_cb;
                ldsm4(fQh, sQh + aaddr);
                ldsm4(fQl, sQl + aaddr);
                #pragma unroll
                for (int ng = 0; ng < 4; ng++) {
                    uint32_t baddr = (ng * 16 + b_r) * FB_STRIDE_B + kk * 32 + b_cb;
                    uint32_t fKh[4], fKl[4];
                    ldsm4(fKh, sKh + baddr);
                    ldsm4(fKl, sKl + baddr);
                    #pragma unroll
                    for (int hf2 = 0; hf2 < 2; hf2++) {
                        const int ni = ng * 2 + hf2;
                        mma_bf16(accS[ni], fQh, fKh[hf2 * 2], fKh[hf2 * 2 + 1]);
                        mma_bf16(accS[ni], fQh, fKl[hf2 * 2], fKl[hf2 * 2 + 1]);
                        mma_bf16(accS[ni], fQl, fKh[hf2 * 2], fKh[hf2 * 2 + 1]);
                    }
                }
            }

            #pragma unroll
            for (int ni = 0; ni < 8; ni++)
                #pragma unroll
                for (int e = 0; e < 4; e++) accS[ni][e] *= SL;

            if (t >= n_tiles - 2) {   // tiles overlapping the diagonal
                const int r0 = q0 + wid * 16 + (lane >> 2);
                #pragma unroll
                for (int ni = 0; ni < 8; ni++) {
                    int c = kt0 + ni * 8 + (lane & 3) * 2;
                    if (c > r0)     accS[ni][0] = -1e30f;
                    if (c + 1 > r0) accS[ni][1] = -1e30f;
                    if (c > r0 + 8)     accS[ni][2] = -1e30f;
                    if (c + 1 > r0 + 8) accS[ni][3] = -1e30f;
                }
            }

            float mx0 = -1e30f, mx1 = -1e30f;
            #pragma unroll
            for (int ni = 0; ni < 8; ni++) {
                mx0 = fmaxf(mx0, fmaxf(accS[ni][0], accS[ni][1]));
                mx1 = fmaxf(mx1, fmaxf(accS[ni][2], accS[ni][3]));
            }
            mx0 = fmaxf(mx0, __shfl_xor_sync(0xffffffffu, mx0, 1));
            mx0 = fmaxf(mx0, __shfl_xor_sync(0xffffffffu, mx0, 2));
            mx1 = fmaxf(mx1, __shfl_xor_sync(0xffffffffu, mx1, 1));
            mx1 = fmaxf(mx1, __shfl_xor_sync(0xffffffffu, mx1, 2));

            const float mn0 = fmaxf(m0, mx0), mn1 = fmaxf(m1, mx1);
            const float al0 = exp2f(m0 - mn0), al1 = exp2f(m1 - mn1);
            m0 = mn0; m1 = mn1;

            uint32_t phA[8], phB[8], plA[8], plB[8];
            float s0 = 0.f, s1 = 0.f;
            #pragma unroll
            for (int ni = 0; ni < 8; ni++) {
                float p0 = exp2f(accS[ni][0] - mn0);
                float p1 = exp2f(accS[ni][1] - mn0);
                float p2 = exp2f(accS[ni][2] - mn1);
                float p3 = exp2f(accS[ni][3] - mn1);
                s0 += p0 + p1; s1 += p2 + p3;
                phA[ni] = pack_bf2(p0, p1);
                phB[ni] = pack_bf2(p2, p3);
                float q0f = p0 - __bfloat162float(__float2bfloat16(p0));
                float q1f = p1 - __bfloat162float(__float2bfloat16(p1));
                float q2f = p2 - __bfloat162float(__float2bfloat16(p2));
                float q3f = p3 - __bfloat162float(__float2bfloat16(p3));
                plA[ni] = pack_bf2(q0f, q1f);
                plB[ni] = pack_bf2(q2f, q3f);
            }
            s0 += __shfl_xor_sync(0xffffffffu, s0, 1);
            s0 += __shfl_xor_sync(0xffffffffu, s0, 2);
            s1 += __shfl_xor_sync(0xffffffffu, s1, 1);
            s1 += __shfl_xor_sync(0xffffffffu, s1, 2);
            l0 = l0 * al0 + s0;
            l1 = l1 * al1 + s1;

            #pragma unroll
            for (int ti = 0; ti < 16; ti++) {
                accO[ti][0] *= al0; accO[ti][1] *= al0;
                accO[ti][2] *= al1; accO[ti][3] *= al1;
            }

            #pragma unroll
            for (int j = 0; j < 4; j++) {
                uint32_t aPh[4] = { phA[2*j], phB[2*j], phA[2*j+1], phB[2*j+1] };
                uint32_t aPl[4] = { plA[2*j], plB[2*j], plA[2*j+1], plB[2*j+1] };
                #pragma unroll
                for (int dg = 0; dg < 8; dg++) {
                    uint32_t vaddr = (j * 16 + (lane & 15)) * FB_STRIDE_B
                                   + dg * 32 + (lane >> 4) * 16;
                    uint32_t fVh[4], fVl[4];
                    ldsm4t(fVh, sVh + vaddr);
                    ldsm4t(fVl, sVl + vaddr);
                    const int t0i = dg * 2, t1i = dg * 2 + 1;
                    mma_bf16(accO[t0i], aPh, fVh[0], fVh[1]);
                    mma_bf16(accO[t0i], aPh, fVl[0], fVl[1]);
                    mma_bf16(accO[t0i], aPl, fVh[0], fVh[1]);
                    mma_bf16(accO[t1i], aPh, fVh[2], fVh[3]);
                    mma_bf16(accO[t1i], aPh, fVl[2], fVl[3]);
                    mma_bf16(accO[t1i], aPl, fVh[2], fVh[3]);
                }
            }
        }
        __syncthreads();
    }

    const float inv0 = 1.0f / l0, inv1 = 1.0f / l1;
    const size_t row0 = (size_t)(b * S_LEN + q0 + wid * 16 + (lane >> 2));
    const size_t row1 = row0 + 8;
    __nv_bfloat16* oh0 = Oh_g + row0 * DIMN + h * HD;
    __nv_bfloat16* oh1 = Oh_g + row1 * DIMN + h * HD;
    __nv_bfloat16* ol0 = Ol_g + row0 * DIMN + h * HD;
    __nv_bfloat16* ol1 = Ol_g + row1 * DIMN + h * HD;
    #pragma unroll
    for (int ti = 0; ti < 16; ti++) {
        int c = ti * 8 + (lane & 3) * 2;
        float v0 = accO[ti][0] * inv0, v1 = accO[ti][1] * inv0;
        float v2 = accO[ti][2] * inv1, v3 = accO[ti][3] * inv1;
        *(uint32_t*)(oh0 + c) = pack_bf2(v0, v1);
        *(uint32_t*)(oh1 + c) = pack_bf2(v2, v3);
        float r0x = v0 - __bfloat162float(__float2bfloat16(v0));
        float r0y = v1 - __bfloat162float(__float2bfloat16(v1));
        float r1x = v2 - __bfloat162float(__float2bfloat16(v2));
        float r1y = v3 - __bfloat162float(__float2bfloat16(v3));
        *(uint32_t*)(ol0 + c) = pack_bf2(r0x, r0y);
        *(uint32_t*)(ol1 + c) = pack_bf2(r1x, r1y);
    }
}

// ---------------------------------------------------------------------------
// Launch
// ---------------------------------------------------------------------------
extern "C" void kernel_launch(void* const* d_in, const int* in_sizes, int n_in,
                              void* d_out, int out_size)
{
    const float* x  = (const float*)d_in[0];
    const float* wq = (const float*)d_in[1];
    const float* wk = (const float*)d_in[2];
    const float* wv = (const float*)d_in[3];
    const float* wo = (const float*)d_in[4];
    float* out = (float*)d_out;

    __nv_bfloat16 *xh, *xl, *qh, *ql, *kh, *kl, *vh, *vl, *ah, *al;
    __nv_bfloat16 *wqh, *wql, *wkh, *wkl, *wvh, *wvl, *woh, *wol;
    cudaGetSymbolAddress((void**)&xh, g_xh);   cudaGetSymbolAddress((void**)&xl, g_xl);
    cudaGetSymbolAddress((void**)&qh, g_qh);   cudaGetSymbolAddress((void**)&ql, g_ql);
    cudaGetSymbolAddress((void**)&kh, g_kh);   cudaGetSymbolAddress((void**)&kl, g_kl);
    cudaGetSymbolAddress((void**)&vh, g_vh);   cudaGetSymbolAddress((void**)&vl, g_vl);
    cudaGetSymbolAddress((void**)&ah, g_ah);   cudaGetSymbolAddress((void**)&al, g_al);
    cudaGetSymbolAddress((void**)&wqh, g_wqT_h); cudaGetSymbolAddress((void**)&wql, g_wqT_l);
    cudaGetSymbolAddress((void**)&wkh, g_wkT_h); cudaGetSymbolAddress((void**)&wkl, g_wkT_l);
    cudaGetSymbolAddress((void**)&wvh, g_wvT_h); cudaGetSymbolAddress((void**)&wvl, g_wvT_l);
    cudaGetSymbolAddress((void**)&woh, g_woT_h); cudaGetSymbolAddress((void**)&wol, g_woT_l);

    cudaFuncSetAttribute(gemm_bf16_split<0>,
                         cudaFuncAttributeMaxDynamicSharedMemorySize, GEMM_SMEM);
    cudaFuncSetAttribute(gemm_bf16_split<1>,
                         cudaFuncAttributeMaxDynamicSharedMemorySize, GEMM_SMEM);
    cudaFuncSetAttribute(fattn_kernel,
                         cudaFuncAttributeMaxDynamicSharedMemorySize, FATTN_SMEM);

    int n4x = MROWS * DIMN / 4;
    conv_hilo<<<(n4x + 255) / 256, 256>>>(x, xh, xl, n4x);
    convT_hilo<<<dim3(DIMN / 32, DIMN / 32), dim3(32, 8)>>>(wq, wqh, wql, DIMN, DIMN);
    convT_hilo<<<dim3(KVDIM / 32, DIMN / 32), dim3(32, 8)>>>(wk, wkh, wkl, DIMN, KVDIM);
    convT_hilo<<<dim3(KVDIM / 32, DIMN / 32), dim3(32, 8)>>>(wv, wvh, wvl, DIMN, KVDIM);
    convT_hilo<<<dim3(DIMN / 32, DIMN / 32), dim3(32, 8)>>>(wo, woh, wol, DIMN, DIMN);

    gemm_bf16_split<1><<<dim3(DIMN / 128, MROWS / 128), 256, GEMM_SMEM>>>(
        MROWS, DIMN, DIMN, xh, xl, wqh, wql, nullptr, qh, ql);
    gemm_bf16_split<1><<<dim3(KVDIM / 128, MROWS / 128), 256, GEMM_SMEM>>>(
        MROWS, KVDIM, DIMN, xh, xl, wkh, wkl, nullptr, kh, kl);
    gemm_bf16_split<1><<<dim3(KVDIM / 128, MROWS / 128), 256, GEMM_SMEM>>>(
        MROWS, KVDIM, DIMN, xh, xl, wvh, wvl, nullptr, vh, vl);

    fattn_kernel<<<dim3(S_LEN / 128, HQ, BATCH), 256, FATTN_SMEM>>>(
        qh, ql, kh, kl, vh, vl, ah, al);

    gemm_bf16_split<0><<<dim3(DIMN / 128, MROWS / 128), 256, GEMM_SMEM>>>(
        MROWS, DIMN, DIMN, ah, al, woh, wol, out, nullptr, nullptr);
}

// round 7
// speedup vs baseline: 5.0391x; 1.4404x over previous
#include <cuda_runtime.h>
#include <cuda_fp16.h>
#include <cstdint>

// Problem constants
#define DIMN    4096
#define S_LEN   2048
#define BATCH   2
#define HQ      32
#define HKV     8
#define NREP    4
#define HD      128
#define MROWS   (BATCH * S_LEN)   // 4096
#define KVDIM   (HKV * HD)        // 1024

// ---------------------------------------------------------------------------
// Scratch (__device__ globals)
// ---------------------------------------------------------------------------
__device__ __half g_xh[(size_t)MROWS * DIMN];
__device__ __half g_xl[(size_t)MROWS * DIMN];
__device__ __half g_qh[(size_t)MROWS * DIMN];
__device__ __half g_ql[(size_t)MROWS * DIMN];
__device__ __half g_kh[(size_t)MROWS * KVDIM];    // single plane
__device__ __half g_vh[(size_t)MROWS * KVDIM];    // single plane
__device__ __half g_ah[(size_t)MROWS * DIMN];
__device__ __half g_al[(size_t)MROWS * DIMN];
__device__ __half g_wqT[(size_t)DIMN * DIMN];     // single plane (hi only)
__device__ __half g_woT[(size_t)DIMN * DIMN];
__device__ __half g_wkT[(size_t)KVDIM * DIMN];
__device__ __half g_wvT[(size_t)KVDIM * DIMN];

// ---------------------------------------------------------------------------
// PTX helpers
// ---------------------------------------------------------------------------
__device__ __forceinline__ uint32_t smem_u32(const void* p) {
    return (uint32_t)__cvta_generic_to_shared(p);
}
__device__ __forceinline__ void ldsm4(uint32_t* r, uint32_t addr) {
    asm volatile("ldmatrix.sync.aligned.m8n8.x4.shared.b16 {%0,%1,%2,%3}, [%4];"
                 : "=r"(r[0]), "=r"(r[1]), "=r"(r[2]), "=r"(r[3]) : "r"(addr));
}
__device__ __forceinline__ void ldsm4t(uint32_t* r, uint32_t addr) {
    asm volatile("ldmatrix.sync.aligned.m8n8.x4.trans.shared.b16 {%0,%1,%2,%3}, [%4];"
                 : "=r"(r[0]), "=r"(r[1]), "=r"(r[2]), "=r"(r[3]) : "r"(addr));
}
__device__ __forceinline__ void mma_f16(float* d, const uint32_t* a,
                                        const uint32_t b0, const uint32_t b1) {
    asm volatile(
        "mma.sync.aligned.m16n8k16.row.col.f32.f16.f16.f32 "
        "{%0,%1,%2,%3}, {%4,%5,%6,%7}, {%8,%9}, {%0,%1,%2,%3};"
        : "+f"(d[0]), "+f"(d[1]), "+f"(d[2]), "+f"(d[3])
        : "r"(a[0]), "r"(a[1]), "r"(a[2]), "r"(a[3]), "r"(b0), "r"(b1));
}
__device__ __forceinline__ uint32_t pack_h2(float a, float b) {
    __half2 t = __floats2half2_rn(a, b);
    return *(uint32_t*)&t;
}
__device__ __forceinline__ float h_res(float v) {
    return v - __half2float(__float2half_rn(v));
}

// ---------------------------------------------------------------------------
// fp16 2-term tensor-core GEMM: C[M,N] = (Ah+Al)[M,K] @ Bh[N,K]^T
// CTA 128x128, 8 warps of 64x32, K-chunk 32, 3-stage cp.async, 2 CTAs/SM.
// OUTMODE: 0 = fp32 C, 1 = fp16 pair (Ch,Cl), 2 = fp16 single (Ch).
// ---------------------------------------------------------------------------
constexpr int CK    = 32;
constexpr int PADW  = 40;                  // smem row stride in halves (80 B)
constexpr int PLANE = 128 * PADW * 2;      // 10240 B
constexpr int STAGE = 3 * PLANE;           // Ah, Al, Bh
constexpr int GNS   = 3;
constexpr int GEMM_SMEM = GNS * STAGE;     // 92160

__device__ __forceinline__ void prefetch_chunk(
    const __half* Ah, const __half* Al, const __half* Bh,
    int K, int mtile, int ntile, int k0, uint32_t tbase, int tid)
{
    #pragma unroll
    for (int u = tid; u < 1536; u += 256) {
        int plane = u >> 9;          // 0:Ah 1:Al 2:Bh
        int r = (u >> 2) & 127;
        int seg = u & 3;
        const __half* src;
        if (plane == 0)      src = Ah + (size_t)(mtile + r) * K + k0 + seg * 8;
        else if (plane == 1) src = Al + (size_t)(mtile + r) * K + k0 + seg * 8;
        else                 src = Bh + (size_t)(ntile + r) * K + k0 + seg * 8;
        uint32_t dst = tbase + plane * PLANE + r * (PADW * 2) + seg * 16;
        asm volatile("cp.async.cg.shared.global [%0], [%1], 16;"
                     :: "r"(dst), "l"(src) : "memory");
    }
}

template <int OUTMODE>
__global__ __launch_bounds__(256, 2) void gemm_f16_2t(
    int M, int N, int K,
    const __half* __restrict__ Ah, const __half* __restrict__ Al,
    const __half* __restrict__ Bh,
    float* __restrict__ C,
    __half* __restrict__ Ch, __half* __restrict__ Cl)
{
    extern __shared__ char smem[];
    const uint32_t sbase = smem_u32(smem);

    const int tid = threadIdx.x;
    const int wid = tid >> 5, lane = tid & 31;
    const int wm = wid >> 2;
    const int wn = wid & 3;
    const int mtile = blockIdx.y * 128;
    const int ntile = blockIdx.x * 128;
    const int nch = K / CK;

    float acc[4][4][4];
    #pragma unroll
    for (int mi = 0; mi < 4; mi++)
        #pragma unroll
        for (int ni = 0; ni < 4; ni++)
            #pragma unroll
            for (int e = 0; e < 4; e++) acc[mi][ni][e] = 0.f;

    const int a_row_in16 = (lane & 7) + ((lane >> 3) & 1) * 8;
    const int a_colb     = (lane >> 4) * 16;
    const int b_row_in16 = (lane & 7) + ((lane >> 4) & 1) * 8;
    const int b_colb     = ((lane >> 3) & 1) * 16;

    for (int i = 0; i < GNS; i++) {
        prefetch_chunk(Ah, Al, Bh, K, mtile, ntile, i * CK,
                       sbase + i * STAGE, tid);
        asm volatile("cp.async.commit_group;" ::: "memory");
    }

    for (int i = 0; i < nch; i++) {
        const int s = i % GNS;
        const uint32_t tb = sbase + s * STAGE;
        asm volatile("cp.async.wait_group %0;" :: "n"(GNS - 1) : "memory");
        __syncthreads();

        const uint32_t aH = tb;
        const uint32_t aL = tb + PLANE;
        const uint32_t bH = tb + 2 * PLANE;

        #pragma unroll
        for (int ks = 0; ks < 2; ks++) {
            const int kb = ks * 32;
            uint32_t fB[2][4];
            #pragma unroll
            for (int ng = 0; ng < 2; ng++) {
                int row = wn * 32 + ng * 16 + b_row_in16;
                ldsm4(fB[ng], bH + row * (PADW * 2) + b_colb + kb);
            }
            uint32_t fA[4][4];
            // Pass 1: A-high
            #pragma unroll
            for (int mi = 0; mi < 4; mi++) {
                int row = wm * 64 + mi * 16 + a_row_in16;
                ldsm4(fA[mi], aH + row * (PADW * 2) + a_colb + kb);
            }
            #pragma unroll
            for (int mi = 0; mi < 4; mi++)
                #pragma unroll
                for (int ni = 0; ni < 4; ni++) {
                    const int ng = ni >> 1, hf = (ni & 1) * 2;
                    mma_f16(acc[mi][ni], fA[mi], fB[ng][hf], fB[ng][hf + 1]);
                }
            // Pass 2: A-low (reuse fA)
            #pragma unroll
            for (int mi = 0; mi < 4; mi++) {
                int row = wm * 64 + mi * 16 + a_row_in16;
                ldsm4(fA[mi], aL + row * (PADW * 2) + a_colb + kb);
            }
            #pragma unroll
            for (int mi = 0; mi < 4; mi++)
                #pragma unroll
                for (int ni = 0; ni < 4; ni++) {
                    const int ng = ni >> 1, hf = (ni & 1) * 2;
                    mma_f16(acc[mi][ni], fA[mi], fB[ng][hf], fB[ng][hf + 1]);
                }
        }
        __syncthreads();

        if (i + GNS < nch)
            prefetch_chunk(Ah, Al, Bh, K, mtile, ntile, (i + GNS) * CK,
                           sbase + s * STAGE, tid);
        asm volatile("cp.async.commit_group;" ::: "memory");
    }

    const int r0b = mtile + wm * 64 + (lane >> 2);
    const int c0b = ntile + wn * 32 + (lane & 3) * 2;
    #pragma unroll
    for (int mi = 0; mi < 4; mi++) {
        #pragma unroll
        for (int ni = 0; ni < 4; ni++) {
            size_t o0 = (size_t)(r0b + mi * 16) * N + c0b + ni * 8;
            size_t o1 = (size_t)(r0b + mi * 16 + 8) * N + c0b + ni * 8;
            float v0 = acc[mi][ni][0], v1 = acc[mi][ni][1];
            float v2 = acc[mi][ni][2], v3 = acc[mi][ni][3];
            if (OUTMODE == 0) {
                *(float2*)(C + o0) = make_float2(v0, v1);
                *(float2*)(C + o1) = make_float2(v2, v3);
            } else if (OUTMODE == 2) {
                *(uint32_t*)(Ch + o0) = pack_h2(v0, v1);
                *(uint32_t*)(Ch + o1) = pack_h2(v2, v3);
            } else {
                *(uint32_t*)(Ch + o0) = pack_h2(v0, v1);
                *(uint32_t*)(Ch + o1) = pack_h2(v2, v3);
                *(uint32_t*)(Cl + o0) = pack_h2(h_res(v0), h_res(v1));
                *(uint32_t*)(Cl + o1) = pack_h2(h_res(v2), h_res(v3));
            }
        }
    }
}

// ---------------------------------------------------------------------------
// Conversions
// ---------------------------------------------------------------------------
__global__ void conv_pair(const float* __restrict__ in,
                          __half* __restrict__ hi, __half* __restrict__ lo, int n4)
{
    int i = blockIdx.x * blockDim.x + threadIdx.x;
    if (i >= n4) return;
    float4 v = ((const float4*)in)[i];
    ((uint32_t*)hi)[2 * i]     = pack_h2(v.x, v.y);
    ((uint32_t*)hi)[2 * i + 1] = pack_h2(v.z, v.w);
    ((uint32_t*)lo)[2 * i]     = pack_h2(h_res(v.x), h_res(v.y));
    ((uint32_t*)lo)[2 * i + 1] = pack_h2(h_res(v.z), h_res(v.w));
}

// W[K,N] fp32 -> WT[N,K] fp16 (hi only)
__global__ void convT_single(const float* __restrict__ W,
                             __half* __restrict__ Th, int K, int N)
{
    __shared__ float t[32][33];
    int n0 = blockIdx.x * 32, k0 = blockIdx.y * 32;
    int tx = threadIdx.x, ty0 = threadIdx.y;
    #pragma unroll
    for (int j = 0; j < 4; j++) {
        int ty = ty0 + 8 * j;
        t[ty][tx] = W[(size_t)(k0 + ty) * N + n0 + tx];
    }
    __syncthreads();
    #pragma unroll
    for (int j = 0; j < 4; j++) {
        int ty = ty0 + 8 * j;
        Th[(size_t)(n0 + ty) * K + k0 + tx] = __float2half_rn(t[tx][ty]);
    }
}

// ---------------------------------------------------------------------------
// fp16 2-term tensor-core flash attention, causal GQA.
// CTA: 128 q rows, 8 warps. K tiles of 64, double-buffered.
// smem: Q pair (128 rows) + 2 stages x {Kh, Vh} (64 rows).
// ---------------------------------------------------------------------------
constexpr int FB_STRIDE_B = 272;
constexpr int FPLANE  = 64 * FB_STRIDE_B;      // 17408
constexpr int QPLANE  = 128 * FB_STRIDE_B;     // 34816
constexpr int FATTN_SMEM = 2 * QPLANE + 4 * FPLANE;  // 139264

__global__ __launch_bounds__(256) void fattn_kernel(
    const __half* __restrict__ Qh_g, const __half* __restrict__ Ql_g,
    const __half* __restrict__ Kh_g, const __half* __restrict__ Vh_g,
    __half* __restrict__ Oh_g, __half* __restrict__ Ol_g)
{
    extern __shared__ char smem[];
    const uint32_t sb = smem_u32(smem);
    const uint32_t sQh = sb, sQl = sb + QPLANE;
    const uint32_t kvstart = sb + 2 * QPLANE;

    const int tid = threadIdx.x, wid = tid >> 5, lane = tid & 31;
    const int bx = blockIdx.x, h = blockIdx.y, b = blockIdx.z;
    const int q0 = bx * 128;
    const int kvh = h >> 2;

    const __half* qh = Qh_g + ((size_t)(b * S_LEN + q0)) * DIMN + h * HD;
    const __half* ql = Ql_g + ((size_t)(b * S_LEN + q0)) * DIMN + h * HD;
    const __half* kh = Kh_g + ((size_t)(b * S_LEN)) * KVDIM + kvh * HD;
    const __half* vh = Vh_g + ((size_t)(b * S_LEN)) * KVDIM + kvh * HD;

    auto load_kv = [&](int kt0, int s) {
        const uint32_t base = kvstart + 2 * s * FPLANE;
        #pragma unroll
        for (int u = tid; u < 2048; u += 256) {
            int plane = u >> 10, r = (u >> 4) & 63, seg = u & 15;
            const __half* src = (plane ? vh : kh) + (size_t)(kt0 + r) * KVDIM + seg * 8;
            uint32_t dst = base + plane * FPLANE + r * FB_STRIDE_B + seg * 16;
            asm volatile("cp.async.cg.shared.global [%0], [%1], 16;"
                         :: "r"(dst), "l"(src) : "memory");
        }
    };

    // Prologue: Q (2 planes x 128 rows) + KV(0)
    #pragma unroll
    for (int u = tid; u < 4096; u += 256) {
        int plane = u >> 11, r = (u >> 4) & 127, seg = u & 15;
        const __half* src = (plane ? ql : qh) + (size_t)r * DIMN + seg * 8;
        uint32_t dst = (plane ? sQl : sQh) + r * FB_STRIDE_B + seg * 16;
        asm volatile("cp.async.cg.shared.global [%0], [%1], 16;"
                     :: "r"(dst), "l"(src) : "memory");
    }
    load_kv(0, 0);
    asm volatile("cp.async.commit_group;" ::: "memory");

    float accO[16][4];
    #pragma unroll
    for (int t = 0; t < 16; t++)
        #pragma unroll
        for (int e = 0; e < 4; e++) accO[t][e] = 0.f;
    float m0 = -1e30f, m1 = -1e30f, l0 = 0.f, l1 = 0.f;

    const int a_r  = (lane & 7) + ((lane >> 3) & 1) * 8;
    const int a_cb = (lane >> 4) * 16;
    const int b_r  = (lane & 7) + ((lane >> 4) & 1) * 8;
    const int b_cb = ((lane >> 3) & 1) * 16;

    const float SL = 0.08838834764831845f * 1.4426950408889634f;

    const int n_tiles = 2 * bx + 2;
    for (int t = 0; t < n_tiles; t++) {
        const int kt0 = t * 64;
        const int cur = t & 1;
        if (t < n_tiles - 1) {
            load_kv((t + 1) * 64, cur ^ 1);
            asm volatile("cp.async.commit_group;" ::: "memory");
            asm volatile("cp.async.wait_group 1;" ::: "memory");
        } else {
            asm volatile("cp.async.wait_group 0;" ::: "memory");
        }
        __syncthreads();

        const bool active = !(t == n_tiles - 1 && wid < 4);

        if (active) {
            const uint32_t kvb = kvstart + 2 * cur * FPLANE;
            const uint32_t sKh = kvb, sVh = kvb + FPLANE;

            float accS[8][4];
            #pragma unroll
            for (int ni = 0; ni < 8; ni++)
                #pragma unroll
                for (int e = 0; e < 4; e++) accS[ni][e] = 0.f;

            #pragma unroll
            for (int kk = 0; kk < 8; kk++) {
                uint32_t fQh[4], fQl[4];
                uint32_t aaddr = (wid * 16 + a_r) * FB_STRIDE_B + kk * 32 + a_cb;
                ldsm4(fQh, sQh + aaddr);
                ldsm4(fQl, sQl + aaddr);
                #pragma unroll
                for (int ng = 0; ng < 4; ng++) {
                    uint32_t baddr = (ng * 16 + b_r) * FB_STRIDE_B + kk * 32 + b_cb;
                    uint32_t fKh[4];
                    ldsm4(fKh, sKh + baddr);
                    #pragma unroll
                    for (int hf2 = 0; hf2 < 2; hf2++) {
                        const int ni = ng * 2 + hf2;
                        mma_f16(accS[ni], fQh, fKh[hf2 * 2], fKh[hf2 * 2 + 1]);
                        mma_f16(accS[ni], fQl, fKh[hf2 * 2], fKh[hf2 * 2 + 1]);
                    }
                }
            }

            #pragma unroll
            for (int ni = 0; ni < 8; ni++)
                #pragma unroll
                for (int e = 0; e < 4; e++) accS[ni][e] *= SL;

            if (t >= n_tiles - 2) {
                const int r0 = q0 + wid * 16 + (lane >> 2);
                #pragma unroll
                for (int ni = 0; ni < 8; ni++) {
                    int c = kt0 + ni * 8 + (lane & 3) * 2;
                    if (c > r0)     accS[ni][0] = -1e30f;
                    if (c + 1 > r0) accS[ni][1] = -1e30f;
                    if (c > r0 + 8)     accS[ni][2] = -1e30f;
                    if (c + 1 > r0 + 8) accS[ni][3] = -1e30f;
                }
            }

            float mx0 = -1e30f, mx1 = -1e30f;
            #pragma unroll
            for (int ni = 0; ni < 8; ni++) {
                mx0 = fmaxf(mx0, fmaxf(accS[ni][0], accS[ni][1]));
                mx1 = fmaxf(mx1, fmaxf(accS[ni][2], accS[ni][3]));
            }
            mx0 = fmaxf(mx0, __shfl_xor_sync(0xffffffffu, mx0, 1));
            mx0 = fmaxf(mx0, __shfl_xor_sync(0xffffffffu, mx0, 2));
            mx1 = fmaxf(mx1, __shfl_xor_sync(0xffffffffu, mx1, 1));
            mx1 = fmaxf(mx1, __shfl_xor_sync(0xffffffffu, mx1, 2));

            const float mn0 = fmaxf(m0, mx0), mn1 = fmaxf(m1, mx1);
            const float al0 = exp2f(m0 - mn0), al1 = exp2f(m1 - mn1);
            m0 = mn0; m1 = mn1;

            uint32_t phA[8], phB[8], plA[8], plB[8];
            float s0 = 0.f, s1 = 0.f;
            #pragma unroll
            for (int ni = 0; ni < 8; ni++) {
                float p0 = exp2f(accS[ni][0] - mn0);
                float p1 = exp2f(accS[ni][1] - mn0);
                float p2 = exp2f(accS[ni][2] - mn1);
                float p3 = exp2f(accS[ni][3] - mn1);
                s0 += p0 + p1; s1 += p2 + p3;
                phA[ni] = pack_h2(p0, p1);
                phB[ni] = pack_h2(p2, p3);
                plA[ni] = pack_h2(h_res(p0), h_res(p1));
                plB[ni] = pack_h2(h_res(p2), h_res(p3));
            }
            s0 += __shfl_xor_sync(0xffffffffu, s0, 1);
            s0 += __shfl_xor_sync(0xffffffffu, s0, 2);
            s1 += __shfl_xor_sync(0xffffffffu, s1, 1);
            s1 += __shfl_xor_sync(0xffffffffu, s1, 2);
            l0 = l0 * al0 + s0;
            l1 = l1 * al1 + s1;

            #pragma unroll
            for (int ti = 0; ti < 16; ti++) {
                accO[ti][0] *= al0; accO[ti][1] *= al0;
                accO[ti][2] *= al1; accO[ti][3] *= al1;
            }

            #pragma unroll
            for (int j = 0; j < 4; j++) {
                uint32_t aPh[4] = { phA[2*j], phB[2*j], phA[2*j+1], phB[2*j+1] };
                uint32_t aPl[4] = { plA[2*j], plB[2*j], plA[2*j+1], plB[2*j+1] };
                #pragma unroll
                for (int dg = 0; dg < 8; dg++) {
                    uint32_t vaddr = (j * 16 + (lane & 15)) * FB_STRIDE_B
                                   + dg * 32 + (lane >> 4) * 16;
                    uint32_t fVh[4];
                    ldsm4t(fVh, sVh + vaddr);
                    const int t0i = dg * 2, t1i = dg * 2 + 1;
                    mma_f16(accO[t0i], aPh, fVh[0], fVh[1]);
                    mma_f16(accO[t0i], aPl, fVh[0], fVh[1]);
                    mma_f16(accO[t1i], aPh, fVh[2], fVh[3]);
                    mma_f16(accO[t1i], aPl, fVh[2], fVh[3]);
                }
            }
        }
        __syncthreads();
    }

    const float inv0 = 1.0f / l0, inv1 = 1.0f / l1;
    const size_t row0 = (size_t)(b * S_LEN + q0 + wid * 16 + (lane >> 2));
    const size_t row1 = row0 + 8;
    __half* oh0 = Oh_g + row0 * DIMN + h * HD;
    __half* oh1 = Oh_g + row1 * DIMN + h * HD;
    __half* ol0 = Ol_g + row0 * DIMN + h * HD;
    __half* ol1 = Ol_g + row1 * DIMN + h * HD;
    #pragma unroll
    for (int ti = 0; ti < 16; ti++) {
        int c = ti * 8 + (lane & 3) * 2;
        float v0 = accO[ti][0] * inv0, v1 = accO[ti][1] * inv0;
        float v2 = accO[ti][2] * inv1, v3 = accO[ti][3] * inv1;
        *(uint32_t*)(oh0 + c) = pack_h2(v0, v1);
        *(uint32_t*)(oh1 + c) = pack_h2(v2, v3);
        *(uint32_t*)(ol0 + c) = pack_h2(h_res(v0), h_res(v1));
        *(uint32_t*)(ol1 + c) = pack_h2(h_res(v2), h_res(v3));
    }
}

// ---------------------------------------------------------------------------
// Launch
// ---------------------------------------------------------------------------
extern "C" void kernel_launch(void* const* d_in, const int* in_sizes, int n_in,
                              void* d_out, int out_size)
{
    const float* x  = (const float*)d_in[0];
    const float* wq = (const float*)d_in[1];
    const float* wk = (const float*)d_in[2];
    const float* wv = (const float*)d_in[3];
    const float* wo = (const float*)d_in[4];
    float* out = (float*)d_out;

    __half *xh, *xl, *qh, *ql, *kh, *vh, *ah, *al;
    __half *wqT, *wkT, *wvT, *woT;
    cudaGetSymbolAddress((void**)&xh, g_xh);   cudaGetSymbolAddress((void**)&xl, g_xl);
    cudaGetSymbolAddress((void**)&qh, g_qh);   cudaGetSymbolAddress((void**)&ql, g_ql);
    cudaGetSymbolAddress((void**)&kh, g_kh);   cudaGetSymbolAddress((void**)&vh, g_vh);
    cudaGetSymbolAddress((void**)&ah, g_ah);   cudaGetSymbolAddress((void**)&al, g_al);
    cudaGetSymbolAddress((void**)&wqT, g_wqT); cudaGetSymbolAddress((void**)&wkT, g_wkT);
    cudaGetSymbolAddress((void**)&wvT, g_wvT); cudaGetSymbolAddress((void**)&woT, g_woT);

    cudaFuncSetAttribute(gemm_f16_2t<0>,
                         cudaFuncAttributeMaxDynamicSharedMemorySize, GEMM_SMEM);
    cudaFuncSetAttribute(gemm_f16_2t<1>,
                         cudaFuncAttributeMaxDynamicSharedMemorySize, GEMM_SMEM);
    cudaFuncSetAttribute(gemm_f16_2t<2>,
                         cudaFuncAttributeMaxDynamicSharedMemorySize, GEMM_SMEM);
    cudaFuncSetAttribute(fattn_kernel,
                         cudaFuncAttributeMaxDynamicSharedMemorySize, FATTN_SMEM);

    int n4x = MROWS * DIMN / 4;
    conv_pair<<<(n4x + 255) / 256, 256>>>(x, xh, xl, n4x);
    convT_single<<<dim3(DIMN / 32, DIMN / 32), dim3(32, 8)>>>(wq, wqT, DIMN, DIMN);
    convT_single<<<dim3(KVDIM / 32, DIMN / 32), dim3(32, 8)>>>(wk, wkT, DIMN, KVDIM);
    convT_single<<<dim3(KVDIM / 32, DIMN / 32), dim3(32, 8)>>>(wv, wvT, DIMN, KVDIM);
    convT_single<<<dim3(DIMN / 32, DIMN / 32), dim3(32, 8)>>>(wo, woT, DIMN, DIMN);

    // Projections: Q -> fp16 pair, K/V -> fp16 single
    gemm_f16_2t<1><<<dim3(DIMN / 128, MROWS / 128), 256, GEMM_SMEM>>>(
        MROWS, DIMN, DIMN, xh, xl, wqT, nullptr, qh, ql);
    gemm_f16_2t<2><<<dim3(KVDIM / 128, MROWS / 128), 256, GEMM_SMEM>>>(
        MROWS, KVDIM, DIMN, xh, xl, wkT, nullptr, kh, nullptr);
    gemm_f16_2t<2><<<dim3(KVDIM / 128, MROWS / 128), 256, GEMM_SMEM>>>(
        MROWS, KVDIM, DIMN, xh, xl, wvT, nullptr, vh, nullptr);

    // Attention -> fp16 pair
    fattn_kernel<<<dim3(S_LEN / 128, HQ, BATCH), 256, FATTN_SMEM>>>(
        qh, ql, kh, vh, ah, al);

    // Output projection -> fp32
    gemm_f16_2t<0><<<dim3(DIMN / 128, MROWS / 128), 256, GEMM_SMEM>>>(
        MROWS, DIMN, DIMN, ah, al, woT, out, nullptr, nullptr);
}

// round 8
// speedup vs baseline: 6.4537x; 1.2807x over previous
#include <cuda_runtime.h>
#include <cuda_fp16.h>
#include <cstdint>

// Problem constants
#define DIMN    4096
#define S_LEN   2048
#define BATCH   2
#define HQ      32
#define HKV     8
#define NREP    4
#define HD      128
#define MROWS   (BATCH * S_LEN)   // 4096
#define KVDIM   (HKV * HD)        // 1024

// ---------------------------------------------------------------------------
// Scratch (__device__ globals)
// ---------------------------------------------------------------------------
__device__ __half g_xh[(size_t)MROWS * DIMN];
__device__ __half g_xl[(size_t)MROWS * DIMN];
__device__ __half g_qh[(size_t)MROWS * DIMN];
__device__ __half g_ql[(size_t)MROWS * DIMN];
__device__ __half g_kh[(size_t)MROWS * KVDIM];
__device__ __half g_vh[(size_t)MROWS * KVDIM];
__device__ __half g_ah[(size_t)MROWS * DIMN];
__device__ __half g_wqT[(size_t)DIMN * DIMN];
__device__ __half g_woT[(size_t)DIMN * DIMN];
__device__ __half g_wkT[(size_t)KVDIM * DIMN];
__device__ __half g_wvT[(size_t)KVDIM * DIMN];

// ---------------------------------------------------------------------------
// PTX helpers
// ---------------------------------------------------------------------------
__device__ __forceinline__ uint32_t smem_u32(const void* p) {
    return (uint32_t)__cvta_generic_to_shared(p);
}
__device__ __forceinline__ void ldsm4(uint32_t* r, uint32_t addr) {
    asm volatile("ldmatrix.sync.aligned.m8n8.x4.shared.b16 {%0,%1,%2,%3}, [%4];"
                 : "=r"(r[0]), "=r"(r[1]), "=r"(r[2]), "=r"(r[3]) : "r"(addr));
}
__device__ __forceinline__ void ldsm4t(uint32_t* r, uint32_t addr) {
    asm volatile("ldmatrix.sync.aligned.m8n8.x4.trans.shared.b16 {%0,%1,%2,%3}, [%4];"
                 : "=r"(r[0]), "=r"(r[1]), "=r"(r[2]), "=r"(r[3]) : "r"(addr));
}
__device__ __forceinline__ void mma_f16(float* d, const uint32_t* a,
                                        const uint32_t b0, const uint32_t b1) {
    asm volatile(
        "mma.sync.aligned.m16n8k16.row.col.f32.f16.f16.f32 "
        "{%0,%1,%2,%3}, {%4,%5,%6,%7}, {%8,%9}, {%0,%1,%2,%3};"
        : "+f"(d[0]), "+f"(d[1]), "+f"(d[2]), "+f"(d[3])
        : "r"(a[0]), "r"(a[1]), "r"(a[2]), "r"(a[3]), "r"(b0), "r"(b1));
}
__device__ __forceinline__ uint32_t pack_h2(float a, float b) {
    __half2 t = __floats2half2_rn(a, b);
    return *(uint32_t*)&t;
}
__device__ __forceinline__ float h_res(float v) {
    return v - __half2float(__float2half_rn(v));
}

// ---------------------------------------------------------------------------
// fp16 tensor-core GEMM: C[M,N] = (Ah [+ Al])[M,K] @ Bh[N,K]^T
// NTERMS = 1 or 2 A-planes. CTA 128x128, 8 warps, K-chunk 32, 3-stage.
// OUTMODE: 0 = fp32 C, 1 = fp16 pair (Ch,Cl), 2 = fp16 single (Ch).
// ---------------------------------------------------------------------------
constexpr int CK    = 32;
constexpr int PADW  = 40;
constexpr int PLANE = 128 * PADW * 2;      // 10240 B
constexpr int GNS   = 3;

template <int NTERMS>
__device__ __forceinline__ void prefetch_chunk(
    const __half* Ah, const __half* Al, const __half* Bh,
    int K, int mtile, int ntile, int k0, uint32_t tbase, int tid)
{
    #pragma unroll
    for (int u = tid; u < (NTERMS + 1) * 512; u += 256) {
        int plane = u >> 9;
        int r = (u >> 2) & 127;
        int seg = u & 3;
        const __half* src;
        if (plane == 0)                      src = Ah + (size_t)(mtile + r) * K + k0 + seg * 8;
        else if (NTERMS == 2 && plane == 1)  src = Al + (size_t)(mtile + r) * K + k0 + seg * 8;
        else                                 src = Bh + (size_t)(ntile + r) * K + k0 + seg * 8;
        uint32_t dst = tbase + plane * PLANE + r * (PADW * 2) + seg * 16;
        asm volatile("cp.async.cg.shared.global [%0], [%1], 16;"
                     :: "r"(dst), "l"(src) : "memory");
    }
}

template <int OUTMODE, int NTERMS>
__global__ __launch_bounds__(256, 2) void gemm_f16(
    int M, int N, int K,
    const __half* __restrict__ Ah, const __half* __restrict__ Al,
    const __half* __restrict__ Bh,
    float* __restrict__ C,
    __half* __restrict__ Ch, __half* __restrict__ Cl)
{
    constexpr int STG = (NTERMS + 1) * PLANE;
    extern __shared__ char smem[];
    const uint32_t sbase = smem_u32(smem);

    const int tid = threadIdx.x;
    const int wid = tid >> 5, lane = tid & 31;
    const int wm = wid >> 2;
    const int wn = wid & 3;
    const int mtile = blockIdx.y * 128;
    const int ntile = blockIdx.x * 128;
    const int nch = K / CK;

    float acc[4][4][4];
    #pragma unroll
    for (int mi = 0; mi < 4; mi++)
        #pragma unroll
        for (int ni = 0; ni < 4; ni++)
            #pragma unroll
            for (int e = 0; e < 4; e++) acc[mi][ni][e] = 0.f;

    const int a_row_in16 = (lane & 7) + ((lane >> 3) & 1) * 8;
    const int a_colb     = (lane >> 4) * 16;
    const int b_row_in16 = (lane & 7) + ((lane >> 4) & 1) * 8;
    const int b_colb     = ((lane >> 3) & 1) * 16;

    for (int i = 0; i < GNS; i++) {
        prefetch_chunk<NTERMS>(Ah, Al, Bh, K, mtile, ntile, i * CK,
                               sbase + i * STG, tid);
        asm volatile("cp.async.commit_group;" ::: "memory");
    }

    for (int i = 0; i < nch; i++) {
        const int s = i % GNS;
        const uint32_t tb = sbase + s * STG;
        asm volatile("cp.async.wait_group %0;" :: "n"(GNS - 1) : "memory");
        __syncthreads();

        const uint32_t aH = tb;
        const uint32_t aL = tb + PLANE;
        const uint32_t bH = tb + NTERMS * PLANE;

        #pragma unroll
        for (int ks = 0; ks < 2; ks++) {
            const int kb = ks * 32;
            uint32_t fB[2][4];
            #pragma unroll
            for (int ng = 0; ng < 2; ng++) {
                int row = wn * 32 + ng * 16 + b_row_in16;
                ldsm4(fB[ng], bH + row * (PADW * 2) + b_colb + kb);
            }
            uint32_t fA[4][4];
            #pragma unroll
            for (int mi = 0; mi < 4; mi++) {
                int row = wm * 64 + mi * 16 + a_row_in16;
                ldsm4(fA[mi], aH + row * (PADW * 2) + a_colb + kb);
            }
            #pragma unroll
            for (int mi = 0; mi < 4; mi++)
                #pragma unroll
                for (int ni = 0; ni < 4; ni++) {
                    const int ng = ni >> 1, hf = (ni & 1) * 2;
                    mma_f16(acc[mi][ni], fA[mi], fB[ng][hf], fB[ng][hf + 1]);
                }
            if (NTERMS == 2) {
                #pragma unroll
                for (int mi = 0; mi < 4; mi++) {
                    int row = wm * 64 + mi * 16 + a_row_in16;
                    ldsm4(fA[mi], aL + row * (PADW * 2) + a_colb + kb);
                }
                #pragma unroll
                for (int mi = 0; mi < 4; mi++)
                    #pragma unroll
                    for (int ni = 0; ni < 4; ni++) {
                        const int ng = ni >> 1, hf = (ni & 1) * 2;
                        mma_f16(acc[mi][ni], fA[mi], fB[ng][hf], fB[ng][hf + 1]);
                    }
            }
        }
        __syncthreads();

        if (i + GNS < nch)
            prefetch_chunk<NTERMS>(Ah, Al, Bh, K, mtile, ntile, (i + GNS) * CK,
                                   sbase + s * STG, tid);
        asm volatile("cp.async.commit_group;" ::: "memory");
    }

    const int r0b = mtile + wm * 64 + (lane >> 2);
    const int c0b = ntile + wn * 32 + (lane & 3) * 2;
    #pragma unroll
    for (int mi = 0; mi < 4; mi++) {
        #pragma unroll
        for (int ni = 0; ni < 4; ni++) {
            size_t o0 = (size_t)(r0b + mi * 16) * N + c0b + ni * 8;
            size_t o1 = (size_t)(r0b + mi * 16 + 8) * N + c0b + ni * 8;
            float v0 = acc[mi][ni][0], v1 = acc[mi][ni][1];
            float v2 = acc[mi][ni][2], v3 = acc[mi][ni][3];
            if (OUTMODE == 0) {
                *(float2*)(C + o0) = make_float2(v0, v1);
                *(float2*)(C + o1) = make_float2(v2, v3);
            } else if (OUTMODE == 2) {
                *(uint32_t*)(Ch + o0) = pack_h2(v0, v1);
                *(uint32_t*)(Ch + o1) = pack_h2(v2, v3);
            } else {
                *(uint32_t*)(Ch + o0) = pack_h2(v0, v1);
                *(uint32_t*)(Ch + o1) = pack_h2(v2, v3);
                *(uint32_t*)(Cl + o0) = pack_h2(h_res(v0), h_res(v1));
                *(uint32_t*)(Cl + o1) = pack_h2(h_res(v2), h_res(v3));
            }
        }
    }
}

// ---------------------------------------------------------------------------
// Conversions
// ---------------------------------------------------------------------------
__global__ void conv_pair(const float* __restrict__ in,
                          __half* __restrict__ hi, __half* __restrict__ lo, int n4)
{
    int i = blockIdx.x * blockDim.x + threadIdx.x;
    if (i >= n4) return;
    float4 v = ((const float4*)in)[i];
    ((uint32_t*)hi)[2 * i]     = pack_h2(v.x, v.y);
    ((uint32_t*)hi)[2 * i + 1] = pack_h2(v.z, v.w);
    ((uint32_t*)lo)[2 * i]     = pack_h2(h_res(v.x), h_res(v.y));
    ((uint32_t*)lo)[2 * i + 1] = pack_h2(h_res(v.z), h_res(v.w));
}

__global__ void convT_single(const float* __restrict__ W,
                             __half* __restrict__ Th, int K, int N)
{
    __shared__ float t[32][33];
    int n0 = blockIdx.x * 32, k0 = blockIdx.y * 32;
    int tx = threadIdx.x, ty0 = threadIdx.y;
    #pragma unroll
    for (int j = 0; j < 4; j++) {
        int ty = ty0 + 8 * j;
        t[ty][tx] = W[(size_t)(k0 + ty) * N + n0 + tx];
    }
    __syncthreads();
    #pragma unroll
    for (int j = 0; j < 4; j++) {
        int ty = ty0 + 8 * j;
        Th[(size_t)(n0 + ty) * K + k0 + tx] = __float2half_rn(t[tx][ty]);
    }
}

// ---------------------------------------------------------------------------
// fp16 2-term tensor-core flash attention, causal GQA.
// CTA: 128 q rows, 8 warps. K tiles of 64, double-buffered.
// Output: single fp16 plane (wo GEMM is 1-term).
// ---------------------------------------------------------------------------
constexpr int FB_STRIDE_B = 272;
constexpr int FPLANE  = 64 * FB_STRIDE_B;      // 17408
constexpr int QPLANE  = 128 * FB_STRIDE_B;     // 34816
constexpr int FATTN_SMEM = 2 * QPLANE + 4 * FPLANE;  // 139264

__global__ __launch_bounds__(256) void fattn_kernel(
    const __half* __restrict__ Qh_g, const __half* __restrict__ Ql_g,
    const __half* __restrict__ Kh_g, const __half* __restrict__ Vh_g,
    __half* __restrict__ Oh_g)
{
    extern __shared__ char smem[];
    const uint32_t sb = smem_u32(smem);
    const uint32_t sQh = sb, sQl = sb + QPLANE;
    const uint32_t kvstart = sb + 2 * QPLANE;

    const int tid = threadIdx.x, wid = tid >> 5, lane = tid & 31;
    const int bx = blockIdx.x, h = blockIdx.y, b = blockIdx.z;
    const int q0 = bx * 128;
    const int kvh = h >> 2;

    const __half* qh = Qh_g + ((size_t)(b * S_LEN + q0)) * DIMN + h * HD;
    const __half* ql = Ql_g + ((size_t)(b * S_LEN + q0)) * DIMN + h * HD;
    const __half* kh = Kh_g + ((size_t)(b * S_LEN)) * KVDIM + kvh * HD;
    const __half* vh = Vh_g + ((size_t)(b * S_LEN)) * KVDIM + kvh * HD;

    auto load_kv = [&](int kt0, int s) {
        const uint32_t base = kvstart + 2 * s * FPLANE;
        #pragma unroll
        for (int u = tid; u < 2048; u += 256) {
            int plane = u >> 10, r = (u >> 4) & 63, seg = u & 15;
            const __half* src = (plane ? vh : kh) + (size_t)(kt0 + r) * KVDIM + seg * 8;
            uint32_t dst = base + plane * FPLANE + r * FB_STRIDE_B + seg * 16;
            asm volatile("cp.async.cg.shared.global [%0], [%1], 16;"
                         :: "r"(dst), "l"(src) : "memory");
        }
    };

    #pragma unroll
    for (int u = tid; u < 4096; u += 256) {
        int plane = u >> 11, r = (u >> 4) & 127, seg = u & 15;
        const __half* src = (plane ? ql : qh) + (size_t)r * DIMN + seg * 8;
        uint32_t dst = (plane ? sQl : sQh) + r * FB_STRIDE_B + seg * 16;
        asm volatile("cp.async.cg.shared.global [%0], [%1], 16;"
                     :: "r"(dst), "l"(src) : "memory");
    }
    load_kv(0, 0);
    asm volatile("cp.async.commit_group;" ::: "memory");

    float accO[16][4];
    #pragma unroll
    for (int t = 0; t < 16; t++)
        #pragma unroll
        for (int e = 0; e < 4; e++) accO[t][e] = 0.f;
    float m0 = -1e30f, m1 = -1e30f, l0 = 0.f, l1 = 0.f;

    const int a_r  = (lane & 7) + ((lane >> 3) & 1) * 8;
    const int a_cb = (lane >> 4) * 16;
    const int b_r  = (lane & 7) + ((lane >> 4) & 1) * 8;
    const int b_cb = ((lane >> 3) & 1) * 16;

    const float SL = 0.08838834764831845f * 1.4426950408889634f;

    const int n_tiles = 2 * bx + 2;
    for (int t = 0; t < n_tiles; t++) {
        const int kt0 = t * 64;
        const int cur = t & 1;
        if (t < n_tiles - 1) {
            load_kv((t + 1) * 64, cur ^ 1);
            asm volatile("cp.async.commit_group;" ::: "memory");
            asm volatile("cp.async.wait_group 1;" ::: "memory");
        } else {
            asm volatile("cp.async.wait_group 0;" ::: "memory");
        }
        __syncthreads();

        const bool active = !(t == n_tiles - 1 && wid < 4);

        if (active) {
            const uint32_t kvb = kvstart + 2 * cur * FPLANE;
            const uint32_t sKh = kvb, sVh = kvb + FPLANE;

            float accS[8][4];
            #pragma unroll
            for (int ni = 0; ni < 8; ni++)
                #pragma unroll
                for (int e = 0; e < 4; e++) accS[ni][e] = 0.f;

            #pragma unroll
            for (int kk = 0; kk < 8; kk++) {
                uint32_t fQh[4], fQl[4];
                uint32_t aaddr = (wid * 16 + a_r) * FB_STRIDE_B + kk * 32 + a_cb;
                ldsm4(fQh, sQh + aaddr);
                ldsm4(fQl, sQl + aaddr);
                #pragma unroll
                for (int ng = 0; ng < 4; ng++) {
                    uint32_t baddr = (ng * 16 + b_r) * FB_STRIDE_B + kk * 32 + b_cb;
                    uint32_t fKh[4];
                    ldsm4(fKh, sKh + baddr);
                    #pragma unroll
                    for (int hf2 = 0; hf2 < 2; hf2++) {
                        const int ni = ng * 2 + hf2;
                        mma_f16(accS[ni], fQh, fKh[hf2 * 2], fKh[hf2 * 2 + 1]);
                        mma_f16(accS[ni], fQl, fKh[hf2 * 2], fKh[hf2 * 2 + 1]);
                    }
                }
            }

            #pragma unroll
            for (int ni = 0; ni < 8; ni++)
                #pragma unroll
                for (int e = 0; e < 4; e++) accS[ni][e] *= SL;

            if (t >= n_tiles - 2) {
                const int r0 = q0 + wid * 16 + (lane >> 2);
                #pragma unroll
                for (int ni = 0; ni < 8; ni++) {
                    int c = kt0 + ni * 8 + (lane & 3) * 2;
                    if (c > r0)     accS[ni][0] = -1e30f;
                    if (c + 1 > r0) accS[ni][1] = -1e30f;
                    if (c > r0 + 8)     accS[ni][2] = -1e30f;
                    if (c + 1 > r0 + 8) accS[ni][3] = -1e30f;
                }
            }

            float mx0 = -1e30f, mx1 = -1e30f;
            #pragma unroll
            for (int ni = 0; ni < 8; ni++) {
                mx0 = fmaxf(mx0, fmaxf(accS[ni][0], accS[ni][1]));
                mx1 = fmaxf(mx1, fmaxf(accS[ni][2], accS[ni][3]));
            }
            mx0 = fmaxf(mx0, __shfl_xor_sync(0xffffffffu, mx0, 1));
            mx0 = fmaxf(mx0, __shfl_xor_sync(0xffffffffu, mx0, 2));
            mx1 = fmaxf(mx1, __shfl_xor_sync(0xffffffffu, mx1, 1));
            mx1 = fmaxf(mx1, __shfl_xor_sync(0xffffffffu, mx1, 2));

            const float mn0 = fmaxf(m0, mx0), mn1 = fmaxf(m1, mx1);
            const float al0 = exp2f(m0 - mn0), al1 = exp2f(m1 - mn1);
            m0 = mn0; m1 = mn1;

            uint32_t phA[8], phB[8], plA[8], plB[8];
            float s0 = 0.f, s1 = 0.f;
            #pragma unroll
            for (int ni = 0; ni < 8; ni++) {
                float p0 = exp2f(accS[ni][0] - mn0);
                float p1 = exp2f(accS[ni][1] - mn0);
                float p2 = exp2f(accS[ni][2] - mn1);
                float p3 = exp2f(accS[ni][3] - mn1);
                s0 += p0 + p1; s1 += p2 + p3;
                phA[ni] = pack_h2(p0, p1);
                phB[ni] = pack_h2(p2, p3);
                plA[ni] = pack_h2(h_res(p0), h_res(p1));
                plB[ni] = pack_h2(h_res(p2), h_res(p3));
            }
            s0 += __shfl_xor_sync(0xffffffffu, s0, 1);
            s0 += __shfl_xor_sync(0xffffffffu, s0, 2);
            s1 += __shfl_xor_sync(0xffffffffu, s1, 1);
            s1 += __shfl_xor_sync(0xffffffffu, s1, 2);
            l0 = l0 * al0 + s0;
            l1 = l1 * al1 + s1;

            #pragma unroll
            for (int ti = 0; ti < 16; ti++) {
                accO[ti][0] *= al0; accO[ti][1] *= al0;
                accO[ti][2] *= al1; accO[ti][3] *= al1;
            }

            #pragma unroll
            for (int j = 0; j < 4; j++) {
                uint32_t aPh[4] = { phA[2*j], phB[2*j], phA[2*j+1], phB[2*j+1] };
                uint32_t aPl[4] = { plA[2*j], plB[2*j], plA[2*j+1], plB[2*j+1] };
                #pragma unroll
                for (int dg = 0; dg < 8; dg++) {
                    uint32_t vaddr = (j * 16 + (lane & 15)) * FB_STRIDE_B
                                   + dg * 32 + (lane >> 4) * 16;
                    uint32_t fVh[4];
                    ldsm4t(fVh, sVh + vaddr);
                    const int t0i = dg * 2, t1i = dg * 2 + 1;
                    mma_f16(accO[t0i], aPh, fVh[0], fVh[1]);
                    mma_f16(accO[t0i], aPl, fVh[0], fVh[1]);
                    mma_f16(accO[t1i], aPh, fVh[2], fVh[3]);
                    mma_f16(accO[t1i], aPl, fVh[2], fVh[3]);
                }
            }
        }
        __syncthreads();
    }

    const float inv0 = 1.0f / l0, inv1 = 1.0f / l1;
    const size_t row0 = (size_t)(b * S_LEN + q0 + wid * 16 + (lane >> 2));
    const size_t row1 = row0 + 8;
    __half* oh0 = Oh_g + row0 * DIMN + h * HD;
    __half* oh1 = Oh_g + row1 * DIMN + h * HD;
    #pragma unroll
    for (int ti = 0; ti < 16; ti++) {
        int c = ti * 8 + (lane & 3) * 2;
        *(uint32_t*)(oh0 + c) = pack_h2(accO[ti][0] * inv0, accO[ti][1] * inv0);
        *(uint32_t*)(oh1 + c) = pack_h2(accO[ti][2] * inv1, accO[ti][3] * inv1);
    }
}

// ---------------------------------------------------------------------------
// Launch
// ---------------------------------------------------------------------------
extern "C" void kernel_launch(void* const* d_in, const int* in_sizes, int n_in,
                              void* d_out, int out_size)
{
    const float* x  = (const float*)d_in[0];
    const float* wq = (const float*)d_in[1];
    const float* wk = (const float*)d_in[2];
    const float* wv = (const float*)d_in[3];
    const float* wo = (const float*)d_in[4];
    float* out = (float*)d_out;

    __half *xh, *xl, *qh, *ql, *kh, *vh, *ah;
    __half *wqT, *wkT, *wvT, *woT;
    cudaGetSymbolAddress((void**)&xh, g_xh);   cudaGetSymbolAddress((void**)&xl, g_xl);
    cudaGetSymbolAddress((void**)&qh, g_qh);   cudaGetSymbolAddress((void**)&ql, g_ql);
    cudaGetSymbolAddress((void**)&kh, g_kh);   cudaGetSymbolAddress((void**)&vh, g_vh);
    cudaGetSymbolAddress((void**)&ah, g_ah);
    cudaGetSymbolAddress((void**)&wqT, g_wqT); cudaGetSymbolAddress((void**)&wkT, g_wkT);
    cudaGetSymbolAddress((void**)&wvT, g_wvT); cudaGetSymbolAddress((void**)&woT, g_woT);

    const int SM2 = GNS * 3 * PLANE;   // 2-term stages
    const int SM1 = GNS * 2 * PLANE;   // 1-term stages
    cudaFuncSetAttribute(gemm_f16<1, 2>,
                         cudaFuncAttributeMaxDynamicSharedMemorySize, SM2);
    cudaFuncSetAttribute(gemm_f16<2, 1>,
                         cudaFuncAttributeMaxDynamicSharedMemorySize, SM1);
    cudaFuncSetAttribute(gemm_f16<0, 1>,
                         cudaFuncAttributeMaxDynamicSharedMemorySize, SM1);
    cudaFuncSetAttribute(fattn_kernel,
                         cudaFuncAttributeMaxDynamicSharedMemorySize, FATTN_SMEM);

    int n4x = MROWS * DIMN / 4;
    conv_pair<<<(n4x + 255) / 256, 256>>>(x, xh, xl, n4x);
    convT_single<<<dim3(DIMN / 32, DIMN / 32), dim3(32, 8)>>>(wq, wqT, DIMN, DIMN);
    convT_single<<<dim3(KVDIM / 32, DIMN / 32), dim3(32, 8)>>>(wk, wkT, DIMN, KVDIM);
    convT_single<<<dim3(KVDIM / 32, DIMN / 32), dim3(32, 8)>>>(wv, wvT, DIMN, KVDIM);
    convT_single<<<dim3(DIMN / 32, DIMN / 32), dim3(32, 8)>>>(wo, woT, DIMN, DIMN);

    // Q: 2-term (logit path). K/V: 1-term.
    gemm_f16<1, 2><<<dim3(DIMN / 128, MROWS / 128), 256, SM2>>>(
        MROWS, DIMN, DIMN, xh, xl, wqT, nullptr, qh, ql);
    gemm_f16<2, 1><<<dim3(KVDIM / 128, MROWS / 128), 256, SM1>>>(
        MROWS, KVDIM, DIMN, xh, nullptr, wkT, nullptr, kh, nullptr);
    gemm_f16<2, 1><<<dim3(KVDIM / 128, MROWS / 128), 256, SM1>>>(
        MROWS, KVDIM, DIMN, xh, nullptr, wvT, nullptr, vh, nullptr);

    fattn_kernel<<<dim3(S_LEN / 128, HQ, BATCH), 256, FATTN_SMEM>>>(
        qh, ql, kh, vh, ah);

    // Output projection: 1-term.
    gemm_f16<0, 1><<<dim3(DIMN / 128, MROWS / 128), 256, SM1>>>(
        MROWS, DIMN, DIMN, ah, nullptr, woT, out, nullptr, nullptr);
}

// round 9
// speedup vs baseline: 7.0339x; 1.0899x over previous
#include <cuda_runtime.h>
#include <cuda_fp16.h>
#include <cstdint>

// Problem constants
#define DIMN    4096
#define S_LEN   2048
#define BATCH   2
#define HQ      32
#define HKV     8
#define NREP    4
#define HD      128
#define MROWS   (BATCH * S_LEN)   // 4096
#define KVDIM   (HKV * HD)        // 1024

// ---------------------------------------------------------------------------
// Scratch (__device__ globals)
// ---------------------------------------------------------------------------
__device__ __half g_xh[(size_t)MROWS * DIMN];
__device__ __half g_xl[(size_t)MROWS * DIMN];
__device__ __half g_qh[(size_t)MROWS * DIMN];     // single plane
__device__ __half g_kh[(size_t)MROWS * KVDIM];    // hi plane
__device__ __half g_kl[(size_t)MROWS * KVDIM];    // lo plane
__device__ __half g_vh[(size_t)MROWS * KVDIM];
__device__ __half g_ah[(size_t)MROWS * DIMN];
__device__ __half g_wqT[(size_t)DIMN * DIMN];
__device__ __half g_woT[(size_t)DIMN * DIMN];
__device__ __half g_wkT[(size_t)KVDIM * DIMN];
__device__ __half g_wvT[(size_t)KVDIM * DIMN];

// ---------------------------------------------------------------------------
// PTX helpers
// ---------------------------------------------------------------------------
__device__ __forceinline__ uint32_t smem_u32(const void* p) {
    return (uint32_t)__cvta_generic_to_shared(p);
}
__device__ __forceinline__ void ldsm4(uint32_t* r, uint32_t addr) {
    asm volatile("ldmatrix.sync.aligned.m8n8.x4.shared.b16 {%0,%1,%2,%3}, [%4];"
                 : "=r"(r[0]), "=r"(r[1]), "=r"(r[2]), "=r"(r[3]) : "r"(addr));
}
__device__ __forceinline__ void ldsm4t(uint32_t* r, uint32_t addr) {
    asm volatile("ldmatrix.sync.aligned.m8n8.x4.trans.shared.b16 {%0,%1,%2,%3}, [%4];"
                 : "=r"(r[0]), "=r"(r[1]), "=r"(r[2]), "=r"(r[3]) : "r"(addr));
}
__device__ __forceinline__ void mma_f16(float* d, const uint32_t* a,
                                        const uint32_t b0, const uint32_t b1) {
    asm volatile(
        "mma.sync.aligned.m16n8k16.row.col.f32.f16.f16.f32 "
        "{%0,%1,%2,%3}, {%4,%5,%6,%7}, {%8,%9}, {%0,%1,%2,%3};"
        : "+f"(d[0]), "+f"(d[1]), "+f"(d[2]), "+f"(d[3])
        : "r"(a[0]), "r"(a[1]), "r"(a[2]), "r"(a[3]), "r"(b0), "r"(b1));
}
__device__ __forceinline__ uint32_t pack_h2(float a, float b) {
    __half2 t = __floats2half2_rn(a, b);
    return *(uint32_t*)&t;
}
__device__ __forceinline__ float h_res(float v) {
    return v - __half2float(__float2half_rn(v));
}

// ---------------------------------------------------------------------------
// fp16 tensor-core GEMM: C[M,N] = (Ah [+ Al])[M,K] @ Bh[N,K]^T
// NTERMS = 1 or 2 A-planes. CTA 128x128, 8 warps, K-chunk 32, 3-stage.
// OUTMODE: 0 = fp32 C, 1 = fp16 pair (Ch,Cl), 2 = fp16 single (Ch).
// ---------------------------------------------------------------------------
constexpr int CK    = 32;
constexpr int PADW  = 40;
constexpr int PLANE = 128 * PADW * 2;      // 10240 B
constexpr int GNS   = 3;

template <int NTERMS>
__device__ __forceinline__ void prefetch_chunk(
    const __half* Ah, const __half* Al, const __half* Bh,
    int K, int mtile, int ntile, int k0, uint32_t tbase, int tid)
{
    #pragma unroll
    for (int u = tid; u < (NTERMS + 1) * 512; u += 256) {
        int plane = u >> 9;
        int r = (u >> 2) & 127;
        int seg = u & 3;
        const __half* src;
        if (plane == 0)                      src = Ah + (size_t)(mtile + r) * K + k0 + seg * 8;
        else if (NTERMS == 2 && plane == 1)  src = Al + (size_t)(mtile + r) * K + k0 + seg * 8;
        else                                 src = Bh + (size_t)(ntile + r) * K + k0 + seg * 8;
        uint32_t dst = tbase + plane * PLANE + r * (PADW * 2) + seg * 16;
        asm volatile("cp.async.cg.shared.global [%0], [%1], 16;"
                     :: "r"(dst), "l"(src) : "memory");
    }
}

template <int OUTMODE, int NTERMS>
__global__ __launch_bounds__(256, 2) void gemm_f16(
    int M, int N, int K,
    const __half* __restrict__ Ah, const __half* __restrict__ Al,
    const __half* __restrict__ Bh,
    float* __restrict__ C,
    __half* __restrict__ Ch, __half* __restrict__ Cl)
{
    constexpr int STG = (NTERMS + 1) * PLANE;
    extern __shared__ char smem[];
    const uint32_t sbase = smem_u32(smem);

    const int tid = threadIdx.x;
    const int wid = tid >> 5, lane = tid & 31;
    const int wm = wid >> 2;
    const int wn = wid & 3;
    const int mtile = blockIdx.y * 128;
    const int ntile = blockIdx.x * 128;
    const int nch = K / CK;

    float acc[4][4][4];
    #pragma unroll
    for (int mi = 0; mi < 4; mi++)
        #pragma unroll
        for (int ni = 0; ni < 4; ni++)
            #pragma unroll
            for (int e = 0; e < 4; e++) acc[mi][ni][e] = 0.f;

    const int a_row_in16 = (lane & 7) + ((lane >> 3) & 1) * 8;
    const int a_colb     = (lane >> 4) * 16;
    const int b_row_in16 = (lane & 7) + ((lane >> 4) & 1) * 8;
    const int b_colb     = ((lane >> 3) & 1) * 16;

    for (int i = 0; i < GNS; i++) {
        prefetch_chunk<NTERMS>(Ah, Al, Bh, K, mtile, ntile, i * CK,
                               sbase + i * STG, tid);
        asm volatile("cp.async.commit_group;" ::: "memory");
    }

    for (int i = 0; i < nch; i++) {
        const int s = i % GNS;
        const uint32_t tb = sbase + s * STG;
        asm volatile("cp.async.wait_group %0;" :: "n"(GNS - 1) : "memory");
        __syncthreads();

        const uint32_t aH = tb;
        const uint32_t aL = tb + PLANE;
        const uint32_t bH = tb + NTERMS * PLANE;

        #pragma unroll
        for (int ks = 0; ks < 2; ks++) {
            const int kb = ks * 32;
            uint32_t fB[2][4];
            #pragma unroll
            for (int ng = 0; ng < 2; ng++) {
                int row = wn * 32 + ng * 16 + b_row_in16;
                ldsm4(fB[ng], bH + row * (PADW * 2) + b_colb + kb);
            }
            uint32_t fA[4][4];
            #pragma unroll
            for (int mi = 0; mi < 4; mi++) {
                int row = wm * 64 + mi * 16 + a_row_in16;
                ldsm4(fA[mi], aH + row * (PADW * 2) + a_colb + kb);
            }
            #pragma unroll
            for (int mi = 0; mi < 4; mi++)
                #pragma unroll
                for (int ni = 0; ni < 4; ni++) {
                    const int ng = ni >> 1, hf = (ni & 1) * 2;
                    mma_f16(acc[mi][ni], fA[mi], fB[ng][hf], fB[ng][hf + 1]);
                }
            if (NTERMS == 2) {
                #pragma unroll
                for (int mi = 0; mi < 4; mi++) {
                    int row = wm * 64 + mi * 16 + a_row_in16;
                    ldsm4(fA[mi], aL + row * (PADW * 2) + a_colb + kb);
                }
                #pragma unroll
                for (int mi = 0; mi < 4; mi++)
                    #pragma unroll
                    for (int ni = 0; ni < 4; ni++) {
                        const int ng = ni >> 1, hf = (ni & 1) * 2;
                        mma_f16(acc[mi][ni], fA[mi], fB[ng][hf], fB[ng][hf + 1]);
                    }
            }
        }
        __syncthreads();

        if (i + GNS < nch)
            prefetch_chunk<NTERMS>(Ah, Al, Bh, K, mtile, ntile, (i + GNS) * CK,
                                   sbase + s * STG, tid);
        asm volatile("cp.async.commit_group;" ::: "memory");
    }

    const int r0b = mtile + wm * 64 + (lane >> 2);
    const int c0b = ntile + wn * 32 + (lane & 3) * 2;
    #pragma unroll
    for (int mi = 0; mi < 4; mi++) {
        #pragma unroll
        for (int ni = 0; ni < 4; ni++) {
            size_t o0 = (size_t)(r0b + mi * 16) * N + c0b + ni * 8;
            size_t o1 = (size_t)(r0b + mi * 16 + 8) * N + c0b + ni * 8;
            float v0 = acc[mi][ni][0], v1 = acc[mi][ni][1];
            float v2 = acc[mi][ni][2], v3 = acc[mi][ni][3];
            if (OUTMODE == 0) {
                *(float2*)(C + o0) = make_float2(v0, v1);
                *(float2*)(C + o1) = make_float2(v2, v3);
            } else if (OUTMODE == 2) {
                *(uint32_t*)(Ch + o0) = pack_h2(v0, v1);
                *(uint32_t*)(Ch + o1) = pack_h2(v2, v3);
            } else {
                *(uint32_t*)(Ch + o0) = pack_h2(v0, v1);
                *(uint32_t*)(Ch + o1) = pack_h2(v2, v3);
                *(uint32_t*)(Cl + o0) = pack_h2(h_res(v0), h_res(v1));
                *(uint32_t*)(Cl + o1) = pack_h2(h_res(v2), h_res(v3));
            }
        }
    }
}

// ---------------------------------------------------------------------------
// Conversions
// ---------------------------------------------------------------------------
__global__ void conv_pair(const float* __restrict__ in,
                          __half* __restrict__ hi, __half* __restrict__ lo, int n4)
{
    int i = blockIdx.x * blockDim.x + threadIdx.x;
    if (i >= n4) return;
    float4 v = ((const float4*)in)[i];
    ((uint32_t*)hi)[2 * i]     = pack_h2(v.x, v.y);
    ((uint32_t*)hi)[2 * i + 1] = pack_h2(v.z, v.w);
    ((uint32_t*)lo)[2 * i]     = pack_h2(h_res(v.x), h_res(v.y));
    ((uint32_t*)lo)[2 * i + 1] = pack_h2(h_res(v.z), h_res(v.w));
}

__global__ void convT_single(const float* __restrict__ W,
                             __half* __restrict__ Th, int K, int N)
{
    __shared__ float t[32][33];
    int n0 = blockIdx.x * 32, k0 = blockIdx.y * 32;
    int tx = threadIdx.x, ty0 = threadIdx.y;
    #pragma unroll
    for (int j = 0; j < 4; j++) {
        int ty = ty0 + 8 * j;
        t[ty][tx] = W[(size_t)(k0 + ty) * N + n0 + tx];
    }
    __syncthreads();
    #pragma unroll
    for (int j = 0; j < 4; j++) {
        int ty = ty0 + 8 * j;
        Th[(size_t)(n0 + ty) * K + k0 + tx] = __float2half_rn(t[tx][ty]);
    }
}

// ---------------------------------------------------------------------------
// fp16 flash attention: S = q @ (Kh+Kl)^T (2-term on K side), causal GQA.
// CTA: 128 q rows, 8 warps. K tiles of 64, double-buffered.
// smem: 1 Q plane (128 rows) + 2 stages x {Kh, Kl, V} (64 rows each).
// ---------------------------------------------------------------------------
constexpr int FB_STRIDE_B = 272;
constexpr int FPLANE  = 64 * FB_STRIDE_B;      // 17408
constexpr int QPLANE  = 128 * FB_STRIDE_B;     // 34816
constexpr int FATTN_SMEM = QPLANE + 6 * FPLANE;  // 139264

__global__ __launch_bounds__(256) void fattn_kernel(
    const __half* __restrict__ Qh_g,
    const __half* __restrict__ Kh_g, const __half* __restrict__ Kl_g,
    const __half* __restrict__ Vh_g,
    __half* __restrict__ Oh_g)
{
    extern __shared__ char smem[];
    const uint32_t sb = smem_u32(smem);
    const uint32_t sQh = sb;
    const uint32_t kvstart = sb + QPLANE;

    const int tid = threadIdx.x, wid = tid >> 5, lane = tid & 31;
    const int bx = blockIdx.x, h = blockIdx.y, b = blockIdx.z;
    const int q0 = bx * 128;
    const int kvh = h >> 2;

    const __half* qh = Qh_g + ((size_t)(b * S_LEN + q0)) * DIMN + h * HD;
    const __half* kh = Kh_g + ((size_t)(b * S_LEN)) * KVDIM + kvh * HD;
    const __half* kl = Kl_g + ((size_t)(b * S_LEN)) * KVDIM + kvh * HD;
    const __half* vh = Vh_g + ((size_t)(b * S_LEN)) * KVDIM + kvh * HD;

    auto load_kv = [&](int kt0, int s) {
        const uint32_t base = kvstart + 3 * s * FPLANE;
        #pragma unroll
        for (int u = tid; u < 3072; u += 256) {
            int plane = u >> 10, r = (u >> 4) & 63, seg = u & 15;
            const __half* src;
            if (plane == 0)      src = kh;
            else if (plane == 1) src = kl;
            else                 src = vh;
            src += (size_t)(kt0 + r) * KVDIM + seg * 8;
            uint32_t dst = base + plane * FPLANE + r * FB_STRIDE_B + seg * 16;
            asm volatile("cp.async.cg.shared.global [%0], [%1], 16;"
                         :: "r"(dst), "l"(src) : "memory");
        }
    };

    // Prologue: Q (1 plane x 128 rows) + KV(0)
    #pragma unroll
    for (int u = tid; u < 2048; u += 256) {
        int r = (u >> 4) & 127, seg = u & 15;
        const __half* src = qh + (size_t)r * DIMN + seg * 8;
        uint32_t dst = sQh + r * FB_STRIDE_B + seg * 16;
        asm volatile("cp.async.cg.shared.global [%0], [%1], 16;"
                     :: "r"(dst), "l"(src) : "memory");
    }
    load_kv(0, 0);
    asm volatile("cp.async.commit_group;" ::: "memory");

    float accO[16][4];
    #pragma unroll
    for (int t = 0; t < 16; t++)
        #pragma unroll
        for (int e = 0; e < 4; e++) accO[t][e] = 0.f;
    float m0 = -1e30f, m1 = -1e30f, l0 = 0.f, l1 = 0.f;

    const int a_r  = (lane & 7) + ((lane >> 3) & 1) * 8;
    const int a_cb = (lane >> 4) * 16;
    const int b_r  = (lane & 7) + ((lane >> 4) & 1) * 8;
    const int b_cb = ((lane >> 3) & 1) * 16;

    const float SL = 0.08838834764831845f * 1.4426950408889634f;

    const int n_tiles = 2 * bx + 2;
    for (int t = 0; t < n_tiles; t++) {
        const int kt0 = t * 64;
        const int cur = t & 1;
        if (t < n_tiles - 1) {
            load_kv((t + 1) * 64, cur ^ 1);
            asm volatile("cp.async.commit_group;" ::: "memory");
            asm volatile("cp.async.wait_group 1;" ::: "memory");
        } else {
            asm volatile("cp.async.wait_group 0;" ::: "memory");
        }
        __syncthreads();

        const bool active = !(t == n_tiles - 1 && wid < 4);

        if (active) {
            const uint32_t kvb = kvstart + 3 * cur * FPLANE;
            const uint32_t sKh = kvb, sKl = kvb + FPLANE, sVh = kvb + 2 * FPLANE;

            float accS[8][4];
            #pragma unroll
            for (int ni = 0; ni < 8; ni++)
                #pragma unroll
                for (int e = 0; e < 4; e++) accS[ni][e] = 0.f;

            #pragma unroll
            for (int kk = 0; kk < 8; kk++) {
                uint32_t fQ[4];
                uint32_t aaddr = (wid * 16 + a_r) * FB_STRIDE_B + kk * 32 + a_cb;
                ldsm4(fQ, sQh + aaddr);
                #pragma unroll
                for (int ng = 0; ng < 4; ng++) {
                    uint32_t baddr = (ng * 16 + b_r) * FB_STRIDE_B + kk * 32 + b_cb;
                    uint32_t fKh[4], fKl[4];
                    ldsm4(fKh, sKh + baddr);
                    ldsm4(fKl, sKl + baddr);
                    #pragma unroll
                    for (int hf2 = 0; hf2 < 2; hf2++) {
                        const int ni = ng * 2 + hf2;
                        mma_f16(accS[ni], fQ, fKh[hf2 * 2], fKh[hf2 * 2 + 1]);
                        mma_f16(accS[ni], fQ, fKl[hf2 * 2], fKl[hf2 * 2 + 1]);
                    }
                }
            }

            #pragma unroll
            for (int ni = 0; ni < 8; ni++)
                #pragma unroll
                for (int e = 0; e < 4; e++) accS[ni][e] *= SL;

            if (t >= n_tiles - 2) {
                const int r0 = q0 + wid * 16 + (lane >> 2);
                #pragma unroll
                for (int ni = 0; ni < 8; ni++) {
                    int c = kt0 + ni * 8 + (lane & 3) * 2;
                    if (c > r0)     accS[ni][0] = -1e30f;
                    if (c + 1 > r0) accS[ni][1] = -1e30f;
                    if (c > r0 + 8)     accS[ni][2] = -1e30f;
                    if (c + 1 > r0 + 8) accS[ni][3] = -1e30f;
                }
            }

            float mx0 = -1e30f, mx1 = -1e30f;
            #pragma unroll
            for (int ni = 0; ni < 8; ni++) {
                mx0 = fmaxf(mx0, fmaxf(accS[ni][0], accS[ni][1]));
                mx1 = fmaxf(mx1, fmaxf(accS[ni][2], accS[ni][3]));
            }
            mx0 = fmaxf(mx0, __shfl_xor_sync(0xffffffffu, mx0, 1));
            mx0 = fmaxf(mx0, __shfl_xor_sync(0xffffffffu, mx0, 2));
            mx1 = fmaxf(mx1, __shfl_xor_sync(0xffffffffu, mx1, 1));
            mx1 = fmaxf(mx1, __shfl_xor_sync(0xffffffffu, mx1, 2));

            const float mn0 = fmaxf(m0, mx0), mn1 = fmaxf(m1, mx1);
            const float al0 = exp2f(m0 - mn0), al1 = exp2f(m1 - mn1);
            m0 = mn0; m1 = mn1;

            uint32_t phA[8], phB[8], plA[8], plB[8];
            float s0 = 0.f, s1 = 0.f;
            #pragma unroll
            for (int ni = 0; ni < 8; ni++) {
                float p0 = exp2f(accS[ni][0] - mn0);
                float p1 = exp2f(accS[ni][1] - mn0);
                float p2 = exp2f(accS[ni][2] - mn1);
                float p3 = exp2f(accS[ni][3] - mn1);
                s0 += p0 + p1; s1 += p2 + p3;
                phA[ni] = pack_h2(p0, p1);
                phB[ni] = pack_h2(p2, p3);
                plA[ni] = pack_h2(h_res(p0), h_res(p1));
                plB[ni] = pack_h2(h_res(p2), h_res(p3));
            }
            s0 += __shfl_xor_sync(0xffffffffu, s0, 1);
            s0 += __shfl_xor_sync(0xffffffffu, s0, 2);
            s1 += __shfl_xor_sync(0xffffffffu, s1, 1);
            s1 += __shfl_xor_sync(0xffffffffu, s1, 2);
            l0 = l0 * al0 + s0;
            l1 = l1 * al1 + s1;

            #pragma unroll
            for (int ti = 0; ti < 16; ti++) {
                accO[ti][0] *= al0; accO[ti][1] *= al0;
                accO[ti][2] *= al1; accO[ti][3] *= al1;
            }

            #pragma unroll
            for (int j = 0; j < 4; j++) {
                uint32_t aPh[4] = { phA[2*j], phB[2*j], phA[2*j+1], phB[2*j+1] };
                uint32_t aPl[4] = { plA[2*j], plB[2*j], plA[2*j+1], plB[2*j+1] };
                #pragma unroll
                for (int dg = 0; dg < 8; dg++) {
                    uint32_t vaddr = (j * 16 + (lane & 15)) * FB_STRIDE_B
                                   + dg * 32 + (lane >> 4) * 16;
                    uint32_t fVh[4];
                    ldsm4t(fVh, sVh + vaddr);
                    const int t0i = dg * 2, t1i = dg * 2 + 1;
                    mma_f16(accO[t0i], aPh, fVh[0], fVh[1]);
                    mma_f16(accO[t0i], aPl, fVh[0], fVh[1]);
                    mma_f16(accO[t1i], aPh, fVh[2], fVh[3]);
                    mma_f16(accO[t1i], aPl, fVh[2], fVh[3]);
                }
            }
        }
        __syncthreads();
    }

    const float inv0 = 1.0f / l0, inv1 = 1.0f / l1;
    const size_t row0 = (size_t)(b * S_LEN + q0 + wid * 16 + (lane >> 2));
    const size_t row1 = row0 + 8;
    __half* oh0 = Oh_g + row0 * DIMN + h * HD;
    __half* oh1 = Oh_g + row1 * DIMN + h * HD;
    #pragma unroll
    for (int ti = 0; ti < 16; ti++) {
        int c = ti * 8 + (lane & 3) * 2;
        *(uint32_t*)(oh0 + c) = pack_h2(accO[ti][0] * inv0, accO[ti][1] * inv0);
        *(uint32_t*)(oh1 + c) = pack_h2(accO[ti][2] * inv1, accO[ti][3] * inv1);
    }
}

// ---------------------------------------------------------------------------
// Launch
// ---------------------------------------------------------------------------
extern "C" void kernel_launch(void* const* d_in, const int* in_sizes, int n_in,
                              void* d_out, int out_size)
{
    const float* x  = (const float*)d_in[0];
    const float* wq = (const float*)d_in[1];
    const float* wk = (const float*)d_in[2];
    const float* wv = (const float*)d_in[3];
    const float* wo = (const float*)d_in[4];
    float* out = (float*)d_out;

    __half *xh, *xl, *qh, *kh, *kl, *vh, *ah;
    __half *wqT, *wkT, *wvT, *woT;
    cudaGetSymbolAddress((void**)&xh, g_xh);   cudaGetSymbolAddress((void**)&xl, g_xl);
    cudaGetSymbolAddress((void**)&qh, g_qh);
    cudaGetSymbolAddress((void**)&kh, g_kh);   cudaGetSymbolAddress((void**)&kl, g_kl);
    cudaGetSymbolAddress((void**)&vh, g_vh);
    cudaGetSymbolAddress((void**)&ah, g_ah);
    cudaGetSymbolAddress((void**)&wqT, g_wqT); cudaGetSymbolAddress((void**)&wkT, g_wkT);
    cudaGetSymbolAddress((void**)&wvT, g_wvT); cudaGetSymbolAddress((void**)&woT, g_woT);

    const int SM2 = GNS * 3 * PLANE;   // 2-term stages
    const int SM1 = GNS * 2 * PLANE;   // 1-term stages
    cudaFuncSetAttribute(gemm_f16<2, 1>,
                         cudaFuncAttributeMaxDynamicSharedMemorySize, SM1);
    cudaFuncSetAttribute(gemm_f16<1, 2>,
                         cudaFuncAttributeMaxDynamicSharedMemorySize, SM2);
    cudaFuncSetAttribute(gemm_f16<0, 1>,
                         cudaFuncAttributeMaxDynamicSharedMemorySize, SM1);
    cudaFuncSetAttribute(fattn_kernel,
                         cudaFuncAttributeMaxDynamicSharedMemorySize, FATTN_SMEM);

    int n4x = MROWS * DIMN / 4;
    conv_pair<<<(n4x + 255) / 256, 256>>>(x, xh, xl, n4x);
    convT_single<<<dim3(DIMN / 32, DIMN / 32), dim3(32, 8)>>>(wq, wqT, DIMN, DIMN);
    convT_single<<<dim3(KVDIM / 32, DIMN / 32), dim3(32, 8)>>>(wk, wkT, DIMN, KVDIM);
    convT_single<<<dim3(KVDIM / 32, DIMN / 32), dim3(32, 8)>>>(wv, wvT, DIMN, KVDIM);
    convT_single<<<dim3(DIMN / 32, DIMN / 32), dim3(32, 8)>>>(wo, woT, DIMN, DIMN);

    // Q: 1-term, single-plane out. K: 2-term, pair out. V: 1-term.
    gemm_f16<2, 1><<<dim3(DIMN / 128, MROWS / 128), 256, SM1>>>(
        MROWS, DIMN, DIMN, xh, nullptr, wqT, nullptr, qh, nullptr);
    gemm_f16<1, 2><<<dim3(KVDIM / 128, MROWS / 128), 256, SM2>>>(
        MROWS, KVDIM, DIMN, xh, xl, wkT, nullptr, kh, kl);
    gemm_f16<2, 1><<<dim3(KVDIM / 128, MROWS / 128), 256, SM1>>>(
        MROWS, KVDIM, DIMN, xh, nullptr, wvT, nullptr, vh, nullptr);

    fattn_kernel<<<dim3(S_LEN / 128, HQ, BATCH), 256, FATTN_SMEM>>>(
        qh, kh, kl, vh, ah);

    // Output projection: 1-term.
    gemm_f16<0, 1><<<dim3(DIMN / 128, MROWS / 128), 256, SM1>>>(
        MROWS, DIMN, DIMN, ah, nullptr, woT, out, nullptr, nullptr);
}

// round 10
// speedup vs baseline: 7.2167x; 1.0260x over previous
#include <cuda_runtime.h>
#include <cuda_fp16.h>
#include <cstdint>

// Problem constants
#define DIMN    4096
#define S_LEN   2048
#define BATCH   2
#define HQ      32
#define HKV     8
#define NREP    4
#define HD      128
#define MROWS   (BATCH * S_LEN)   // 4096
#define KVDIM   (HKV * HD)        // 1024

// ---------------------------------------------------------------------------
// Scratch (__device__ globals)
// ---------------------------------------------------------------------------
__device__ __half g_xh[(size_t)MROWS * DIMN];
__device__ __half g_xl[(size_t)MROWS * DIMN];
__device__ __half g_qh[(size_t)MROWS * DIMN];
__device__ __half g_kh[(size_t)MROWS * KVDIM];
__device__ __half g_kl[(size_t)MROWS * KVDIM];
__device__ __half g_vh[(size_t)MROWS * KVDIM];
__device__ __half g_ah[(size_t)MROWS * DIMN];
__device__ __half g_wqT[(size_t)DIMN * DIMN];
__device__ __half g_woT[(size_t)DIMN * DIMN];
__device__ __half g_wkT[(size_t)KVDIM * DIMN];
__device__ __half g_wvT[(size_t)KVDIM * DIMN];

// ---------------------------------------------------------------------------
// PTX helpers
// ---------------------------------------------------------------------------
__device__ __forceinline__ uint32_t smem_u32(const void* p) {
    return (uint32_t)__cvta_generic_to_shared(p);
}
__device__ __forceinline__ void ldsm4(uint32_t* r, uint32_t addr) {
    asm volatile("ldmatrix.sync.aligned.m8n8.x4.shared.b16 {%0,%1,%2,%3}, [%4];"
                 : "=r"(r[0]), "=r"(r[1]), "=r"(r[2]), "=r"(r[3]) : "r"(addr));
}
__device__ __forceinline__ void ldsm4t(uint32_t* r, uint32_t addr) {
    asm volatile("ldmatrix.sync.aligned.m8n8.x4.trans.shared.b16 {%0,%1,%2,%3}, [%4];"
                 : "=r"(r[0]), "=r"(r[1]), "=r"(r[2]), "=r"(r[3]) : "r"(addr));
}
__device__ __forceinline__ void mma_f16(float* d, const uint32_t* a,
                                        const uint32_t b0, const uint32_t b1) {
    asm volatile(
        "mma.sync.aligned.m16n8k16.row.col.f32.f16.f16.f32 "
        "{%0,%1,%2,%3}, {%4,%5,%6,%7}, {%8,%9}, {%0,%1,%2,%3};"
        : "+f"(d[0]), "+f"(d[1]), "+f"(d[2]), "+f"(d[3])
        : "r"(a[0]), "r"(a[1]), "r"(a[2]), "r"(a[3]), "r"(b0), "r"(b1));
}
__device__ __forceinline__ uint32_t pack_h2(float a, float b) {
    __half2 t = __floats2half2_rn(a, b);
    return *(uint32_t*)&t;
}
__device__ __forceinline__ float h_res(float v) {
    return v - __half2float(__float2half_rn(v));
}

// ---------------------------------------------------------------------------
// GEMM common pieces
// ---------------------------------------------------------------------------
constexpr int CK    = 32;
constexpr int PADW  = 40;
constexpr int PLANE = 128 * PADW * 2;      // 10240 B
constexpr int GNS   = 3;

__device__ __forceinline__ void prefetch_rt(
    const __half* Ah, const __half* Al, const __half* Bh, int nterms,
    int K, int mtile, int ntile, int k0, uint32_t tbase, int tid)
{
    const int tot = (nterms + 1) * 512;
    for (int u = tid; u < tot; u += 256) {
        int plane = u >> 9;
        int r = (u >> 2) & 127;
        int seg = u & 3;
        const __half* src;
        if (plane == 0)                     src = Ah + (size_t)(mtile + r) * K + k0 + seg * 8;
        else if (nterms == 2 && plane == 1) src = Al + (size_t)(mtile + r) * K + k0 + seg * 8;
        else                                src = Bh + (size_t)(ntile + r) * K + k0 + seg * 8;
        uint32_t dst = tbase + plane * PLANE + r * (PADW * 2) + seg * 16;
        asm volatile("cp.async.cg.shared.global [%0], [%1], 16;"
                     :: "r"(dst), "l"(src) : "memory");
    }
}

// ---------------------------------------------------------------------------
// Merged Q|K|V projection GEMM. grid.x = 48 column tiles:
//   [0,32): q (1-term, out qh), [32,40): k (2-term, out kh+kl), [40,48): v (1-term, out vh)
// ---------------------------------------------------------------------------
constexpr int QKV_SMEM = GNS * 3 * PLANE;   // 92160 (max: 2-term stage)

__global__ __launch_bounds__(256, 2) void gemm_qkv(
    const __half* __restrict__ xh, const __half* __restrict__ xl,
    const __half* __restrict__ wqT, const __half* __restrict__ wkT,
    const __half* __restrict__ wvT,
    __half* __restrict__ qh, __half* __restrict__ kh,
    __half* __restrict__ kl, __half* __restrict__ vh)
{
    extern __shared__ char smem[];
    const uint32_t sbase = smem_u32(smem);

    const int tid = threadIdx.x;
    const int wid = tid >> 5, lane = tid & 31;
    const int wm = wid >> 2;
    const int wn = wid & 3;
    const int mtile = blockIdx.y * 128;
    const int nx = blockIdx.x;
    const int K = DIMN;
    const int nch = K / CK;

    // Segment select (uniform per CTA)
    const __half* B;
    __half *Oh, *Ol;
    int ntile, Nout, nterms;
    if (nx < 32)      { B = wqT; Oh = qh; Ol = nullptr; ntile = nx * 128;        Nout = DIMN;  nterms = 1; }
    else if (nx < 40) { B = wkT; Oh = kh; Ol = kl;      ntile = (nx - 32) * 128; Nout = KVDIM; nterms = 2; }
    else              { B = wvT; Oh = vh; Ol = nullptr; ntile = (nx - 40) * 128; Nout = KVDIM; nterms = 1; }
    const int STG = (nterms + 1) * PLANE;

    float acc[4][4][4];
    #pragma unroll
    for (int mi = 0; mi < 4; mi++)
        #pragma unroll
        for (int ni = 0; ni < 4; ni++)
            #pragma unroll
            for (int e = 0; e < 4; e++) acc[mi][ni][e] = 0.f;

    const int a_row_in16 = (lane & 7) + ((lane >> 3) & 1) * 8;
    const int a_colb     = (lane >> 4) * 16;
    const int b_row_in16 = (lane & 7) + ((lane >> 4) & 1) * 8;
    const int b_colb     = ((lane >> 3) & 1) * 16;

    for (int i = 0; i < GNS; i++) {
        prefetch_rt(xh, xl, B, nterms, K, mtile, ntile, i * CK, sbase + i * STG, tid);
        asm volatile("cp.async.commit_group;" ::: "memory");
    }

    for (int i = 0; i < nch; i++) {
        const int s = i % GNS;
        const uint32_t tb = sbase + s * STG;
        asm volatile("cp.async.wait_group %0;" :: "n"(GNS - 1) : "memory");
        __syncthreads();

        const uint32_t aH = tb;
        const uint32_t aL = tb + PLANE;
        const uint32_t bH = tb + nterms * PLANE;

        #pragma unroll
        for (int ks = 0; ks < 2; ks++) {
            const int kb = ks * 32;
            uint32_t fB[2][4];
            #pragma unroll
            for (int ng = 0; ng < 2; ng++) {
                int row = wn * 32 + ng * 16 + b_row_in16;
                ldsm4(fB[ng], bH + row * (PADW * 2) + b_colb + kb);
            }
            uint32_t fA[4][4];
            #pragma unroll
            for (int mi = 0; mi < 4; mi++) {
                int row = wm * 64 + mi * 16 + a_row_in16;
                ldsm4(fA[mi], aH + row * (PADW * 2) + a_colb + kb);
            }
            #pragma unroll
            for (int mi = 0; mi < 4; mi++)
                #pragma unroll
                for (int ni = 0; ni < 4; ni++) {
                    const int ng = ni >> 1, hf = (ni & 1) * 2;
                    mma_f16(acc[mi][ni], fA[mi], fB[ng][hf], fB[ng][hf + 1]);
                }
            if (nterms == 2) {
                #pragma unroll
                for (int mi = 0; mi < 4; mi++) {
                    int row = wm * 64 + mi * 16 + a_row_in16;
                    ldsm4(fA[mi], aL + row * (PADW * 2) + a_colb + kb);
                }
                #pragma unroll
                for (int mi = 0; mi < 4; mi++)
                    #pragma unroll
                    for (int ni = 0; ni < 4; ni++) {
                        const int ng = ni >> 1, hf = (ni & 1) * 2;
                        mma_f16(acc[mi][ni], fA[mi], fB[ng][hf], fB[ng][hf + 1]);
                    }
            }
        }
        __syncthreads();

        if (i + GNS < nch)
            prefetch_rt(xh, xl, B, nterms, K, mtile, ntile, (i + GNS) * CK,
                        sbase + s * STG, tid);
        asm volatile("cp.async.commit_group;" ::: "memory");
    }

    const int r0b = mtile + wm * 64 + (lane >> 2);
    const int c0b = ntile + wn * 32 + (lane & 3) * 2;
    #pragma unroll
    for (int mi = 0; mi < 4; mi++) {
        #pragma unroll
        for (int ni = 0; ni < 4; ni++) {
            size_t o0 = (size_t)(r0b + mi * 16) * Nout + c0b + ni * 8;
            size_t o1 = (size_t)(r0b + mi * 16 + 8) * Nout + c0b + ni * 8;
            float v0 = acc[mi][ni][0], v1 = acc[mi][ni][1];
            float v2 = acc[mi][ni][2], v3 = acc[mi][ni][3];
            *(uint32_t*)(Oh + o0) = pack_h2(v0, v1);
            *(uint32_t*)(Oh + o1) = pack_h2(v2, v3);
            if (Ol != nullptr) {
                *(uint32_t*)(Ol + o0) = pack_h2(h_res(v0), h_res(v1));
                *(uint32_t*)(Ol + o1) = pack_h2(h_res(v2), h_res(v3));
            }
        }
    }
}

// ---------------------------------------------------------------------------
// wo GEMM: C[M,N] = A[M,K] @ B[N,K]^T, 1-term, fp32 out.
// ---------------------------------------------------------------------------
constexpr int WO_SMEM = GNS * 2 * PLANE;   // 61440

__global__ __launch_bounds__(256, 2) void gemm_wo(
    int M, int N, int K,
    const __half* __restrict__ Ah, const __half* __restrict__ Bh,
    float* __restrict__ C)
{
    constexpr int STG = 2 * PLANE;
    extern __shared__ char smem[];
    const uint32_t sbase = smem_u32(smem);

    const int tid = threadIdx.x;
    const int wid = tid >> 5, lane = tid & 31;
    const int wm = wid >> 2;
    const int wn = wid & 3;
    const int mtile = blockIdx.y * 128;
    const int ntile = blockIdx.x * 128;
    const int nch = K / CK;

    float acc[4][4][4];
    #pragma unroll
    for (int mi = 0; mi < 4; mi++)
        #pragma unroll
        for (int ni = 0; ni < 4; ni++)
            #pragma unroll
            for (int e = 0; e < 4; e++) acc[mi][ni][e] = 0.f;

    const int a_row_in16 = (lane & 7) + ((lane >> 3) & 1) * 8;
    const int a_colb     = (lane >> 4) * 16;
    const int b_row_in16 = (lane & 7) + ((lane >> 4) & 1) * 8;
    const int b_colb     = ((lane >> 3) & 1) * 16;

    for (int i = 0; i < GNS; i++) {
        prefetch_rt(Ah, nullptr, Bh, 1, K, mtile, ntile, i * CK, sbase + i * STG, tid);
        asm volatile("cp.async.commit_group;" ::: "memory");
    }

    for (int i = 0; i < nch; i++) {
        const int s = i % GNS;
        const uint32_t tb = sbase + s * STG;
        asm volatile("cp.async.wait_group %0;" :: "n"(GNS - 1) : "memory");
        __syncthreads();

        const uint32_t aH = tb;
        const uint32_t bH = tb + PLANE;

        #pragma unroll
        for (int ks = 0; ks < 2; ks++) {
            const int kb = ks * 32;
            uint32_t fB[2][4];
            #pragma unroll
            for (int ng = 0; ng < 2; ng++) {
                int row = wn * 32 + ng * 16 + b_row_in16;
                ldsm4(fB[ng], bH + row * (PADW * 2) + b_colb + kb);
            }
            uint32_t fA[4][4];
            #pragma unroll
            for (int mi = 0; mi < 4; mi++) {
                int row = wm * 64 + mi * 16 + a_row_in16;
                ldsm4(fA[mi], aH + row * (PADW * 2) + a_colb + kb);
            }
            #pragma unroll
            for (int mi = 0; mi < 4; mi++)
                #pragma unroll
                for (int ni = 0; ni < 4; ni++) {
                    const int ng = ni >> 1, hf = (ni & 1) * 2;
                    mma_f16(acc[mi][ni], fA[mi], fB[ng][hf], fB[ng][hf + 1]);
                }
        }
        __syncthreads();

        if (i + GNS < nch)
            prefetch_rt(Ah, nullptr, Bh, 1, K, mtile, ntile, (i + GNS) * CK,
                        sbase + s * STG, tid);
        asm volatile("cp.async.commit_group;" ::: "memory");
    }

    const int r0b = mtile + wm * 64 + (lane >> 2);
    const int c0b = ntile + wn * 32 + (lane & 3) * 2;
    #pragma unroll
    for (int mi = 0; mi < 4; mi++) {
        #pragma unroll
        for (int ni = 0; ni < 4; ni++) {
            size_t o0 = (size_t)(r0b + mi * 16) * N + c0b + ni * 8;
            size_t o1 = (size_t)(r0b + mi * 16 + 8) * N + c0b + ni * 8;
            *(float2*)(C + o0) = make_float2(acc[mi][ni][0], acc[mi][ni][1]);
            *(float2*)(C + o1) = make_float2(acc[mi][ni][2], acc[mi][ni][3]);
        }
    }
}

// ---------------------------------------------------------------------------
// Conversions
// ---------------------------------------------------------------------------
__global__ void conv_pair(const float* __restrict__ in,
                          __half* __restrict__ hi, __half* __restrict__ lo, int n4)
{
    int i = blockIdx.x * blockDim.x + threadIdx.x;
    if (i >= n4) return;
    float4 v = ((const float4*)in)[i];
    ((uint32_t*)hi)[2 * i]     = pack_h2(v.x, v.y);
    ((uint32_t*)hi)[2 * i + 1] = pack_h2(v.z, v.w);
    ((uint32_t*)lo)[2 * i]     = pack_h2(h_res(v.x), h_res(v.y));
    ((uint32_t*)lo)[2 * i + 1] = pack_h2(h_res(v.z), h_res(v.w));
}

__global__ void convT_single(const float* __restrict__ W,
                             __half* __restrict__ Th, int K, int N)
{
    __shared__ float t[32][33];
    int n0 = blockIdx.x * 32, k0 = blockIdx.y * 32;
    int tx = threadIdx.x, ty0 = threadIdx.y;
    #pragma unroll
    for (int j = 0; j < 4; j++) {
        int ty = ty0 + 8 * j;
        t[ty][tx] = W[(size_t)(k0 + ty) * N + n0 + tx];
    }
    __syncthreads();
    #pragma unroll
    for (int j = 0; j < 4; j++) {
        int ty = ty0 + 8 * j;
        Th[(size_t)(n0 + ty) * K + k0 + tx] = __float2half_rn(t[tx][ty]);
    }
}

// ---------------------------------------------------------------------------
// fp16 flash attention: S = q @ (Kh+Kl)^T, O = P @ V (1-term PV), causal GQA.
// CTA: 128 q rows, 8 warps. K tiles of 64, double-buffered.
// bx reversed so longest CTAs launch first (tail packing).
// ---------------------------------------------------------------------------
constexpr int FB_STRIDE_B = 272;
constexpr int FPLANE  = 64 * FB_STRIDE_B;      // 17408
constexpr int QPLANE  = 128 * FB_STRIDE_B;     // 34816
constexpr int FATTN_SMEM = QPLANE + 6 * FPLANE;  // 139264

__global__ __launch_bounds__(256) void fattn_kernel(
    const __half* __restrict__ Qh_g,
    const __half* __restrict__ Kh_g, const __half* __restrict__ Kl_g,
    const __half* __restrict__ Vh_g,
    __half* __restrict__ Oh_g)
{
    extern __shared__ char smem[];
    const uint32_t sb = smem_u32(smem);
    const uint32_t sQh = sb;
    const uint32_t kvstart = sb + QPLANE;

    const int tid = threadIdx.x, wid = tid >> 5, lane = tid & 31;
    const int bx = gridDim.x - 1 - blockIdx.x;   // longest work first
    const int h = blockIdx.y, b = blockIdx.z;
    const int q0 = bx * 128;
    const int kvh = h >> 2;

    const __half* qh = Qh_g + ((size_t)(b * S_LEN + q0)) * DIMN + h * HD;
    const __half* kh = Kh_g + ((size_t)(b * S_LEN)) * KVDIM + kvh * HD;
    const __half* kl = Kl_g + ((size_t)(b * S_LEN)) * KVDIM + kvh * HD;
    const __half* vh = Vh_g + ((size_t)(b * S_LEN)) * KVDIM + kvh * HD;

    auto load_kv = [&](int kt0, int s) {
        const uint32_t base = kvstart + 3 * s * FPLANE;
        #pragma unroll
        for (int u = tid; u < 3072; u += 256) {
            int plane = u >> 10, r = (u >> 4) & 63, seg = u & 15;
            const __half* src;
            if (plane == 0)      src = kh;
            else if (plane == 1) src = kl;
            else                 src = vh;
            src += (size_t)(kt0 + r) * KVDIM + seg * 8;
            uint32_t dst = base + plane * FPLANE + r * FB_STRIDE_B + seg * 16;
            asm volatile("cp.async.cg.shared.global [%0], [%1], 16;"
                         :: "r"(dst), "l"(src) : "memory");
        }
    };

    #pragma unroll
    for (int u = tid; u < 2048; u += 256) {
        int r = (u >> 4) & 127, seg = u & 15;
        const __half* src = qh + (size_t)r * DIMN + seg * 8;
        uint32_t dst = sQh + r * FB_STRIDE_B + seg * 16;
        asm volatile("cp.async.cg.shared.global [%0], [%1], 16;"
                     :: "r"(dst), "l"(src) : "memory");
    }
    load_kv(0, 0);
    asm volatile("cp.async.commit_group;" ::: "memory");

    float accO[16][4];
    #pragma unroll
    for (int t = 0; t < 16; t++)
        #pragma unroll
        for (int e = 0; e < 4; e++) accO[t][e] = 0.f;
    float m0 = -1e30f, m1 = -1e30f, l0 = 0.f, l1 = 0.f;

    const int a_r  = (lane & 7) + ((lane >> 3) & 1) * 8;
    const int a_cb = (lane >> 4) * 16;
    const int b_r  = (lane & 7) + ((lane >> 4) & 1) * 8;
    const int b_cb = ((lane >> 3) & 1) * 16;

    const float SL = 0.08838834764831845f * 1.4426950408889634f;

    const int n_tiles = 2 * bx + 2;
    for (int t = 0; t < n_tiles; t++) {
        const int kt0 = t * 64;
        const int cur = t & 1;
        if (t < n_tiles - 1) {
            load_kv((t + 1) * 64, cur ^ 1);
            asm volatile("cp.async.commit_group;" ::: "memory");
            asm volatile("cp.async.wait_group 1;" ::: "memory");
        } else {
            asm volatile("cp.async.wait_group 0;" ::: "memory");
        }
        __syncthreads();

        const bool active = !(t == n_tiles - 1 && wid < 4);

        if (active) {
            const uint32_t kvb = kvstart + 3 * cur * FPLANE;
            const uint32_t sKh = kvb, sKl = kvb + FPLANE, sVh = kvb + 2 * FPLANE;

            float accS[8][4];
            #pragma unroll
            for (int ni = 0; ni < 8; ni++)
                #pragma unroll
                for (int e = 0; e < 4; e++) accS[ni][e] = 0.f;

            #pragma unroll
            for (int kk = 0; kk < 8; kk++) {
                uint32_t fQ[4];
                uint32_t aaddr = (wid * 16 + a_r) * FB_STRIDE_B + kk * 32 + a_cb;
                ldsm4(fQ, sQh + aaddr);
                #pragma unroll
                for (int ng = 0; ng < 4; ng++) {
                    uint32_t baddr = (ng * 16 + b_r) * FB_STRIDE_B + kk * 32 + b_cb;
                    uint32_t fKh[4], fKl[4];
                    ldsm4(fKh, sKh + baddr);
                    ldsm4(fKl, sKl + baddr);
                    #pragma unroll
                    for (int hf2 = 0; hf2 < 2; hf2++) {
                        const int ni = ng * 2 + hf2;
                        mma_f16(accS[ni], fQ, fKh[hf2 * 2], fKh[hf2 * 2 + 1]);
                        mma_f16(accS[ni], fQ, fKl[hf2 * 2], fKl[hf2 * 2 + 1]);
                    }
                }
            }

            #pragma unroll
            for (int ni = 0; ni < 8; ni++)
                #pragma unroll
                for (int e = 0; e < 4; e++) accS[ni][e] *= SL;

            if (t >= n_tiles - 2) {
                const int r0 = q0 + wid * 16 + (lane >> 2);
                #pragma unroll
                for (int ni = 0; ni < 8; ni++) {
                    int c = kt0 + ni * 8 + (lane & 3) * 2;
                    if (c > r0)     accS[ni][0] = -1e30f;
                    if (c + 1 > r0) accS[ni][1] = -1e30f;
                    if (c > r0 + 8)     accS[ni][2] = -1e30f;
                    if (c + 1 > r0 + 8) accS[ni][3] = -1e30f;
                }
            }

            float mx0 = -1e30f, mx1 = -1e30f;
            #pragma unroll
            for (int ni = 0; ni < 8; ni++) {
                mx0 = fmaxf(mx0, fmaxf(accS[ni][0], accS[ni][1]));
                mx1 = fmaxf(mx1, fmaxf(accS[ni][2], accS[ni][3]));
            }
            mx0 = fmaxf(mx0, __shfl_xor_sync(0xffffffffu, mx0, 1));
            mx0 = fmaxf(mx0, __shfl_xor_sync(0xffffffffu, mx0, 2));
            mx1 = fmaxf(mx1, __shfl_xor_sync(0xffffffffu, mx1, 1));
            mx1 = fmaxf(mx1, __shfl_xor_sync(0xffffffffu, mx1, 2));

            const float mn0 = fmaxf(m0, mx0), mn1 = fmaxf(m1, mx1);
            const float al0 = exp2f(m0 - mn0), al1 = exp2f(m1 - mn1);
            m0 = mn0; m1 = mn1;

            uint32_t phA[8], phB[8];
            float s0 = 0.f, s1 = 0.f;
            #pragma unroll
            for (int ni = 0; ni < 8; ni++) {
                float p0 = exp2f(accS[ni][0] - mn0);
                float p1 = exp2f(accS[ni][1] - mn0);
                float p2 = exp2f(accS[ni][2] - mn1);
                float p3 = exp2f(accS[ni][3] - mn1);
                s0 += p0 + p1; s1 += p2 + p3;
                phA[ni] = pack_h2(p0, p1);
                phB[ni] = pack_h2(p2, p3);
            }
            s0 += __shfl_xor_sync(0xffffffffu, s0, 1);
            s0 += __shfl_xor_sync(0xffffffffu, s0, 2);
            s1 += __shfl_xor_sync(0xffffffffu, s1, 1);
            s1 += __shfl_xor_sync(0xffffffffu, s1, 2);
            l0 = l0 * al0 + s0;
            l1 = l1 * al1 + s1;

            #pragma unroll
            for (int ti = 0; ti < 16; ti++) {
                accO[ti][0] *= al0; accO[ti][1] *= al0;
                accO[ti][2] *= al1; accO[ti][3] *= al1;
            }

            #pragma unroll
            for (int j = 0; j < 4; j++) {
                uint32_t aPh[4] = { phA[2*j], phB[2*j], phA[2*j+1], phB[2*j+1] };
                #pragma unroll
                for (int dg = 0; dg < 8; dg++) {
                    uint32_t vaddr = (j * 16 + (lane & 15)) * FB_STRIDE_B
                                   + dg * 32 + (lane >> 4) * 16;
                    uint32_t fVh[4];
                    ldsm4t(fVh, sVh + vaddr);
                    mma_f16(accO[dg * 2],     aPh, fVh[0], fVh[1]);
                    mma_f16(accO[dg * 2 + 1], aPh, fVh[2], fVh[3]);
                }
            }
        }
        __syncthreads();
    }

    const float inv0 = 1.0f / l0, inv1 = 1.0f / l1;
    const size_t row0 = (size_t)(b * S_LEN + q0 + wid * 16 + (lane >> 2));
    const size_t row1 = row0 + 8;
    __half* oh0 = Oh_g + row0 * DIMN + h * HD;
    __half* oh1 = Oh_g + row1 * DIMN + h * HD;
    #pragma unroll
    for (int ti = 0; ti < 16; ti++) {
        int c = ti * 8 + (lane & 3) * 2;
        *(uint32_t*)(oh0 + c) = pack_h2(accO[ti][0] * inv0, accO[ti][1] * inv0);
        *(uint32_t*)(oh1 + c) = pack_h2(accO[ti][2] * inv1, accO[ti][3] * inv1);
    }
}

// ---------------------------------------------------------------------------
// Launch
// ---------------------------------------------------------------------------
extern "C" void kernel_launch(void* const* d_in, const int* in_sizes, int n_in,
                              void* d_out, int out_size)
{
    const float* x  = (const float*)d_in[0];
    const float* wq = (const float*)d_in[1];
    const float* wk = (const float*)d_in[2];
    const float* wv = (const float*)d_in[3];
    const float* wo = (const float*)d_in[4];
    float* out = (float*)d_out;

    __half *xh, *xl, *qh, *kh, *kl, *vh, *ah;
    __half *wqT, *wkT, *wvT, *woT;
    cudaGetSymbolAddress((void**)&xh, g_xh);   cudaGetSymbolAddress((void**)&xl, g_xl);
    cudaGetSymbolAddress((void**)&qh, g_qh);
    cudaGetSymbolAddress((void**)&kh, g_kh);   cudaGetSymbolAddress((void**)&kl, g_kl);
    cudaGetSymbolAddress((void**)&vh, g_vh);
    cudaGetSymbolAddress((void**)&ah, g_ah);
    cudaGetSymbolAddress((void**)&wqT, g_wqT); cudaGetSymbolAddress((void**)&wkT, g_wkT);
    cudaGetSymbolAddress((void**)&wvT, g_wvT); cudaGetSymbolAddress((void**)&woT, g_woT);

    cudaFuncSetAttribute(gemm_qkv,
                         cudaFuncAttributeMaxDynamicSharedMemorySize, QKV_SMEM);
    cudaFuncSetAttribute(gemm_wo,
                         cudaFuncAttributeMaxDynamicSharedMemorySize, WO_SMEM);
    cudaFuncSetAttribute(fattn_kernel,
                         cudaFuncAttributeMaxDynamicSharedMemorySize, FATTN_SMEM);

    int n4x = MROWS * DIMN / 4;
    conv_pair<<<(n4x + 255) / 256, 256>>>(x, xh, xl, n4x);
    convT_single<<<dim3(DIMN / 32, DIMN / 32), dim3(32, 8)>>>(wq, wqT, DIMN, DIMN);
    convT_single<<<dim3(KVDIM / 32, DIMN / 32), dim3(32, 8)>>>(wk, wkT, DIMN, KVDIM);
    convT_single<<<dim3(KVDIM / 32, DIMN / 32), dim3(32, 8)>>>(wv, wvT, DIMN, KVDIM);
    convT_single<<<dim3(DIMN / 32, DIMN / 32), dim3(32, 8)>>>(wo, woT, DIMN, DIMN);

    // Merged Q|K|V projection
    gemm_qkv<<<dim3(48, MROWS / 128), 256, QKV_SMEM>>>(
        xh, xl, wqT, wkT, wvT, qh, kh, kl, vh);

    fattn_kernel<<<dim3(S_LEN / 128, HQ, BATCH), 256, FATTN_SMEM>>>(
        qh, kh, kl, vh, ah);

    gemm_wo<<<dim3(DIMN / 128, MROWS / 128), 256, WO_SMEM>>>(
        MROWS, DIMN, DIMN, ah, woT, out);
}

// round 11
// speedup vs baseline: 7.9731x; 1.1048x over previous
#include <cuda_runtime.h>
#include <cuda_fp16.h>
#include <cstdint>

// Problem constants
#define DIMN    4096
#define S_LEN   2048
#define BATCH   2
#define HQ      32
#define HKV     8
#define NREP    4
#define HD      128
#define MROWS   (BATCH * S_LEN)   // 4096
#define KVDIM   (HKV * HD)        // 1024

// ---------------------------------------------------------------------------
// Scratch (__device__ globals)
// ---------------------------------------------------------------------------
__device__ __half g_xh[(size_t)MROWS * DIMN];
__device__ __half g_xl[(size_t)MROWS * DIMN];
__device__ __half g_qh[(size_t)MROWS * DIMN];
__device__ __half g_kh[(size_t)MROWS * KVDIM];
__device__ __half g_kl[(size_t)MROWS * KVDIM];
__device__ __half g_vh[(size_t)MROWS * KVDIM];
__device__ __half g_ah[(size_t)MROWS * DIMN];
__device__ __half g_wqT[(size_t)DIMN * DIMN];
__device__ __half g_woT[(size_t)DIMN * DIMN];
__device__ __half g_wkT[(size_t)KVDIM * DIMN];
__device__ __half g_wvT[(size_t)KVDIM * DIMN];

// ---------------------------------------------------------------------------
// PTX helpers
// ---------------------------------------------------------------------------
__device__ __forceinline__ uint32_t smem_u32(const void* p) {
    return (uint32_t)__cvta_generic_to_shared(p);
}
__device__ __forceinline__ void ldsm4(uint32_t* r, uint32_t addr) {
    asm volatile("ldmatrix.sync.aligned.m8n8.x4.shared.b16 {%0,%1,%2,%3}, [%4];"
                 : "=r"(r[0]), "=r"(r[1]), "=r"(r[2]), "=r"(r[3]) : "r"(addr));
}
__device__ __forceinline__ void ldsm4t(uint32_t* r, uint32_t addr) {
    asm volatile("ldmatrix.sync.aligned.m8n8.x4.trans.shared.b16 {%0,%1,%2,%3}, [%4];"
                 : "=r"(r[0]), "=r"(r[1]), "=r"(r[2]), "=r"(r[3]) : "r"(addr));
}
__device__ __forceinline__ void mma_f16(float* d, const uint32_t* a,
                                        const uint32_t b0, const uint32_t b1) {
    asm volatile(
        "mma.sync.aligned.m16n8k16.row.col.f32.f16.f16.f32 "
        "{%0,%1,%2,%3}, {%4,%5,%6,%7}, {%8,%9}, {%0,%1,%2,%3};"
        : "+f"(d[0]), "+f"(d[1]), "+f"(d[2]), "+f"(d[3])
        : "r"(a[0]), "r"(a[1]), "r"(a[2]), "r"(a[3]), "r"(b0), "r"(b1));
}
__device__ __forceinline__ uint32_t pack_h2(float a, float b) {
    __half2 t = __floats2half2_rn(a, b);
    return *(uint32_t*)&t;
}
__device__ __forceinline__ float h_res(float v) {
    return v - __half2float(__float2half_rn(v));
}

// ---------------------------------------------------------------------------
// GEMM common: K-chunk 64, 2-stage pipeline.
// Smem row: 64 halves + 8 pad = 144 B (conflict-free ldsm across 8 rows).
// ---------------------------------------------------------------------------
constexpr int CK     = 64;
constexpr int PADW   = 72;                    // halves per smem row
constexpr int PLANE  = 128 * PADW * 2;        // 18432 B
constexpr int GNS    = 2;

__device__ __forceinline__ void prefetch_rt(
    const __half* Ah, const __half* Al, const __half* Bh, int nterms,
    int K, int mtile, int ntile, int k0, uint32_t tbase, int tid)
{
    const int tot = (nterms + 1) * 1024;
    for (int u = tid; u < tot; u += 256) {
        int plane = u >> 10;
        int r = (u >> 3) & 127;
        int seg = u & 7;
        const __half* src;
        if (plane == 0)                     src = Ah + (size_t)(mtile + r) * K + k0 + seg * 8;
        else if (nterms == 2 && plane == 1) src = Al + (size_t)(mtile + r) * K + k0 + seg * 8;
        else                                src = Bh + (size_t)(ntile + r) * K + k0 + seg * 8;
        uint32_t dst = tbase + plane * PLANE + r * (PADW * 2) + seg * 16;
        asm volatile("cp.async.cg.shared.global [%0], [%1], 16;"
                     :: "r"(dst), "l"(src) : "memory");
    }
}

// ---------------------------------------------------------------------------
// Merged Q|K|V projection GEMM. grid.x = 48 column tiles:
//   [0,32): q (1-term, out qh), [32,40): k (2-term, out kh+kl), [40,48): v (1-term)
// ---------------------------------------------------------------------------
constexpr int QKV_SMEM = GNS * 3 * PLANE;   // 110592 (max: 2-term stage)

__global__ __launch_bounds__(256, 2) void gemm_qkv(
    const __half* __restrict__ xh, const __half* __restrict__ xl,
    const __half* __restrict__ wqT, const __half* __restrict__ wkT,
    const __half* __restrict__ wvT,
    __half* __restrict__ qh, __half* __restrict__ kh,
    __half* __restrict__ kl, __half* __restrict__ vh)
{
    extern __shared__ char smem[];
    const uint32_t sbase = smem_u32(smem);

    const int tid = threadIdx.x;
    const int wid = tid >> 5, lane = tid & 31;
    const int wm = wid >> 2;
    const int wn = wid & 3;
    const int mtile = blockIdx.y * 128;
    const int nx = blockIdx.x;
    const int K = DIMN;
    const int nch = K / CK;   // 64

    const __half* B;
    __half *Oh, *Ol;
    int ntile, Nout, nterms;
    if (nx < 32)      { B = wqT; Oh = qh; Ol = nullptr; ntile = nx * 128;        Nout = DIMN;  nterms = 1; }
    else if (nx < 40) { B = wkT; Oh = kh; Ol = kl;      ntile = (nx - 32) * 128; Nout = KVDIM; nterms = 2; }
    else              { B = wvT; Oh = vh; Ol = nullptr; ntile = (nx - 40) * 128; Nout = KVDIM; nterms = 1; }
    const int STG = (nterms + 1) * PLANE;

    float acc[4][4][4];
    #pragma unroll
    for (int mi = 0; mi < 4; mi++)
        #pragma unroll
        for (int ni = 0; ni < 4; ni++)
            #pragma unroll
            for (int e = 0; e < 4; e++) acc[mi][ni][e] = 0.f;

    const int a_row_in16 = (lane & 7) + ((lane >> 3) & 1) * 8;
    const int a_colb     = (lane >> 4) * 16;
    const int b_row_in16 = (lane & 7) + ((lane >> 4) & 1) * 8;
    const int b_colb     = ((lane >> 3) & 1) * 16;

    for (int i = 0; i < GNS; i++) {
        prefetch_rt(xh, xl, B, nterms, K, mtile, ntile, i * CK, sbase + i * STG, tid);
        asm volatile("cp.async.commit_group;" ::: "memory");
    }

    for (int i = 0; i < nch; i++) {
        const int s = i % GNS;
        const uint32_t tb = sbase + s * STG;
        asm volatile("cp.async.wait_group %0;" :: "n"(GNS - 1) : "memory");
        __syncthreads();

        const uint32_t aH = tb;
        const uint32_t aL = tb + PLANE;
        const uint32_t bH = tb + nterms * PLANE;

        #pragma unroll
        for (int ks = 0; ks < 4; ks++) {
            const int kb = ks * 32;
            uint32_t fB[2][4];
            #pragma unroll
            for (int ng = 0; ng < 2; ng++) {
                int row = wn * 32 + ng * 16 + b_row_in16;
                ldsm4(fB[ng], bH + row * (PADW * 2) + b_colb + kb);
            }
            uint32_t fA[4][4];
            #pragma unroll
            for (int mi = 0; mi < 4; mi++) {
                int row = wm * 64 + mi * 16 + a_row_in16;
                ldsm4(fA[mi], aH + row * (PADW * 2) + a_colb + kb);
            }
            #pragma unroll
            for (int mi = 0; mi < 4; mi++)
                #pragma unroll
                for (int ni = 0; ni < 4; ni++) {
                    const int ng = ni >> 1, hf = (ni & 1) * 2;
                    mma_f16(acc[mi][ni], fA[mi], fB[ng][hf], fB[ng][hf + 1]);
                }
            if (nterms == 2) {
                #pragma unroll
                for (int mi = 0; mi < 4; mi++) {
                    int row = wm * 64 + mi * 16 + a_row_in16;
                    ldsm4(fA[mi], aL + row * (PADW * 2) + a_colb + kb);
                }
                #pragma unroll
                for (int mi = 0; mi < 4; mi++)
                    #pragma unroll
                    for (int ni = 0; ni < 4; ni++) {
                        const int ng = ni >> 1, hf = (ni & 1) * 2;
                        mma_f16(acc[mi][ni], fA[mi], fB[ng][hf], fB[ng][hf + 1]);
                    }
            }
        }
        __syncthreads();

        if (i + GNS < nch)
            prefetch_rt(xh, xl, B, nterms, K, mtile, ntile, (i + GNS) * CK,
                        sbase + s * STG, tid);
        asm volatile("cp.async.commit_group;" ::: "memory");
    }

    const int r0b = mtile + wm * 64 + (lane >> 2);
    const int c0b = ntile + wn * 32 + (lane & 3) * 2;
    #pragma unroll
    for (int mi = 0; mi < 4; mi++) {
        #pragma unroll
        for (int ni = 0; ni < 4; ni++) {
            size_t o0 = (size_t)(r0b + mi * 16) * Nout + c0b + ni * 8;
            size_t o1 = (size_t)(r0b + mi * 16 + 8) * Nout + c0b + ni * 8;
            float v0 = acc[mi][ni][0], v1 = acc[mi][ni][1];
            float v2 = acc[mi][ni][2], v3 = acc[mi][ni][3];
            *(uint32_t*)(Oh + o0) = pack_h2(v0, v1);
            *(uint32_t*)(Oh + o1) = pack_h2(v2, v3);
            if (Ol != nullptr) {
                *(uint32_t*)(Ol + o0) = pack_h2(h_res(v0), h_res(v1));
                *(uint32_t*)(Ol + o1) = pack_h2(h_res(v2), h_res(v3));
            }
        }
    }
}

// ---------------------------------------------------------------------------
// wo GEMM: C[M,N] = A[M,K] @ B[N,K]^T, 1-term, fp32 out.
// ---------------------------------------------------------------------------
constexpr int WO_SMEM = GNS * 2 * PLANE;   // 73728

__global__ __launch_bounds__(256, 2) void gemm_wo(
    int M, int N, int K,
    const __half* __restrict__ Ah, const __half* __restrict__ Bh,
    float* __restrict__ C)
{
    constexpr int STG = 2 * PLANE;
    extern __shared__ char smem[];
    const uint32_t sbase = smem_u32(smem);

    const int tid = threadIdx.x;
    const int wid = tid >> 5, lane = tid & 31;
    const int wm = wid >> 2;
    const int wn = wid & 3;
    const int mtile = blockIdx.y * 128;
    const int ntile = blockIdx.x * 128;
    const int nch = K / CK;

    float acc[4][4][4];
    #pragma unroll
    for (int mi = 0; mi < 4; mi++)
        #pragma unroll
        for (int ni = 0; ni < 4; ni++)
            #pragma unroll
            for (int e = 0; e < 4; e++) acc[mi][ni][e] = 0.f;

    const int a_row_in16 = (lane & 7) + ((lane >> 3) & 1) * 8;
    const int a_colb     = (lane >> 4) * 16;
    const int b_row_in16 = (lane & 7) + ((lane >> 4) & 1) * 8;
    const int b_colb     = ((lane >> 3) & 1) * 16;

    for (int i = 0; i < GNS; i++) {
        prefetch_rt(Ah, nullptr, Bh, 1, K, mtile, ntile, i * CK, sbase + i * STG, tid);
        asm volatile("cp.async.commit_group;" ::: "memory");
    }

    for (int i = 0; i < nch; i++) {
        const int s = i % GNS;
        const uint32_t tb = sbase + s * STG;
        asm volatile("cp.async.wait_group %0;" :: "n"(GNS - 1) : "memory");
        __syncthreads();

        const uint32_t aH = tb;
        const uint32_t bH = tb + PLANE;

        #pragma unroll
        for (int ks = 0; ks < 4; ks++) {
            const int kb = ks * 32;
            uint32_t fB[2][4];
            #pragma unroll
            for (int ng = 0; ng < 2; ng++) {
                int row = wn * 32 + ng * 16 + b_row_in16;
                ldsm4(fB[ng], bH + row * (PADW * 2) + b_colb + kb);
            }
            uint32_t fA[4][4];
            #pragma unroll
            for (int mi = 0; mi < 4; mi++) {
                int row = wm * 64 + mi * 16 + a_row_in16;
                ldsm4(fA[mi], aH + row * (PADW * 2) + a_colb + kb);
            }
            #pragma unroll
            for (int mi = 0; mi < 4; mi++)
                #pragma unroll
                for (int ni = 0; ni < 4; ni++) {
                    const int ng = ni >> 1, hf = (ni & 1) * 2;
                    mma_f16(acc[mi][ni], fA[mi], fB[ng][hf], fB[ng][hf + 1]);
                }
        }
        __syncthreads();

        if (i + GNS < nch)
            prefetch_rt(Ah, nullptr, Bh, 1, K, mtile, ntile, (i + GNS) * CK,
                        sbase + s * STG, tid);
        asm volatile("cp.async.commit_group;" ::: "memory");
    }

    const int r0b = mtile + wm * 64 + (lane >> 2);
    const int c0b = ntile + wn * 32 + (lane & 3) * 2;
    #pragma unroll
    for (int mi = 0; mi < 4; mi++) {
        #pragma unroll
        for (int ni = 0; ni < 4; ni++) {
            size_t o0 = (size_t)(r0b + mi * 16) * N + c0b + ni * 8;
            size_t o1 = (size_t)(r0b + mi * 16 + 8) * N + c0b + ni * 8;
            *(float2*)(C + o0) = make_float2(acc[mi][ni][0], acc[mi][ni][1]);
            *(float2*)(C + o1) = make_float2(acc[mi][ni][2], acc[mi][ni][3]);
        }
    }
}

// ---------------------------------------------------------------------------
// Conversions
// ---------------------------------------------------------------------------
__global__ void conv_pair(const float* __restrict__ in,
                          __half* __restrict__ hi, __half* __restrict__ lo, int n8)
{
    int i = blockIdx.x * blockDim.x + threadIdx.x;
    if (i >= n8) return;
    float4 v0 = ((const float4*)in)[2 * i];
    float4 v1 = ((const float4*)in)[2 * i + 1];
    uint4 h, l;
    h.x = pack_h2(v0.x, v0.y);  h.y = pack_h2(v0.z, v0.w);
    h.z = pack_h2(v1.x, v1.y);  h.w = pack_h2(v1.z, v1.w);
    l.x = pack_h2(h_res(v0.x), h_res(v0.y));
    l.y = pack_h2(h_res(v0.z), h_res(v0.w));
    l.z = pack_h2(h_res(v1.x), h_res(v1.y));
    l.w = pack_h2(h_res(v1.z), h_res(v1.w));
    ((uint4*)hi)[i] = h;
    ((uint4*)lo)[i] = l;
}

// Merged weight transpose: flat grid.x segments
//   [0,128): wq  [128,160): wk  [160,192): wv  [192,320): wo
__global__ void convT_all(const float* __restrict__ wq, const float* __restrict__ wk,
                          const float* __restrict__ wv, const float* __restrict__ wo,
                          __half* __restrict__ wqT, __half* __restrict__ wkT,
                          __half* __restrict__ wvT, __half* __restrict__ woT)
{
    __shared__ float t[32][33];
    const int gx = blockIdx.x;
    const float* W;
    __half* Th;
    int n0, N;
    if (gx < 128)      { W = wq; Th = wqT; n0 = gx * 32;         N = DIMN; }
    else if (gx < 160) { W = wk; Th = wkT; n0 = (gx - 128) * 32; N = KVDIM; }
    else if (gx < 192) { W = wv; Th = wvT; n0 = (gx - 160) * 32; N = KVDIM; }
    else               { W = wo; Th = woT; n0 = (gx - 192) * 32; N = DIMN; }
    const int K = DIMN;
    int k0 = blockIdx.y * 32;
    int tx = threadIdx.x, ty0 = threadIdx.y;
    #pragma unroll
    for (int j = 0; j < 4; j++) {
        int ty = ty0 + 8 * j;
        t[ty][tx] = W[(size_t)(k0 + ty) * N + n0 + tx];
    }
    __syncthreads();
    #pragma unroll
    for (int j = 0; j < 4; j++) {
        int ty = ty0 + 8 * j;
        Th[(size_t)(n0 + ty) * K + k0 + tx] = __float2half_rn(t[tx][ty]);
    }
}

// ---------------------------------------------------------------------------
// fp16 flash attention: S = q @ (Kh+Kl)^T, O = P @ V (1-term PV), causal GQA.
// CTA: 128 q rows, 8 warps. K tiles of 64, double-buffered. bx reversed.
// ---------------------------------------------------------------------------
constexpr int FB_STRIDE_B = 272;
constexpr int FPLANE  = 64 * FB_STRIDE_B;      // 17408
constexpr int QPLANE  = 128 * FB_STRIDE_B;     // 34816
constexpr int FATTN_SMEM = QPLANE + 6 * FPLANE;  // 139264

__global__ __launch_bounds__(256) void fattn_kernel(
    const __half* __restrict__ Qh_g,
    const __half* __restrict__ Kh_g, const __half* __restrict__ Kl_g,
    const __half* __restrict__ Vh_g,
    __half* __restrict__ Oh_g)
{
    extern __shared__ char smem[];
    const uint32_t sb = smem_u32(smem);
    const uint32_t sQh = sb;
    const uint32_t kvstart = sb + QPLANE;

    const int tid = threadIdx.x, wid = tid >> 5, lane = tid & 31;
    const int bx = gridDim.x - 1 - blockIdx.x;
    const int h = blockIdx.y, b = blockIdx.z;
    const int q0 = bx * 128;
    const int kvh = h >> 2;

    const __half* qh = Qh_g + ((size_t)(b * S_LEN + q0)) * DIMN + h * HD;
    const __half* kh = Kh_g + ((size_t)(b * S_LEN)) * KVDIM + kvh * HD;
    const __half* kl = Kl_g + ((size_t)(b * S_LEN)) * KVDIM + kvh * HD;
    const __half* vh = Vh_g + ((size_t)(b * S_LEN)) * KVDIM + kvh * HD;

    auto load_kv = [&](int kt0, int s) {
        const uint32_t base = kvstart + 3 * s * FPLANE;
        #pragma unroll
        for (int u = tid; u < 3072; u += 256) {
            int plane = u >> 10, r = (u >> 4) & 63, seg = u & 15;
            const __half* src;
            if (plane == 0)      src = kh;
            else if (plane == 1) src = kl;
            else                 src = vh;
            src += (size_t)(kt0 + r) * KVDIM + seg * 8;
            uint32_t dst = base + plane * FPLANE + r * FB_STRIDE_B + seg * 16;
            asm volatile("cp.async.cg.shared.global [%0], [%1], 16;"
                         :: "r"(dst), "l"(src) : "memory");
        }
    };

    #pragma unroll
    for (int u = tid; u < 2048; u += 256) {
        int r = (u >> 4) & 127, seg = u & 15;
        const __half* src = qh + (size_t)r * DIMN + seg * 8;
        uint32_t dst = sQh + r * FB_STRIDE_B + seg * 16;
        asm volatile("cp.async.cg.shared.global [%0], [%1], 16;"
                     :: "r"(dst), "l"(src) : "memory");
    }
    load_kv(0, 0);
    asm volatile("cp.async.commit_group;" ::: "memory");

    float accO[16][4];
    #pragma unroll
    for (int t = 0; t < 16; t++)
        #pragma unroll
        for (int e = 0; e < 4; e++) accO[t][e] = 0.f;
    float m0 = -1e30f, m1 = -1e30f, l0 = 0.f, l1 = 0.f;

    const int a_r  = (lane & 7) + ((lane >> 3) & 1) * 8;
    const int a_cb = (lane >> 4) * 16;
    const int b_r  = (lane & 7) + ((lane >> 4) & 1) * 8;
    const int b_cb = ((lane >> 3) & 1) * 16;

    const float SL = 0.08838834764831845f * 1.4426950408889634f;

    const int n_tiles = 2 * bx + 2;
    for (int t = 0; t < n_tiles; t++) {
        const int kt0 = t * 64;
        const int cur = t & 1;
        if (t < n_tiles - 1) {
            load_kv((t + 1) * 64, cur ^ 1);
            asm volatile("cp.async.commit_group;" ::: "memory");
            asm volatile("cp.async.wait_group 1;" ::: "memory");
        } else {
            asm volatile("cp.async.wait_group 0;" ::: "memory");
        }
        __syncthreads();

        const bool active = !(t == n_tiles - 1 && wid < 4);

        if (active) {
            const uint32_t kvb = kvstart + 3 * cur * FPLANE;
            const uint32_t sKh = kvb, sKl = kvb + FPLANE, sVh = kvb + 2 * FPLANE;

            float accS[8][4];
            #pragma unroll
            for (int ni = 0; ni < 8; ni++)
                #pragma unroll
                for (int e = 0; e < 4; e++) accS[ni][e] = 0.f;

            #pragma unroll
            for (int kk = 0; kk < 8; kk++) {
                uint32_t fQ[4];
                uint32_t aaddr = (wid * 16 + a_r) * FB_STRIDE_B + kk * 32 + a_cb;
                ldsm4(fQ, sQh + aaddr);
                #pragma unroll
                for (int ng = 0; ng < 4; ng++) {
                    uint32_t baddr = (ng * 16 + b_r) * FB_STRIDE_B + kk * 32 + b_cb;
                    uint32_t fKh[4], fKl[4];
                    ldsm4(fKh, sKh + baddr);
                    ldsm4(fKl, sKl + baddr);
                    #pragma unroll
                    for (int hf2 = 0; hf2 < 2; hf2++) {
                        const int ni = ng * 2 + hf2;
                        mma_f16(accS[ni], fQ, fKh[hf2 * 2], fKh[hf2 * 2 + 1]);
                        mma_f16(accS[ni], fQ, fKl[hf2 * 2], fKl[hf2 * 2 + 1]);
                    }
                }
            }

            #pragma unroll
            for (int ni = 0; ni < 8; ni++)
                #pragma unroll
                for (int e = 0; e < 4; e++) accS[ni][e] *= SL;

            if (t >= n_tiles - 2) {
                const int r0 = q0 + wid * 16 + (lane >> 2);
                #pragma unroll
                for (int ni = 0; ni < 8; ni++) {
                    int c = kt0 + ni * 8 + (lane & 3) * 2;
                    if (c > r0)     accS[ni][0] = -1e30f;
                    if (c + 1 > r0) accS[ni][1] = -1e30f;
                    if (c > r0 + 8)     accS[ni][2] = -1e30f;
                    if (c + 1 > r0 + 8) accS[ni][3] = -1e30f;
                }
            }

            float mx0 = -1e30f, mx1 = -1e30f;
            #pragma unroll
            for (int ni = 0; ni < 8; ni++) {
                mx0 = fmaxf(mx0, fmaxf(accS[ni][0], accS[ni][1]));
                mx1 = fmaxf(mx1, fmaxf(accS[ni][2], accS[ni][3]));
            }
            mx0 = fmaxf(mx0, __shfl_xor_sync(0xffffffffu, mx0, 1));
            mx0 = fmaxf(mx0, __shfl_xor_sync(0xffffffffu, mx0, 2));
            mx1 = fmaxf(mx1, __shfl_xor_sync(0xffffffffu, mx1, 1));
            mx1 = fmaxf(mx1, __shfl_xor_sync(0xffffffffu, mx1, 2));

            const float mn0 = fmaxf(m0, mx0), mn1 = fmaxf(m1, mx1);
            const float al0 = exp2f(m0 - mn0), al1 = exp2f(m1 - mn1);
            m0 = mn0; m1 = mn1;

            uint32_t phA[8], phB[8];
            float s0 = 0.f, s1 = 0.f;
            #pragma unroll
            for (int ni = 0; ni < 8; ni++) {
                float p0 = exp2f(accS[ni][0] - mn0);
                float p1 = exp2f(accS[ni][1] - mn0);
                float p2 = exp2f(accS[ni][2] - mn1);
                float p3 = exp2f(accS[ni][3] - mn1);
                s0 += p0 + p1; s1 += p2 + p3;
                phA[ni] = pack_h2(p0, p1);
                phB[ni] = pack_h2(p2, p3);
            }
            s0 += __shfl_xor_sync(0xffffffffu, s0, 1);
            s0 += __shfl_xor_sync(0xffffffffu, s0, 2);
            s1 += __shfl_xor_sync(0xffffffffu, s1, 1);
            s1 += __shfl_xor_sync(0xffffffffu, s1, 2);
            l0 = l0 * al0 + s0;
            l1 = l1 * al1 + s1;

            #pragma unroll
            for (int ti = 0; ti < 16; ti++) {
                accO[ti][0] *= al0; accO[ti][1] *= al0;
                accO[ti][2] *= al1; accO[ti][3] *= al1;
            }

            #pragma unroll
            for (int j = 0; j < 4; j++) {
                uint32_t aPh[4] = { phA[2*j], phB[2*j], phA[2*j+1], phB[2*j+1] };
                #pragma unroll
                for (int dg = 0; dg < 8; dg++) {
                    uint32_t vaddr = (j * 16 + (lane & 15)) * FB_STRIDE_B
                                   + dg * 32 + (lane >> 4) * 16;
                    uint32_t fVh[4];
                    ldsm4t(fVh, sVh + vaddr);
                    mma_f16(accO[dg * 2],     aPh, fVh[0], fVh[1]);
                    mma_f16(accO[dg * 2 + 1], aPh, fVh[2], fVh[3]);
                }
            }
        }
        __syncthreads();
    }

    const float inv0 = 1.0f / l0, inv1 = 1.0f / l1;
    const size_t row0 = (size_t)(b * S_LEN + q0 + wid * 16 + (lane >> 2));
    const size_t row1 = row0 + 8;
    __half* oh0 = Oh_g + row0 * DIMN + h * HD;
    __half* oh1 = Oh_g + row1 * DIMN + h * HD;
    #pragma unroll
    for (int ti = 0; ti < 16; ti++) {
        int c = ti * 8 + (lane & 3) * 2;
        *(uint32_t*)(oh0 + c) = pack_h2(accO[ti][0] * inv0, accO[ti][1] * inv0);
        *(uint32_t*)(oh1 + c) = pack_h2(accO[ti][2] * inv1, accO[ti][3] * inv1);
    }
}

// ---------------------------------------------------------------------------
// Launch
// ---------------------------------------------------------------------------
extern "C" void kernel_launch(void* const* d_in, const int* in_sizes, int n_in,
                              void* d_out, int out_size)
{
    const float* x  = (const float*)d_in[0];
    const float* wq = (const float*)d_in[1];
    const float* wk = (const float*)d_in[2];
    const float* wv = (const float*)d_in[3];
    const float* wo = (const float*)d_in[4];
    float* out = (float*)d_out;

    __half *xh, *xl, *qh, *kh, *kl, *vh, *ah;
    __half *wqT, *wkT, *wvT, *woT;
    cudaGetSymbolAddress((void**)&xh, g_xh);   cudaGetSymbolAddress((void**)&xl, g_xl);
    cudaGetSymbolAddress((void**)&qh, g_qh);
    cudaGetSymbolAddress((void**)&kh, g_kh);   cudaGetSymbolAddress((void**)&kl, g_kl);
    cudaGetSymbolAddress((void**)&vh, g_vh);
    cudaGetSymbolAddress((void**)&ah, g_ah);
    cudaGetSymbolAddress((void**)&wqT, g_wqT); cudaGetSymbolAddress((void**)&wkT, g_wkT);
    cudaGetSymbolAddress((void**)&wvT, g_wvT); cudaGetSymbolAddress((void**)&woT, g_woT);

    cudaFuncSetAttribute(gemm_qkv,
                         cudaFuncAttributeMaxDynamicSharedMemorySize, QKV_SMEM);
    cudaFuncSetAttribute(gemm_wo,
                         cudaFuncAttributeMaxDynamicSharedMemorySize, WO_SMEM);
    cudaFuncSetAttribute(fattn_kernel,
                         cudaFuncAttributeMaxDynamicSharedMemorySize, FATTN_SMEM);

    int n8x = MROWS * DIMN / 8;
    conv_pair<<<(n8x + 255) / 256, 256>>>(x, xh, xl, n8x);
    convT_all<<<dim3(320, DIMN / 32), dim3(32, 8)>>>(
        wq, wk, wv, wo, wqT, wkT, wvT, woT);

    gemm_qkv<<<dim3(48, MROWS / 128), 256, QKV_SMEM>>>(
        xh, xl, wqT, wkT, wvT, qh, kh, kl, vh);

    fattn_kernel<<<dim3(S_LEN / 128, HQ, BATCH), 256, FATTN_SMEM>>>(
        qh, kh, kl, vh, ah);

    gemm_wo<<<dim3(DIMN / 128, MROWS / 128), 256, WO_SMEM>>>(
        MROWS, DIMN, DIMN, ah, woT, out);
}

// round 12
// speedup vs baseline: 8.2951x; 1.0404x over previous
#include <cuda_runtime.h>
#include <cuda_fp16.h>
#include <cstdint>

// Problem constants
#define DIMN    4096
#define S_LEN   2048
#define BATCH   2
#define HQ      32
#define HKV     8
#define NREP    4
#define HD      128
#define MROWS   (BATCH * S_LEN)   // 4096
#define KVDIM   (HKV * HD)        // 1024

// ---------------------------------------------------------------------------
// Scratch (__device__ globals)
// ---------------------------------------------------------------------------
__device__ __half g_xh[(size_t)MROWS * DIMN];
__device__ __half g_xl[(size_t)MROWS * DIMN];
__device__ __half g_qh[(size_t)MROWS * DIMN];
__device__ __half g_kh[(size_t)MROWS * KVDIM];
__device__ __half g_kl[(size_t)MROWS * KVDIM];
__device__ __half g_vh[(size_t)MROWS * KVDIM];
__device__ __half g_ah[(size_t)MROWS * DIMN];
__device__ __half g_wqT[(size_t)DIMN * DIMN];
__device__ __half g_woT[(size_t)DIMN * DIMN];
__device__ __half g_wkT[(size_t)KVDIM * DIMN];
__device__ __half g_wvT[(size_t)KVDIM * DIMN];

// ---------------------------------------------------------------------------
// PTX helpers
// ---------------------------------------------------------------------------
__device__ __forceinline__ uint32_t smem_u32(const void* p) {
    return (uint32_t)__cvta_generic_to_shared(p);
}
__device__ __forceinline__ void ldsm4(uint32_t* r, uint32_t addr) {
    asm volatile("ldmatrix.sync.aligned.m8n8.x4.shared.b16 {%0,%1,%2,%3}, [%4];"
                 : "=r"(r[0]), "=r"(r[1]), "=r"(r[2]), "=r"(r[3]) : "r"(addr));
}
__device__ __forceinline__ void ldsm4t(uint32_t* r, uint32_t addr) {
    asm volatile("ldmatrix.sync.aligned.m8n8.x4.trans.shared.b16 {%0,%1,%2,%3}, [%4];"
                 : "=r"(r[0]), "=r"(r[1]), "=r"(r[2]), "=r"(r[3]) : "r"(addr));
}
__device__ __forceinline__ void mma_f16(float* d, const uint32_t* a,
                                        const uint32_t b0, const uint32_t b1) {
    asm volatile(
        "mma.sync.aligned.m16n8k16.row.col.f32.f16.f16.f32 "
        "{%0,%1,%2,%3}, {%4,%5,%6,%7}, {%8,%9}, {%0,%1,%2,%3};"
        : "+f"(d[0]), "+f"(d[1]), "+f"(d[2]), "+f"(d[3])
        : "r"(a[0]), "r"(a[1]), "r"(a[2]), "r"(a[3]), "r"(b0), "r"(b1));
}
__device__ __forceinline__ uint32_t pack_h2(float a, float b) {
    __half2 t = __floats2half2_rn(a, b);
    return *(uint32_t*)&t;
}
__device__ __forceinline__ float h_res(float v) {
    return v - __half2float(__float2half_rn(v));
}

// ---------------------------------------------------------------------------
// GEMM common: K-chunk 64, 2-stage pipeline. (unchanged from R11)
// ---------------------------------------------------------------------------
constexpr int CK     = 64;
constexpr int PADW   = 72;
constexpr int PLANE  = 128 * PADW * 2;        // 18432 B
constexpr int GNS    = 2;

__device__ __forceinline__ void prefetch_rt(
    const __half* Ah, const __half* Al, const __half* Bh, int nterms,
    int K, int mtile, int ntile, int k0, uint32_t tbase, int tid)
{
    const int tot = (nterms + 1) * 1024;
    for (int u = tid; u < tot; u += 256) {
        int plane = u >> 10;
        int r = (u >> 3) & 127;
        int seg = u & 7;
        const __half* src;
        if (plane == 0)                     src = Ah + (size_t)(mtile + r) * K + k0 + seg * 8;
        else if (nterms == 2 && plane == 1) src = Al + (size_t)(mtile + r) * K + k0 + seg * 8;
        else                                src = Bh + (size_t)(ntile + r) * K + k0 + seg * 8;
        uint32_t dst = tbase + plane * PLANE + r * (PADW * 2) + seg * 16;
        asm volatile("cp.async.cg.shared.global [%0], [%1], 16;"
                     :: "r"(dst), "l"(src) : "memory");
    }
}

constexpr int QKV_SMEM = GNS * 3 * PLANE;   // 110592

__global__ __launch_bounds__(256, 2) void gemm_qkv(
    const __half* __restrict__ xh, const __half* __restrict__ xl,
    const __half* __restrict__ wqT, const __half* __restrict__ wkT,
    const __half* __restrict__ wvT,
    __half* __restrict__ qh, __half* __restrict__ kh,
    __half* __restrict__ kl, __half* __restrict__ vh)
{
    extern __shared__ char smem[];
    const uint32_t sbase = smem_u32(smem);

    const int tid = threadIdx.x;
    const int wid = tid >> 5, lane = tid & 31;
    const int wm = wid >> 2;
    const int wn = wid & 3;
    const int mtile = blockIdx.y * 128;
    const int nx = blockIdx.x;
    const int K = DIMN;
    const int nch = K / CK;

    const __half* B;
    __half *Oh, *Ol;
    int ntile, Nout, nterms;
    if (nx < 32)      { B = wqT; Oh = qh; Ol = nullptr; ntile = nx * 128;        Nout = DIMN;  nterms = 1; }
    else if (nx < 40) { B = wkT; Oh = kh; Ol = kl;      ntile = (nx - 32) * 128; Nout = KVDIM; nterms = 2; }
    else              { B = wvT; Oh = vh; Ol = nullptr; ntile = (nx - 40) * 128; Nout = KVDIM; nterms = 1; }
    const int STG = (nterms + 1) * PLANE;

    float acc[4][4][4];
    #pragma unroll
    for (int mi = 0; mi < 4; mi++)
        #pragma unroll
        for (int ni = 0; ni < 4; ni++)
            #pragma unroll
            for (int e = 0; e < 4; e++) acc[mi][ni][e] = 0.f;

    const int a_row_in16 = (lane & 7) + ((lane >> 3) & 1) * 8;
    const int a_colb     = (lane >> 4) * 16;
    const int b_row_in16 = (lane & 7) + ((lane >> 4) & 1) * 8;
    const int b_colb     = ((lane >> 3) & 1) * 16;

    for (int i = 0; i < GNS; i++) {
        prefetch_rt(xh, xl, B, nterms, K, mtile, ntile, i * CK, sbase + i * STG, tid);
        asm volatile("cp.async.commit_group;" ::: "memory");
    }

    for (int i = 0; i < nch; i++) {
        const int s = i % GNS;
        const uint32_t tb = sbase + s * STG;
        asm volatile("cp.async.wait_group %0;" :: "n"(GNS - 1) : "memory");
        __syncthreads();

        const uint32_t aH = tb;
        const uint32_t aL = tb + PLANE;
        const uint32_t bH = tb + nterms * PLANE;

        #pragma unroll
        for (int ks = 0; ks < 4; ks++) {
            const int kb = ks * 32;
            uint32_t fB[2][4];
            #pragma unroll
            for (int ng = 0; ng < 2; ng++) {
                int row = wn * 32 + ng * 16 + b_row_in16;
                ldsm4(fB[ng], bH + row * (PADW * 2) + b_colb + kb);
            }
            uint32_t fA[4][4];
            #pragma unroll
            for (int mi = 0; mi < 4; mi++) {
                int row = wm * 64 + mi * 16 + a_row_in16;
                ldsm4(fA[mi], aH + row * (PADW * 2) + a_colb + kb);
            }
            #pragma unroll
            for (int mi = 0; mi < 4; mi++)
                #pragma unroll
                for (int ni = 0; ni < 4; ni++) {
                    const int ng = ni >> 1, hf = (ni & 1) * 2;
                    mma_f16(acc[mi][ni], fA[mi], fB[ng][hf], fB[ng][hf + 1]);
                }
            if (nterms == 2) {
                #pragma unroll
                for (int mi = 0; mi < 4; mi++) {
                    int row = wm * 64 + mi * 16 + a_row_in16;
                    ldsm4(fA[mi], aL + row * (PADW * 2) + a_colb + kb);
                }
                #pragma unroll
                for (int mi = 0; mi < 4; mi++)
                    #pragma unroll
                    for (int ni = 0; ni < 4; ni++) {
                        const int ng = ni >> 1, hf = (ni & 1) * 2;
                        mma_f16(acc[mi][ni], fA[mi], fB[ng][hf], fB[ng][hf + 1]);
                    }
            }
        }
        __syncthreads();

        if (i + GNS < nch)
            prefetch_rt(xh, xl, B, nterms, K, mtile, ntile, (i + GNS) * CK,
                        sbase + s * STG, tid);
        asm volatile("cp.async.commit_group;" ::: "memory");
    }

    const int r0b = mtile + wm * 64 + (lane >> 2);
    const int c0b = ntile + wn * 32 + (lane & 3) * 2;
    #pragma unroll
    for (int mi = 0; mi < 4; mi++) {
        #pragma unroll
        for (int ni = 0; ni < 4; ni++) {
            size_t o0 = (size_t)(r0b + mi * 16) * Nout + c0b + ni * 8;
            size_t o1 = (size_t)(r0b + mi * 16 + 8) * Nout + c0b + ni * 8;
            float v0 = acc[mi][ni][0], v1 = acc[mi][ni][1];
            float v2 = acc[mi][ni][2], v3 = acc[mi][ni][3];
            *(uint32_t*)(Oh + o0) = pack_h2(v0, v1);
            *(uint32_t*)(Oh + o1) = pack_h2(v2, v3);
            if (Ol != nullptr) {
                *(uint32_t*)(Ol + o0) = pack_h2(h_res(v0), h_res(v1));
                *(uint32_t*)(Ol + o1) = pack_h2(h_res(v2), h_res(v3));
            }
        }
    }
}

constexpr int WO_SMEM = GNS * 2 * PLANE;   // 73728

__global__ __launch_bounds__(256, 2) void gemm_wo(
    int M, int N, int K,
    const __half* __restrict__ Ah, const __half* __restrict__ Bh,
    float* __restrict__ C)
{
    constexpr int STG = 2 * PLANE;
    extern __shared__ char smem[];
    const uint32_t sbase = smem_u32(smem);

    const int tid = threadIdx.x;
    const int wid = tid >> 5, lane = tid & 31;
    const int wm = wid >> 2;
    const int wn = wid & 3;
    const int mtile = blockIdx.y * 128;
    const int ntile = blockIdx.x * 128;
    const int nch = K / CK;

    float acc[4][4][4];
    #pragma unroll
    for (int mi = 0; mi < 4; mi++)
        #pragma unroll
        for (int ni = 0; ni < 4; ni++)
            #pragma unroll
            for (int e = 0; e < 4; e++) acc[mi][ni][e] = 0.f;

    const int a_row_in16 = (lane & 7) + ((lane >> 3) & 1) * 8;
    const int a_colb     = (lane >> 4) * 16;
    const int b_row_in16 = (lane & 7) + ((lane >> 4) & 1) * 8;
    const int b_colb     = ((lane >> 3) & 1) * 16;

    for (int i = 0; i < GNS; i++) {
        prefetch_rt(Ah, nullptr, Bh, 1, K, mtile, ntile, i * CK, sbase + i * STG, tid);
        asm volatile("cp.async.commit_group;" ::: "memory");
    }

    for (int i = 0; i < nch; i++) {
        const int s = i % GNS;
        const uint32_t tb = sbase + s * STG;
        asm volatile("cp.async.wait_group %0;" :: "n"(GNS - 1) : "memory");
        __syncthreads();

        const uint32_t aH = tb;
        const uint32_t bH = tb + PLANE;

        #pragma unroll
        for (int ks = 0; ks < 4; ks++) {
            const int kb = ks * 32;
            uint32_t fB[2][4];
            #pragma unroll
            for (int ng = 0; ng < 2; ng++) {
                int row = wn * 32 + ng * 16 + b_row_in16;
                ldsm4(fB[ng], bH + row * (PADW * 2) + b_colb + kb);
            }
            uint32_t fA[4][4];
            #pragma unroll
            for (int mi = 0; mi < 4; mi++) {
                int row = wm * 64 + mi * 16 + a_row_in16;
                ldsm4(fA[mi], aH + row * (PADW * 2) + a_colb + kb);
            }
            #pragma unroll
            for (int mi = 0; mi < 4; mi++)
                #pragma unroll
                for (int ni = 0; ni < 4; ni++) {
                    const int ng = ni >> 1, hf = (ni & 1) * 2;
                    mma_f16(acc[mi][ni], fA[mi], fB[ng][hf], fB[ng][hf + 1]);
                }
        }
        __syncthreads();

        if (i + GNS < nch)
            prefetch_rt(Ah, nullptr, Bh, 1, K, mtile, ntile, (i + GNS) * CK,
                        sbase + s * STG, tid);
        asm volatile("cp.async.commit_group;" ::: "memory");
    }

    const int r0b = mtile + wm * 64 + (lane >> 2);
    const int c0b = ntile + wn * 32 + (lane & 3) * 2;
    #pragma unroll
    for (int mi = 0; mi < 4; mi++) {
        #pragma unroll
        for (int ni = 0; ni < 4; ni++) {
            size_t o0 = (size_t)(r0b + mi * 16) * N + c0b + ni * 8;
            size_t o1 = (size_t)(r0b + mi * 16 + 8) * N + c0b + ni * 8;
            *(float2*)(C + o0) = make_float2(acc[mi][ni][0], acc[mi][ni][1]);
            *(float2*)(C + o1) = make_float2(acc[mi][ni][2], acc[mi][ni][3]);
        }
    }
}

// ---------------------------------------------------------------------------
// Conversions
// ---------------------------------------------------------------------------
__global__ void conv_pair(const float* __restrict__ in,
                          __half* __restrict__ hi, __half* __restrict__ lo, int n8)
{
    int i = blockIdx.x * blockDim.x + threadIdx.x;
    if (i >= n8) return;
    float4 v0 = ((const float4*)in)[2 * i];
    float4 v1 = ((const float4*)in)[2 * i + 1];
    uint4 h, l;
    h.x = pack_h2(v0.x, v0.y);  h.y = pack_h2(v0.z, v0.w);
    h.z = pack_h2(v1.x, v1.y);  h.w = pack_h2(v1.z, v1.w);
    l.x = pack_h2(h_res(v0.x), h_res(v0.y));
    l.y = pack_h2(h_res(v0.z), h_res(v0.w));
    l.z = pack_h2(h_res(v1.x), h_res(v1.y));
    l.w = pack_h2(h_res(v1.z), h_res(v1.w));
    ((uint4*)hi)[i] = h;
    ((uint4*)lo)[i] = l;
}

__global__ void convT_all(const float* __restrict__ wq, const float* __restrict__ wk,
                          const float* __restrict__ wv, const float* __restrict__ wo,
                          __half* __restrict__ wqT, __half* __restrict__ wkT,
                          __half* __restrict__ wvT, __half* __restrict__ woT)
{
    __shared__ float t[32][33];
    const int gx = blockIdx.x;
    const float* W;
    __half* Th;
    int n0, N;
    if (gx < 128)      { W = wq; Th = wqT; n0 = gx * 32;         N = DIMN; }
    else if (gx < 160) { W = wk; Th = wkT; n0 = (gx - 128) * 32; N = KVDIM; }
    else if (gx < 192) { W = wv; Th = wvT; n0 = (gx - 160) * 32; N = KVDIM; }
    else               { W = wo; Th = woT; n0 = (gx - 192) * 32; N = DIMN; }
    const int K = DIMN;
    int k0 = blockIdx.y * 32;
    int tx = threadIdx.x, ty0 = threadIdx.y;
    #pragma unroll
    for (int j = 0; j < 4; j++) {
        int ty = ty0 + 8 * j;
        t[ty][tx] = W[(size_t)(k0 + ty) * N + n0 + tx];
    }
    __syncthreads();
    #pragma unroll
    for (int j = 0; j < 4; j++) {
        int ty = ty0 + 8 * j;
        Th[(size_t)(n0 + ty) * K + k0 + tx] = __float2half_rn(t[tx][ty]);
    }
}

// ---------------------------------------------------------------------------
// fp16 flash attention: S = q @ (Kh+Kl)^T, O = P @ V, causal GQA.
// CTA: 128 q rows, 8 warps. K tiles of 32, 3-stage cp.async ring.
// smem = Q(34816) + 9 KV planes (9*8704) = 113152 -> 2 CTAs/SM.
// ---------------------------------------------------------------------------
constexpr int FB_STRIDE_B = 272;
constexpr int KT = 32;                          // K-tile rows
constexpr int FPLANE  = KT * FB_STRIDE_B;       // 8704
constexpr int QPLANE  = 128 * FB_STRIDE_B;      // 34816
constexpr int FSTAGES = 3;
constexpr int FATTN_SMEM = QPLANE + FSTAGES * 3 * FPLANE;  // 113152

__global__ __launch_bounds__(256, 2) void fattn_kernel(
    const __half* __restrict__ Qh_g,
    const __half* __restrict__ Kh_g, const __half* __restrict__ Kl_g,
    const __half* __restrict__ Vh_g,
    __half* __restrict__ Oh_g)
{
    extern __shared__ char smem[];
    const uint32_t sb = smem_u32(smem);
    const uint32_t sQh = sb;
    const uint32_t kvstart = sb + QPLANE;

    const int tid = threadIdx.x, wid = tid >> 5, lane = tid & 31;
    const int bx = gridDim.x - 1 - blockIdx.x;
    const int h = blockIdx.y, b = blockIdx.z;
    const int q0 = bx * 128;
    const int kvh = h >> 2;

    const __half* qh = Qh_g + ((size_t)(b * S_LEN + q0)) * DIMN + h * HD;
    const __half* kh = Kh_g + ((size_t)(b * S_LEN)) * KVDIM + kvh * HD;
    const __half* kl = Kl_g + ((size_t)(b * S_LEN)) * KVDIM + kvh * HD;
    const __half* vh = Vh_g + ((size_t)(b * S_LEN)) * KVDIM + kvh * HD;

    auto load_kv = [&](int kt0, int s) {
        const uint32_t base = kvstart + 3 * s * FPLANE;
        #pragma unroll
        for (int u = tid; u < 1536; u += 256) {
            int plane = u / 512, r = (u >> 4) & 31, seg = u & 15;
            const __half* src;
            if (plane == 0)      src = kh;
            else if (plane == 1) src = kl;
            else                 src = vh;
            src += (size_t)(kt0 + r) * KVDIM + seg * 8;
            uint32_t dst = base + plane * FPLANE + r * FB_STRIDE_B + seg * 16;
            asm volatile("cp.async.cg.shared.global [%0], [%1], 16;"
                         :: "r"(dst), "l"(src) : "memory");
        }
    };

    // Prologue: Q + first 2 KV stages
    #pragma unroll
    for (int u = tid; u < 2048; u += 256) {
        int r = (u >> 4) & 127, seg = u & 15;
        const __half* src = qh + (size_t)r * DIMN + seg * 8;
        uint32_t dst = sQh + r * FB_STRIDE_B + seg * 16;
        asm volatile("cp.async.cg.shared.global [%0], [%1], 16;"
                     :: "r"(dst), "l"(src) : "memory");
    }
    load_kv(0, 0);
    asm volatile("cp.async.commit_group;" ::: "memory");
    load_kv(KT, 1);
    asm volatile("cp.async.commit_group;" ::: "memory");

    float accO[16][4];
    #pragma unroll
    for (int t = 0; t < 16; t++)
        #pragma unroll
        for (int e = 0; e < 4; e++) accO[t][e] = 0.f;
    float m0 = -1e30f, m1 = -1e30f, l0 = 0.f, l1 = 0.f;

    const int a_r  = (lane & 7) + ((lane >> 3) & 1) * 8;
    const int a_cb = (lane >> 4) * 16;
    const int b_r  = (lane & 7) + ((lane >> 4) & 1) * 8;
    const int b_cb = ((lane >> 3) & 1) * 16;

    const float SL = 0.08838834764831845f * 1.4426950408889634f;

    const int n_tiles = 4 * bx + 4;
    for (int t = 0; t < n_tiles; t++) {
        const int kt0 = t * KT;
        const int cur = t % FSTAGES;
        // Keep the ring full: load tile t+2 (slot (t+2)%3), then wait for tile t.
        if (t + 2 < n_tiles) load_kv((t + 2) * KT, (t + 2) % FSTAGES);
        asm volatile("cp.async.commit_group;" ::: "memory");
        asm volatile("cp.async.wait_group %0;" :: "n"(2) : "memory");
        __syncthreads();

        // Warp fully masked for this tile?
        const bool active = (kt0 <= q0 + wid * 16 + 15);

        if (active) {
            const uint32_t kvb = kvstart + 3 * cur * FPLANE;
            const uint32_t sKh = kvb, sKl = kvb + FPLANE, sVh = kvb + 2 * FPLANE;

            float accS[4][4];
            #pragma unroll
            for (int ni = 0; ni < 4; ni++)
                #pragma unroll
                for (int e = 0; e < 4; e++) accS[ni][e] = 0.f;

            #pragma unroll
            for (int kk = 0; kk < 8; kk++) {
                uint32_t fQ[4];
                uint32_t aaddr = (wid * 16 + a_r) * FB_STRIDE_B + kk * 32 + a_cb;
                ldsm4(fQ, sQh + aaddr);
                #pragma unroll
                for (int ng = 0; ng < 2; ng++) {
                    uint32_t baddr = (ng * 16 + b_r) * FB_STRIDE_B + kk * 32 + b_cb;
                    uint32_t fKh[4], fKl[4];
                    ldsm4(fKh, sKh + baddr);
                    ldsm4(fKl, sKl + baddr);
                    #pragma unroll
                    for (int hf2 = 0; hf2 < 2; hf2++) {
                        const int ni = ng * 2 + hf2;
                        mma_f16(accS[ni], fQ, fKh[hf2 * 2], fKh[hf2 * 2 + 1]);
                        mma_f16(accS[ni], fQ, fKl[hf2 * 2], fKl[hf2 * 2 + 1]);
                    }
                }
            }

            #pragma unroll
            for (int ni = 0; ni < 4; ni++)
                #pragma unroll
                for (int e = 0; e < 4; e++) accS[ni][e] *= SL;

            if (t >= n_tiles - 4) {   // tiles overlapping the diagonal
                const int r0 = q0 + wid * 16 + (lane >> 2);
                #pragma unroll
                for (int ni = 0; ni < 4; ni++) {
                    int c = kt0 + ni * 8 + (lane & 3) * 2;
                    if (c > r0)     accS[ni][0] = -1e30f;
                    if (c + 1 > r0) accS[ni][1] = -1e30f;
                    if (c > r0 + 8)     accS[ni][2] = -1e30f;
                    if (c + 1 > r0 + 8) accS[ni][3] = -1e30f;
                }
            }

            float mx0 = -1e30f, mx1 = -1e30f;
            #pragma unroll
            for (int ni = 0; ni < 4; ni++) {
                mx0 = fmaxf(mx0, fmaxf(accS[ni][0], accS[ni][1]));
                mx1 = fmaxf(mx1, fmaxf(accS[ni][2], accS[ni][3]));
            }
            mx0 = fmaxf(mx0, __shfl_xor_sync(0xffffffffu, mx0, 1));
            mx0 = fmaxf(mx0, __shfl_xor_sync(0xffffffffu, mx0, 2));
            mx1 = fmaxf(mx1, __shfl_xor_sync(0xffffffffu, mx1, 1));
            mx1 = fmaxf(mx1, __shfl_xor_sync(0xffffffffu, mx1, 2));

            const float mn0 = fmaxf(m0, mx0), mn1 = fmaxf(m1, mx1);
            const float al0 = exp2f(m0 - mn0), al1 = exp2f(m1 - mn1);
            m0 = mn0; m1 = mn1;

            uint32_t phA[4], phB[4];
            float s0 = 0.f, s1 = 0.f;
            #pragma unroll
            for (int ni = 0; ni < 4; ni++) {
                float p0 = exp2f(accS[ni][0] - mn0);
                float p1 = exp2f(accS[ni][1] - mn0);
                float p2 = exp2f(accS[ni][2] - mn1);
                float p3 = exp2f(accS[ni][3] - mn1);
                s0 += p0 + p1; s1 += p2 + p3;
                phA[ni] = pack_h2(p0, p1);
                phB[ni] = pack_h2(p2, p3);
            }
            s0 += __shfl_xor_sync(0xffffffffu, s0, 1);
            s0 += __shfl_xor_sync(0xffffffffu, s0, 2);
            s1 += __shfl_xor_sync(0xffffffffu, s1, 1);
            s1 += __shfl_xor_sync(0xffffffffu, s1, 2);
            l0 = l0 * al0 + s0;
            l1 = l1 * al1 + s1;

            #pragma unroll
            for (int ti = 0; ti < 16; ti++) {
                accO[ti][0] *= al0; accO[ti][1] *= al0;
                accO[ti][2] *= al1; accO[ti][3] *= al1;
            }

            #pragma unroll
            for (int j = 0; j < 2; j++) {
                uint32_t aPh[4] = { phA[2*j], phB[2*j], phA[2*j+1], phB[2*j+1] };
                #pragma unroll
                for (int dg = 0; dg < 8; dg++) {
                    uint32_t vaddr = (j * 16 + (lane & 15)) * FB_STRIDE_B
                                   + dg * 32 + (lane >> 4) * 16;
                    uint32_t fVh[4];
                    ldsm4t(fVh, sVh + vaddr);
                    mma_f16(accO[dg * 2],     aPh, fVh[0], fVh[1]);
                    mma_f16(accO[dg * 2 + 1], aPh, fVh[2], fVh[3]);
                }
            }
        }
        __syncthreads();
    }

    const float inv0 = 1.0f / l0, inv1 = 1.0f / l1;
    const size_t row0 = (size_t)(b * S_LEN + q0 + wid * 16 + (lane >> 2));
    const size_t row1 = row0 + 8;
    __half* oh0 = Oh_g + row0 * DIMN + h * HD;
    __half* oh1 = Oh_g + row1 * DIMN + h * HD;
    #pragma unroll
    for (int ti = 0; ti < 16; ti++) {
        int c = ti * 8 + (lane & 3) * 2;
        *(uint32_t*)(oh0 + c) = pack_h2(accO[ti][0] * inv0, accO[ti][1] * inv0);
        *(uint32_t*)(oh1 + c) = pack_h2(accO[ti][2] * inv1, accO[ti][3] * inv1);
    }
}

// ---------------------------------------------------------------------------
// Launch
// ---------------------------------------------------------------------------
extern "C" void kernel_launch(void* const* d_in, const int* in_sizes, int n_in,
                              void* d_out, int out_size)
{
    const float* x  = (const float*)d_in[0];
    const float* wq = (const float*)d_in[1];
    const float* wk = (const float*)d_in[2];
    const float* wv = (const float*)d_in[3];
    const float* wo = (const float*)d_in[4];
    float* out = (float*)d_out;

    __half *xh, *xl, *qh, *kh, *kl, *vh, *ah;
    __half *wqT, *wkT, *wvT, *woT;
    cudaGetSymbolAddress((void**)&xh, g_xh);   cudaGetSymbolAddress((void**)&xl, g_xl);
    cudaGetSymbolAddress((void**)&qh, g_qh);
    cudaGetSymbolAddress((void**)&kh, g_kh);   cudaGetSymbolAddress((void**)&kl, g_kl);
    cudaGetSymbolAddress((void**)&vh, g_vh);
    cudaGetSymbolAddress((void**)&ah, g_ah);
    cudaGetSymbolAddress((void**)&wqT, g_wqT); cudaGetSymbolAddress((void**)&wkT, g_wkT);
    cudaGetSymbolAddress((void**)&wvT, g_wvT); cudaGetSymbolAddress((void**)&woT, g_woT);

    cudaFuncSetAttribute(gemm_qkv,
                         cudaFuncAttributeMaxDynamicSharedMemorySize, QKV_SMEM);
    cudaFuncSetAttribute(gemm_wo,
                         cudaFuncAttributeMaxDynamicSharedMemorySize, WO_SMEM);
    cudaFuncSetAttribute(fattn_kernel,
                         cudaFuncAttributeMaxDynamicSharedMemorySize, FATTN_SMEM);

    int n8x = MROWS * DIMN / 8;
    conv_pair<<<(n8x + 255) / 256, 256>>>(x, xh, xl, n8x);
    convT_all<<<dim3(320, DIMN / 32), dim3(32, 8)>>>(
        wq, wk, wv, wo, wqT, wkT, wvT, woT);

    gemm_qkv<<<dim3(48, MROWS / 128), 256, QKV_SMEM>>>(
        xh, xl, wqT, wkT, wvT, qh, kh, kl, vh);

    fattn_kernel<<<dim3(S_LEN / 128, HQ, BATCH), 256, FATTN_SMEM>>>(
        qh, kh, kl, vh, ah);

    gemm_wo<<<dim3(DIMN / 128, MROWS / 128), 256, WO_SMEM>>>(
        MROWS, DIMN, DIMN, ah, woT, out);
}